// round 2
// baseline (speedup 1.0000x reference)
#include <cuda_runtime.h>
#include <cstdint>
#include <cstdio>

#define B_ 64
#define C_ 1024
#define Q_ 128
#define H_ 256

// ---- scratch (no allocation allowed -> __device__ globals) ----
__device__ float g_m[B_ * C_];            // max_q sim  (per b,c)
__device__ float g_bpart[B_ * 8 * H_];    // partial beta-weighted ctx sums
__device__ float g_zpart[B_ * 8];         // partial softmax denominators

// ---- helpers ----
__device__ __forceinline__ uint32_t f2tf(float x) {
    uint32_t u; asm("cvt.rna.tf32.f32 %0, %1;" : "=r"(u) : "f"(x)); return u;
}
__device__ __forceinline__ float f2tff(float x) { return __uint_as_float(f2tf(x)); }

__device__ __forceinline__ void mma8(float d[4], uint32_t a0, uint32_t a1, uint32_t a2, uint32_t a3,
                                     uint32_t b0, uint32_t b1) {
    asm volatile(
        "mma.sync.aligned.m16n8k8.row.col.f32.tf32.tf32.f32 "
        "{%0,%1,%2,%3}, {%4,%5,%6,%7}, {%8,%9}, {%0,%1,%2,%3};"
        : "+f"(d[0]), "+f"(d[1]), "+f"(d[2]), "+f"(d[3])
        : "r"(a0), "r"(a1), "r"(a2), "r"(a3), "r"(b0), "r"(b1));
}

// smem layout (float offsets)
#define OFF_W    0        // att_w: 768 floats (w_c | w_q | w_m)
#define OFF_BIAS 768
#define OFF_ROWC 772      // 128
#define OFF_ROWQ 900      // 128
#define OFF_Q    1028     // query chunk 128 x 72
#define OFF_A    10244    // ctxm chunk / a-stage 128 x 72
#define OFF_SIM  19460    // sim/alpha 128 x 132
#define SMEM_FLOATS 36356
#define SQS 72
#define SSS 132

__global__ __launch_bounds__(256, 1)
void k1_sim_alpha(const float* __restrict__ ctx, const float* __restrict__ qry,
                  const float* __restrict__ attw, const float* __restrict__ attb,
                  float* __restrict__ out)
{
    extern __shared__ float sm[];
    float* s_w    = sm + OFF_W;
    float* s_rowc = sm + OFF_ROWC;
    float* s_rowq = sm + OFF_ROWQ;
    float* s_q    = sm + OFF_Q;
    float* s_a    = sm + OFF_A;
    float* s_sim  = sm + OFF_SIM;

    const int tid = threadIdx.x, warp = tid >> 5, lane = tid & 31;
    const int b = blockIdx.x >> 3, ct = blockIdx.x & 7;
    const float* ctxb = ctx + ((size_t)(b * C_) + ct * 128) * H_;
    const float* qryb = qry + (size_t)b * Q_ * H_;

    for (int i = tid; i < 768; i += 256) s_w[i] = attw[i];
    if (tid == 0) sm[OFF_BIAS] = attb[0];
    __syncthreads();

    // ---- Phase A0: rowc[c] = ctx.w_c, rowq[q] = qry.w_q (warp per row) ----
    for (int i = 0; i < 16; i++) {
        int r = warp * 16 + i;
        float4 q1 = *(const float4*)(qryb + r * H_ + lane * 4);
        float4 q2 = *(const float4*)(qryb + r * H_ + 128 + lane * 4);
        float4 c1 = *(const float4*)(ctxb + r * H_ + lane * 4);
        float4 c2 = *(const float4*)(ctxb + r * H_ + 128 + lane * 4);
        float4 wc1 = *(const float4*)(s_w + lane * 4);
        float4 wc2 = *(const float4*)(s_w + 128 + lane * 4);
        float4 wq1 = *(const float4*)(s_w + 256 + lane * 4);
        float4 wq2 = *(const float4*)(s_w + 384 + lane * 4);
        float aq = q1.x * wq1.x + q1.y * wq1.y + q1.z * wq1.z + q1.w * wq1.w
                 + q2.x * wq2.x + q2.y * wq2.y + q2.z * wq2.z + q2.w * wq2.w;
        float ac = c1.x * wc1.x + c1.y * wc1.y + c1.z * wc1.z + c1.w * wc1.w
                 + c2.x * wc2.x + c2.y * wc2.y + c2.z * wc2.z + c2.w * wc2.w;
        for (int o = 16; o; o >>= 1) {
            aq += __shfl_xor_sync(~0u, aq, o);
            ac += __shfl_xor_sync(~0u, ac, o);
        }
        if (lane == 0) { s_rowq[r] = aq; s_rowc[r] = ac; }
    }

    // ---- Phase A: GEMM1  sim = (ctx*w_m) @ qry^T  (tf32, K streamed in 64-chunks) ----
    float dacc[16][4];
    #pragma unroll
    for (int j = 0; j < 16; j++)
        #pragma unroll
        for (int e = 0; e < 4; e++) dacc[j][e] = 0.f;

    const int r0 = warp * 16 + (lane >> 2);
    const int kq = lane & 3;

    for (int ko = 0; ko < 4; ko++) {
        __syncthreads();
        #pragma unroll
        for (int i = 0; i < 8; i++) {
            int f = i * 256 + tid;
            int row = f >> 4, c4 = (f & 15) * 4;
            float4 cv = *(const float4*)(ctxb + row * H_ + ko * 64 + c4);
            float4 qv = *(const float4*)(qryb + row * H_ + ko * 64 + c4);
            float4 wm = *(const float4*)(s_w + 512 + ko * 64 + c4);
            float4 cm = { f2tff(cv.x * wm.x), f2tff(cv.y * wm.y),
                          f2tff(cv.z * wm.z), f2tff(cv.w * wm.w) };
            float4 qr = { f2tff(qv.x), f2tff(qv.y), f2tff(qv.z), f2tff(qv.w) };
            *(float4*)(s_a + row * SQS + c4) = cm;
            *(float4*)(s_q + row * SQS + c4) = qr;
        }
        __syncthreads();
        #pragma unroll
        for (int ks = 0; ks < 8; ks++) {
            int k = ks * 8 + kq;
            uint32_t a0 = __float_as_uint(s_a[r0 * SQS + k]);
            uint32_t a1 = __float_as_uint(s_a[(r0 + 8) * SQS + k]);
            uint32_t a2 = __float_as_uint(s_a[r0 * SQS + k + 4]);
            uint32_t a3 = __float_as_uint(s_a[(r0 + 8) * SQS + k + 4]);
            #pragma unroll
            for (int j = 0; j < 16; j++) {
                int n = j * 8 + (lane >> 2);
                uint32_t b0 = __float_as_uint(s_q[n * SQS + k]);
                uint32_t b1 = __float_as_uint(s_q[n * SQS + k + 4]);
                mma8(dacc[j], a0, a1, a2, a3, b0, b1);
            }
        }
    }

    // ---- Phase B: add row/col terms + bias, row max, softmax -> alpha in smem ----
    float bias = sm[OFF_BIAS];
    float rc0 = s_rowc[r0], rc1 = s_rowc[r0 + 8];
    float mx0 = -1e30f, mx1 = -1e30f;
    #pragma unroll
    for (int j = 0; j < 16; j++) {
        int colb = j * 8 + kq * 2;
        float rq0 = s_rowq[colb], rq1 = s_rowq[colb + 1];
        dacc[j][0] += rc0 + rq0 + bias;
        dacc[j][1] += rc0 + rq1 + bias;
        dacc[j][2] += rc1 + rq0 + bias;
        dacc[j][3] += rc1 + rq1 + bias;
        mx0 = fmaxf(mx0, fmaxf(dacc[j][0], dacc[j][1]));
        mx1 = fmaxf(mx1, fmaxf(dacc[j][2], dacc[j][3]));
    }
    mx0 = fmaxf(mx0, __shfl_xor_sync(~0u, mx0, 1));
    mx0 = fmaxf(mx0, __shfl_xor_sync(~0u, mx0, 2));
    mx1 = fmaxf(mx1, __shfl_xor_sync(~0u, mx1, 1));
    mx1 = fmaxf(mx1, __shfl_xor_sync(~0u, mx1, 2));
    if (kq == 0) {
        g_m[b * C_ + ct * 128 + r0]     = mx0;
        g_m[b * C_ + ct * 128 + r0 + 8] = mx1;
    }
    float sum0 = 0.f, sum1 = 0.f;
    #pragma unroll
    for (int j = 0; j < 16; j++) {
        dacc[j][0] = __expf(dacc[j][0] - mx0); sum0 += dacc[j][0];
        dacc[j][1] = __expf(dacc[j][1] - mx0); sum0 += dacc[j][1];
        dacc[j][2] = __expf(dacc[j][2] - mx1); sum1 += dacc[j][2];
        dacc[j][3] = __expf(dacc[j][3] - mx1); sum1 += dacc[j][3];
    }
    sum0 += __shfl_xor_sync(~0u, sum0, 1); sum0 += __shfl_xor_sync(~0u, sum0, 2);
    sum1 += __shfl_xor_sync(~0u, sum1, 1); sum1 += __shfl_xor_sync(~0u, sum1, 2);
    float inv0 = 1.0f / sum0, inv1 = 1.0f / sum1;
    #pragma unroll
    for (int j = 0; j < 16; j++) {
        int colb = j * 8 + kq * 2;
        float2 p0 = { f2tff(dacc[j][0] * inv0), f2tff(dacc[j][1] * inv0) };
        float2 p1 = { f2tff(dacc[j][2] * inv1), f2tff(dacc[j][3] * inv1) };
        *(float2*)(s_sim + r0 * SSS + colb) = p0;
        *(float2*)(s_sim + (r0 + 8) * SSS + colb) = p1;
    }

    // ---- Phase C: GEMM2 a = alpha @ qry (N streamed in 64-chunks) + epilogue ----
    const size_t obase = ((size_t)(b * C_) + ct * 128) * (4 * H_);
    for (int nc = 0; nc < 4; nc++) {
        __syncthreads();
        #pragma unroll
        for (int i = 0; i < 8; i++) {
            int f = i * 256 + tid;
            int row = f >> 4, c4 = (f & 15) * 4;
            float4 qv = *(const float4*)(qryb + row * H_ + nc * 64 + c4);
            float4 qr = { f2tff(qv.x), f2tff(qv.y), f2tff(qv.z), f2tff(qv.w) };
            *(float4*)(s_q + row * SQS + c4) = qr;
        }
        __syncthreads();
        float acc[8][4];
        #pragma unroll
        for (int j = 0; j < 8; j++)
            #pragma unroll
            for (int e = 0; e < 4; e++) acc[j][e] = 0.f;
        #pragma unroll
        for (int ks = 0; ks < 16; ks++) {
            int k = ks * 8 + kq;
            uint32_t a0 = __float_as_uint(s_sim[r0 * SSS + k]);
            uint32_t a1 = __float_as_uint(s_sim[(r0 + 8) * SSS + k]);
            uint32_t a2 = __float_as_uint(s_sim[r0 * SSS + k + 4]);
            uint32_t a3 = __float_as_uint(s_sim[(r0 + 8) * SSS + k + 4]);
            #pragma unroll
            for (int j = 0; j < 8; j++) {
                int n = j * 8 + (lane >> 2);
                uint32_t b0 = __float_as_uint(s_q[k * SQS + n]);
                uint32_t b1 = __float_as_uint(s_q[(k + 4) * SQS + n]);
                mma8(acc[j], a0, a1, a2, a3, b0, b1);
            }
        }
        // stage a-tile to smem for coalesced epilogue
        #pragma unroll
        for (int j = 0; j < 8; j++) {
            int colb = j * 8 + kq * 2;
            *(float2*)(s_a + r0 * SQS + colb)       = make_float2(acc[j][0], acc[j][1]);
            *(float2*)(s_a + (r0 + 8) * SQS + colb) = make_float2(acc[j][2], acc[j][3]);
        }
        __syncthreads();
        #pragma unroll
        for (int i = 0; i < 8; i++) {
            int f = i * 256 + tid;
            int row = f >> 4, c4 = (f & 15) * 4;
            float4 av = *(const float4*)(s_a + row * SQS + c4);
            float4 cv = *(const float4*)(ctxb + row * H_ + nc * 64 + c4);
            size_t o = obase + (size_t)row * (4 * H_) + nc * 64 + c4;
            *(float4*)(out + o) = cv;                       // chunk 0: context
            *(float4*)(out + o + H_) = av;                  // chunk 1: a
            float4 ca = { cv.x * av.x, cv.y * av.y, cv.z * av.z, cv.w * av.w };
            *(float4*)(out + o + 2 * H_) = ca;              // chunk 2: context*a
        }
    }
}

// ---- K2: beta partials. One CTA per (b, 128-row chunk) ----
__global__ __launch_bounds__(256, 1)
void k2_beta(const float* __restrict__ ctx)
{
    __shared__ float smm[1024];
    __shared__ float se[128];
    __shared__ float red[8];
    const int tid = threadIdx.x, lane = tid & 31, warp = tid >> 5;
    const int b = blockIdx.x >> 3, ch = blockIdx.x & 7;

    float lm = -1e30f;
    for (int i = tid; i < 1024; i += 256) {
        float v = g_m[b * 1024 + i];
        smm[i] = v; lm = fmaxf(lm, v);
    }
    for (int o = 16; o; o >>= 1) lm = fmaxf(lm, __shfl_xor_sync(~0u, lm, o));
    if (lane == 0) red[warp] = lm;
    __syncthreads();
    float M = red[0];
    #pragma unroll
    for (int i = 1; i < 8; i++) M = fmaxf(M, red[i]);
    __syncthreads();
    if (tid < 128) se[tid] = __expf(smm[ch * 128 + tid] - M);
    __syncthreads();
    if (tid < 128) {
        float v = se[tid];
        for (int o = 16; o; o >>= 1) v += __shfl_xor_sync(~0u, v, o);
        if (lane == 0) red[warp] = v;
    }
    __syncthreads();
    if (tid == 0) g_zpart[blockIdx.x] = red[0] + red[1] + red[2] + red[3];

    const float* cb = ctx + ((size_t)b * 1024 + ch * 128) * 256;
    float acc = 0.f;
    #pragma unroll 4
    for (int c = 0; c < 128; c++) acc += se[c] * cb[(size_t)c * 256 + tid];
    g_bpart[(size_t)blockIdx.x * 256 + tid] = acc;
}

// ---- K3: bvec = sum(parts)/Z ; out[...,3H:4H] = ctx * bvec ----
__global__ __launch_bounds__(256, 1)
void k3_cb(const float* __restrict__ ctx, float* __restrict__ out)
{
    __shared__ float bv[256];
    const int tid = threadIdx.x;
    const int b = blockIdx.x >> 3, ch = blockIdx.x & 7;
    float z = 0.f, a = 0.f;
    #pragma unroll
    for (int p = 0; p < 8; p++) {
        z += g_zpart[b * 8 + p];
        a += g_bpart[(size_t)(b * 8 + p) * 256 + tid];
    }
    bv[tid] = a / z;
    __syncthreads();
    const float* cb = ctx + ((size_t)b * 1024 + ch * 128) * 256;
    float* ob = out + ((size_t)(b * 1024) + ch * 128) * 1024 + 768;
    #pragma unroll 4
    for (int i = 0; i < 32; i++) {
        int f = i * 256 + tid;
        int row = f >> 6, c4 = (f & 63) * 4;
        float4 cv = *(const float4*)(cb + row * 256 + c4);
        float4 bb = *(const float4*)(bv + c4);
        float4 r = { cv.x * bb.x, cv.y * bb.y, cv.z * bb.z, cv.w * bb.w };
        *(float4*)(ob + (size_t)row * 1024 + c4) = r;
    }
}

extern "C" void kernel_launch(void* const* d_in, const int* in_sizes, int n_in,
                              void* d_out, int out_size)
{
    const float* ctx  = (const float*)d_in[0];
    const float* qry  = (const float*)d_in[2];
    const float* attw = (const float*)d_in[4];
    const float* attb = (const float*)d_in[5];
    float* out = (float*)d_out;

    cudaFuncSetAttribute(k1_sim_alpha, cudaFuncAttributeMaxDynamicSharedMemorySize,
                         SMEM_FLOATS * 4);
    k1_sim_alpha<<<512, 256, SMEM_FLOATS * 4>>>(ctx, qry, attw, attb, out);
    k2_beta<<<512, 256>>>(ctx);
    k3_cb<<<512, 256>>>(ctx, out);
}

// round 4
// speedup vs baseline: 1.1204x; 1.1204x over previous
#include <cuda_runtime.h>
#include <cstdint>

#define B_ 64
#define C_ 1024
#define Q_ 128
#define H_ 256

// ---- scratch ----
__device__ float g_m[B_ * C_];
__device__ float g_bpart[B_ * 8 * H_];
__device__ float g_zpart[B_ * 8];

// ---- smem byte offsets ----
#define SM_W     0        // 768 f32
#define SM_ROWC  3072     // 128 f32
#define SM_ROWQ  3584     // 128 f32
#define SM_SMAX  4096     // 128x2 f32
#define SM_SSUM  5120     // 128x2 f32
#define SM_SINV  6144     // 128 f32
#define SM_BIAS  6656
#define A_OFF    8192     // 3 x 32KB ring (GEMM1 A = raw ctx chunks)
#define B1_OFF   106496   // 2 x 32KB (GEMM1 B = qry*w_m chunks)
#define AL_OFF   8192     // alpha 64KB (reuses A ring after GEMM1)
#define B2_OFF   73728    // 2 x 34816 (GEMM2 B = raw qry chunks, padded rows)
#define SMEM_TOTAL 172032

__device__ __forceinline__ uint32_t smem_u32(const void* p) {
    uint32_t a; asm("{ .reg .u64 t; cvta.to.shared.u64 t, %1; cvt.u32.u64 %0, t; }" : "=r"(a) : "l"(p));
    return a;
}
__device__ __forceinline__ void mma8(float d[4], uint32_t a0, uint32_t a1, uint32_t a2, uint32_t a3,
                                     uint32_t b0, uint32_t b1) {
    asm volatile(
        "mma.sync.aligned.m16n8k8.row.col.f32.tf32.tf32.f32 "
        "{%0,%1,%2,%3}, {%4,%5,%6,%7}, {%8,%9}, {%0,%1,%2,%3};"
        : "+f"(d[0]), "+f"(d[1]), "+f"(d[2]), "+f"(d[3])
        : "r"(a0), "r"(a1), "r"(a2), "r"(a3), "r"(b0), "r"(b1));
}
#define LDSM4(r0, r1, r2, r3, addr) \
    asm volatile("ldmatrix.sync.aligned.m8n8.x4.shared.b16 {%0,%1,%2,%3}, [%4];" \
        : "=r"(r0), "=r"(r1), "=r"(r2), "=r"(r3) : "r"(addr))
#define CPA16(dst, src) \
    asm volatile("cp.async.cg.shared.global [%0], [%1], 16;" :: "r"(dst), "l"(src))
#define CP_COMMIT() asm volatile("cp.async.commit_group;" ::: "memory")
#define CP_WAIT(n)  asm volatile("cp.async.wait_group %0;" :: "n"(n) : "memory")

// ============================ K1 ============================
__global__ __launch_bounds__(256, 1)
void k1_main(const float* __restrict__ ctx, const float* __restrict__ qry,
             const float* __restrict__ attw, const float* __restrict__ attb,
             float* __restrict__ out)
{
    extern __shared__ __align__(1024) char smem[];
    float* smf = (float*)smem;
    const uint32_t sb = smem_u32(smem);
    const int tid = threadIdx.x, warp = tid >> 5, lane = tid & 31;
    const int mw = warp >> 1, nw = warp & 1;
    const int g = lane >> 3, l7 = lane & 7, gb = g & 1, gh = g >> 1;
    const int b = blockIdx.x >> 3, ct = blockIdx.x & 7;
    const float* ctxb = ctx + ((size_t)(b * C_) + ct * 128) * H_;
    const float* qryb = qry + (size_t)b * Q_ * H_;

    for (int i = tid; i < 768; i += 256) smf[i] = attw[i];
    if (tid == 0) smf[SM_BIAS / 4] = attb[0];
    __syncthreads();

    // ---- cp.async stage A chunk (raw ctx [128 m][64 k], swizzled 16B units) ----
    auto cpA = [&](int kc) {
        uint32_t base = sb + A_OFF + (kc % 3) * 32768;
        #pragma unroll
        for (int i = 0; i < 8; i++) {
            int v = i * 256 + tid;
            int m = v >> 4, j = v & 15;
            uint32_t dst = base + m * 256 + ((j ^ (m & 7)) << 4);
            CPA16(dst, ctxb + m * 256 + kc * 64 + j * 4);
        }
    };
    // ---- B1 = qry * w_m (manual: LDG early, STS late) ----
    float4 qv[8];
    auto ldgB1 = [&](int kc) {
        #pragma unroll
        for (int i = 0; i < 8; i++) {
            int v = i * 256 + tid;
            int n = v >> 4, j = v & 15;
            qv[i] = *(const float4*)(qryb + n * 256 + kc * 64 + j * 4);
        }
    };
    auto stsB1 = [&](int kc) {
        uint32_t base = sb + B1_OFF + (kc & 1) * 32768;
        const float* wm = smf + 512 + kc * 64;
        #pragma unroll
        for (int i = 0; i < 8; i++) {
            int v = i * 256 + tid;
            int n = v >> 4, j = v & 15;
            float4 w = *(const float4*)(wm + j * 4);
            float4 r = { qv[i].x * w.x, qv[i].y * w.y, qv[i].z * w.z, qv[i].w * w.w };
            *(float4*)(smem + (B1_OFF + (kc & 1) * 32768) + n * 256 + ((j ^ (n & 7)) << 4)) = r;
            (void)base;
        }
    };

    cpA(0); CP_COMMIT();
    cpA(1); CP_COMMIT();
    ldgB1(0);

    // ---- rowc = ctx.w_c, rowq = qry.w_q (warp per row) ----
    for (int i = 0; i < 16; i++) {
        int r = warp * 16 + i;
        float aq = 0.f, ac = 0.f;
        #pragma unroll
        for (int h = 0; h < 2; h++) {
            float4 q = *(const float4*)(qryb + r * H_ + h * 128 + lane * 4);
            float4 c = *(const float4*)(ctxb + r * H_ + h * 128 + lane * 4);
            float4 wc = *(const float4*)(smf + h * 128 + lane * 4);
            float4 wq = *(const float4*)(smf + 256 + h * 128 + lane * 4);
            aq += q.x * wq.x + q.y * wq.y + q.z * wq.z + q.w * wq.w;
            ac += c.x * wc.x + c.y * wc.y + c.z * wc.z + c.w * wc.w;
        }
        for (int o = 16; o; o >>= 1) {
            aq += __shfl_xor_sync(~0u, aq, o);
            ac += __shfl_xor_sync(~0u, ac, o);
        }
        if (lane == 0) { smf[SM_ROWQ / 4 + r] = aq; smf[SM_ROWC / 4 + r] = ac; }
    }

    CP_WAIT(1);                 // A(0) done
    stsB1(0);
    __syncthreads();

    // ---- GEMM1: sim = ctx @ (qry*w_m)^T ; M=128 N=128 K=256 (4 chunks) ----
    float acc1[2][8][4];
    #pragma unroll
    for (int mt = 0; mt < 2; mt++)
        #pragma unroll
        for (int j = 0; j < 8; j++)
            #pragma unroll
            for (int e = 0; e < 4; e++) acc1[mt][j][e] = 0.f;

    // per-thread LDSM row bases
    uint32_t rAb[2], xA[2], rBb[4], xB[4];
    #pragma unroll
    for (int mt = 0; mt < 2; mt++) {
        int row = mw * 32 + mt * 16 + gb * 8 + l7;
        rAb[mt] = row * 256; xA[mt] = row & 7;
    }
    #pragma unroll
    for (int p = 0; p < 4; p++) {
        int row = nw * 64 + p * 16 + gh * 8 + l7;
        rBb[p] = row * 256; xB[p] = row & 7;
    }

    for (int kc = 0; kc < 4; kc++) {
        if (kc < 3) ldgB1(kc + 1);
        uint32_t Ab = sb + A_OFF + (kc % 3) * 32768;
        uint32_t Bb = sb + B1_OFF + (kc & 1) * 32768;
        #pragma unroll
        for (int ks = 0; ks < 8; ks++) {
            uint32_t a[2][4], bf[4][4];
            #pragma unroll
            for (int mt = 0; mt < 2; mt++) {
                uint32_t u = 2 * ks + gh;
                uint32_t ad = Ab + rAb[mt] + ((u ^ xA[mt]) << 4);
                LDSM4(a[mt][0], a[mt][1], a[mt][2], a[mt][3], ad);
            }
            #pragma unroll
            for (int p = 0; p < 4; p++) {
                uint32_t u = 2 * ks + gb;
                uint32_t ad = Bb + rBb[p] + ((u ^ xB[p]) << 4);
                LDSM4(bf[p][0], bf[p][1], bf[p][2], bf[p][3], ad);
            }
            #pragma unroll
            for (int mt = 0; mt < 2; mt++)
                #pragma unroll
                for (int p = 0; p < 4; p++) {
                    mma8(acc1[mt][2 * p],     a[mt][0], a[mt][1], a[mt][2], a[mt][3], bf[p][0], bf[p][1]);
                    mma8(acc1[mt][2 * p + 1], a[mt][0], a[mt][1], a[mt][2], a[mt][3], bf[p][2], bf[p][3]);
                }
        }
        __syncthreads();
        if (kc < 3) {
            stsB1(kc + 1);
            if (kc < 2) { cpA(kc + 2); CP_COMMIT(); }
            if (kc < 2) { CP_WAIT(1); } else { CP_WAIT(0); }
            __syncthreads();
        }
    }

    // ---- prefetch GEMM2 B chunk 0 (raw qry [128 q][64+4 pad]) ----
    auto cpB2 = [&](int nc) {
        uint32_t base = sb + B2_OFF + (nc & 1) * 34816;
        #pragma unroll
        for (int i = 0; i < 8; i++) {
            int v = i * 256 + tid;
            int q = v >> 4, j = v & 15;
            CPA16(base + q * 272 + j * 16, qryb + q * 256 + nc * 64 + j * 4);
        }
    };
    cpB2(0); CP_COMMIT();

    // ---- softmax (rowq added per-col; rowc+bias folded into g_m only) ----
    const float* rqv = smf + SM_ROWQ / 4;
    float vmax[4] = { -1e30f, -1e30f, -1e30f, -1e30f };
    #pragma unroll
    for (int mt = 0; mt < 2; mt++)
        #pragma unroll
        for (int jt = 0; jt < 8; jt++) {
            int c0 = nw * 64 + jt * 8 + 2 * (lane & 3);
            float r0 = rqv[c0], r1 = rqv[c0 + 1];
            vmax[2 * mt]     = fmaxf(vmax[2 * mt],     fmaxf(acc1[mt][jt][0] + r0, acc1[mt][jt][1] + r1));
            vmax[2 * mt + 1] = fmaxf(vmax[2 * mt + 1], fmaxf(acc1[mt][jt][2] + r0, acc1[mt][jt][3] + r1));
        }
    #pragma unroll
    for (int r = 0; r < 4; r++) {
        vmax[r] = fmaxf(vmax[r], __shfl_xor_sync(~0u, vmax[r], 1));
        vmax[r] = fmaxf(vmax[r], __shfl_xor_sync(~0u, vmax[r], 2));
    }
    if ((lane & 3) == 0)
        #pragma unroll
        for (int r = 0; r < 4; r++) {
            int row = mw * 32 + (r >> 1) * 16 + (r & 1) * 8 + (lane >> 2);
            smf[SM_SMAX / 4 + row * 2 + nw] = vmax[r];
        }
    __syncthreads();
    float rmax[4], rsum[4] = { 0.f, 0.f, 0.f, 0.f };
    #pragma unroll
    for (int r = 0; r < 4; r++) {
        int row = mw * 32 + (r >> 1) * 16 + (r & 1) * 8 + (lane >> 2);
        rmax[r] = fmaxf(smf[SM_SMAX / 4 + row * 2], smf[SM_SMAX / 4 + row * 2 + 1]);
    }
    #pragma unroll
    for (int mt = 0; mt < 2; mt++)
        #pragma unroll
        for (int jt = 0; jt < 8; jt++) {
            int c0 = nw * 64 + jt * 8 + 2 * (lane & 3);
            float r0 = rqv[c0], r1 = rqv[c0 + 1];
            float e0 = __expf(acc1[mt][jt][0] + r0 - rmax[2 * mt]);
            float e1 = __expf(acc1[mt][jt][1] + r1 - rmax[2 * mt]);
            float e2 = __expf(acc1[mt][jt][2] + r0 - rmax[2 * mt + 1]);
            float e3 = __expf(acc1[mt][jt][3] + r1 - rmax[2 * mt + 1]);
            rsum[2 * mt] += e0 + e1; rsum[2 * mt + 1] += e2 + e3;
            // store unnormalized exp to alpha (swizzled f32, rows 512B)
            int rowA = mw * 32 + mt * 16 + (lane >> 2);
            int u = c0 >> 2;
            *(float2*)(smem + AL_OFF + rowA * 512 + ((u ^ (rowA & 7)) << 4) + (c0 & 3) * 4) = make_float2(e0, e1);
            int rowB = rowA + 8;
            *(float2*)(smem + AL_OFF + rowB * 512 + ((u ^ (rowB & 7)) << 4) + (c0 & 3) * 4) = make_float2(e2, e3);
        }
    #pragma unroll
    for (int r = 0; r < 4; r++) {
        rsum[r] += __shfl_xor_sync(~0u, rsum[r], 1);
        rsum[r] += __shfl_xor_sync(~0u, rsum[r], 2);
    }
    if ((lane & 3) == 0)
        #pragma unroll
        for (int r = 0; r < 4; r++) {
            int row = mw * 32 + (r >> 1) * 16 + (r & 1) * 8 + (lane >> 2);
            smf[SM_SSUM / 4 + row * 2 + nw] = rsum[r];
        }
    __syncthreads();
    if (nw == 0 && (lane & 3) == 0) {
        float bias = smf[SM_BIAS / 4];
        #pragma unroll
        for (int r = 0; r < 4; r++) {
            int row = mw * 32 + (r >> 1) * 16 + (r & 1) * 8 + (lane >> 2);
            float tot = smf[SM_SSUM / 4 + row * 2] + smf[SM_SSUM / 4 + row * 2 + 1];
            smf[SM_SINV / 4 + row] = 1.0f / tot;
            g_m[b * C_ + ct * 128 + row] = rmax[r] + smf[SM_ROWC / 4 + row] + bias;
        }
    }
    CP_WAIT(0);
    __syncthreads();

    // ---- GEMM2: D = E @ qry ; M=128, N=256 (4 chunks of 64), K=128 + epilogue ----
    float iv[4];
    #pragma unroll
    for (int r = 0; r < 4; r++) {
        int row = mw * 32 + (r >> 1) * 16 + (r & 1) * 8 + (lane >> 2);
        iv[r] = smf[SM_SINV / 4 + row];
    }
    uint32_t rA2b[2], xA2[2];
    #pragma unroll
    for (int mt = 0; mt < 2; mt++) {
        int row = mw * 32 + mt * 16 + gb * 8 + l7;
        rA2b[mt] = row * 512; xA2[mt] = row & 7;
    }
    const size_t obase = ((size_t)(b * C_) + ct * 128) * (4 * H_);

    for (int nc = 0; nc < 4; nc++) {
        if (nc < 3) { cpB2(nc + 1); CP_COMMIT(); }
        const float* B2f = (const float*)(smem + B2_OFF + (nc & 1) * 34816);
        float acc2[2][4][4];
        #pragma unroll
        for (int mt = 0; mt < 2; mt++)
            #pragma unroll
            for (int nt = 0; nt < 4; nt++)
                #pragma unroll
                for (int e = 0; e < 4; e++) acc2[mt][nt][e] = 0.f;
        #pragma unroll
        for (int ks = 0; ks < 16; ks++) {
            uint32_t a[2][4];
            #pragma unroll
            for (int mt = 0; mt < 2; mt++) {
                uint32_t u = 2 * ks + gh;
                uint32_t ad = sb + AL_OFF + rA2b[mt] + ((u ^ xA2[mt]) << 4);
                LDSM4(a[mt][0], a[mt][1], a[mt][2], a[mt][3], ad);
            }
            int k0 = ks * 8 + (lane & 3);
            uint32_t bf0[4], bf1[4];
            #pragma unroll
            for (int nt = 0; nt < 4; nt++) {
                int n = nw * 32 + nt * 8 + (lane >> 2);
                bf0[nt] = __float_as_uint(B2f[k0 * 68 + n]);
                bf1[nt] = __float_as_uint(B2f[(k0 + 4) * 68 + n]);
            }
            #pragma unroll
            for (int mt = 0; mt < 2; mt++)
                #pragma unroll
                for (int nt = 0; nt < 4; nt++)
                    mma8(acc2[mt][nt], a[mt][0], a[mt][1], a[mt][2], a[mt][3], bf0[nt], bf1[nt]);
        }
        // epilogue: out0 = ctx, out1 = a, out2 = ctx*a  (quad-coalesced 32B)
        #pragma unroll
        for (int mt = 0; mt < 2; mt++)
            #pragma unroll
            for (int h = 0; h < 2; h++) {
                int row = mw * 32 + mt * 16 + h * 8 + (lane >> 2);
                float ivr = iv[mt * 2 + h];
                #pragma unroll
                for (int nt = 0; nt < 4; nt++) {
                    int col = nw * 32 + nt * 8 + 2 * (lane & 3);
                    float2 c = *(const float2*)(ctxb + row * 256 + nc * 64 + col);
                    float a0 = acc2[mt][nt][2 * h] * ivr;
                    float a1 = acc2[mt][nt][2 * h + 1] * ivr;
                    float* o = out + obase + (size_t)row * 1024 + nc * 64 + col;
                    *(float2*)o = c;
                    *(float2*)(o + 256) = make_float2(a0, a1);
                    *(float2*)(o + 512) = make_float2(c.x * a0, c.y * a1);
                }
            }
        if (nc < 3) CP_WAIT(0);
        __syncthreads();
    }
}

// ============================ K2 ============================
__global__ __launch_bounds__(256, 1)
void k2_beta(const float* __restrict__ ctx)
{
    __shared__ float smm[1024];
    __shared__ float se[128];
    __shared__ float red[8];
    const int tid = threadIdx.x, lane = tid & 31, warp = tid >> 5;
    const int b = blockIdx.x >> 3, ch = blockIdx.x & 7;

    float lm = -1e30f;
    for (int i = tid; i < 1024; i += 256) {
        float v = g_m[b * 1024 + i];
        smm[i] = v; lm = fmaxf(lm, v);
    }
    for (int o = 16; o; o >>= 1) lm = fmaxf(lm, __shfl_xor_sync(~0u, lm, o));
    if (lane == 0) red[warp] = lm;
    __syncthreads();
    float M = red[0];
    #pragma unroll
    for (int i = 1; i < 8; i++) M = fmaxf(M, red[i]);
    __syncthreads();
    if (tid < 128) se[tid] = __expf(smm[ch * 128 + tid] - M);
    __syncthreads();
    if (tid < 128) {
        float v = se[tid];
        for (int o = 16; o; o >>= 1) v += __shfl_xor_sync(~0u, v, o);
        if (lane == 0) red[warp] = v;
    }
    __syncthreads();
    if (tid == 0) g_zpart[blockIdx.x] = red[0] + red[1] + red[2] + red[3];

    const float* cb = ctx + ((size_t)b * 1024 + ch * 128) * 256;
    float acc = 0.f;
    #pragma unroll 16
    for (int c = 0; c < 128; c++) acc += se[c] * cb[(size_t)c * 256 + tid];
    g_bpart[(size_t)blockIdx.x * 256 + tid] = acc;
}

// ============================ K3 ============================
__global__ __launch_bounds__(256, 1)
void k3_cb(const float* __restrict__ ctx, float* __restrict__ out)
{
    __shared__ float bv[256];
    const int tid = threadIdx.x;
    const int b = blockIdx.x >> 3, ch = blockIdx.x & 7;
    float z = 0.f, a = 0.f;
    #pragma unroll
    for (int p = 0; p < 8; p++) {
        z += g_zpart[b * 8 + p];
        a += g_bpart[(size_t)(b * 8 + p) * 256 + tid];
    }
    bv[tid] = a / z;
    __syncthreads();
    const float* cb = ctx + ((size_t)b * 1024 + ch * 128) * 256;
    float* ob = out + ((size_t)(b * 1024) + ch * 128) * 1024 + 768;
    #pragma unroll 4
    for (int i = 0; i < 32; i++) {
        int f = i * 256 + tid;
        int row = f >> 6, c4 = (f & 63) * 4;
        float4 cv = *(const float4*)(cb + row * 256 + c4);
        float4 bb = *(const float4*)(bv + c4);
        float4 r = { cv.x * bb.x, cv.y * bb.y, cv.z * bb.z, cv.w * bb.w };
        *(float4*)(ob + (size_t)row * 1024 + c4) = r;
    }
}

extern "C" void kernel_launch(void* const* d_in, const int* in_sizes, int n_in,
                              void* d_out, int out_size)
{
    const float* ctx  = (const float*)d_in[0];
    const float* qry  = (const float*)d_in[2];
    const float* attw = (const float*)d_in[4];
    const float* attb = (const float*)d_in[5];
    float* out = (float*)d_out;

    cudaFuncSetAttribute(k1_main, cudaFuncAttributeMaxDynamicSharedMemorySize, SMEM_TOTAL);
    k1_main<<<512, 256, SMEM_TOTAL>>>(ctx, qry, attw, attb, out);
    k2_beta<<<512, 256>>>(ctx);
    k3_cb<<<512, 256>>>(ctx, out);
}

// round 5
// speedup vs baseline: 1.2232x; 1.0918x over previous
#include <cuda_runtime.h>
#include <cstdint>

#define B_ 64
#define C_ 1024
#define Q_ 128
#define H_ 256

// ---- scratch ----
__device__ float g_m[B_ * C_];
__device__ float g_bpart[B_ * 8 * H_];
__device__ float g_zpart[B_ * 8];

// ---- smem byte offsets ----
#define SM_W     0        // 768 f32
#define SM_ROWC  3072     // 128 f32
#define SM_ROWQ  3584     // 128 f32
#define SM_SMAX  4096     // 128x4 f32
#define SM_SSUM  6144     // 128x4 f32
#define SM_SINV  8192     // 128 f32
#define SM_BIAS  8704
#define A_OFF    12288    // 3 x 32KB ring (GEMM1 A = raw ctx chunks)
#define B1_OFF   110592   // 2 x 32KB (GEMM1 B = qry*w_m chunks)
#define AL_OFF   12288    // alpha 64KB (reuses A ring after GEMM1)
#define B2_OFF   77824    // 2 x 34816 (GEMM2 B = raw qry chunks, padded rows)
#define SMEM_TOTAL 176128

__device__ __forceinline__ uint32_t smem_u32(const void* p) {
    uint32_t a; asm("{ .reg .u64 t; cvta.to.shared.u64 t, %1; cvt.u32.u64 %0, t; }" : "=r"(a) : "l"(p));
    return a;
}
__device__ __forceinline__ void mma8(float d[4], uint32_t a0, uint32_t a1, uint32_t a2, uint32_t a3,
                                     uint32_t b0, uint32_t b1) {
    asm volatile(
        "mma.sync.aligned.m16n8k8.row.col.f32.tf32.tf32.f32 "
        "{%0,%1,%2,%3}, {%4,%5,%6,%7}, {%8,%9}, {%0,%1,%2,%3};"
        : "+f"(d[0]), "+f"(d[1]), "+f"(d[2]), "+f"(d[3])
        : "r"(a0), "r"(a1), "r"(a2), "r"(a3), "r"(b0), "r"(b1));
}
#define LDSM4(r0, r1, r2, r3, addr) \
    asm volatile("ldmatrix.sync.aligned.m8n8.x4.shared.b16 {%0,%1,%2,%3}, [%4];" \
        : "=r"(r0), "=r"(r1), "=r"(r2), "=r"(r3) : "r"(addr))
#define CPA16(dst, src) \
    asm volatile("cp.async.cg.shared.global [%0], [%1], 16;" :: "r"(dst), "l"(src))
#define CP_COMMIT() asm volatile("cp.async.commit_group;" ::: "memory")
#define CP_WAIT(n)  asm volatile("cp.async.wait_group %0;" :: "n"(n) : "memory")

// ============================ K1 ============================
__global__ __launch_bounds__(512, 1)
void k1_main(const float* __restrict__ ctx, const float* __restrict__ qry,
             const float* __restrict__ attw, const float* __restrict__ attb,
             float* __restrict__ out)
{
    extern __shared__ __align__(1024) char smem[];
    float* smf = (float*)smem;
    const uint32_t sb = smem_u32(smem);
    const int tid = threadIdx.x, warp = tid >> 5, lane = tid & 31;
    const int mw = warp >> 2, nw = warp & 3;
    const int g = lane >> 3, l7 = lane & 7, gb = g & 1, gh = g >> 1;
    const int b = blockIdx.x >> 3, ct = blockIdx.x & 7;
    const float* ctxb = ctx + ((size_t)(b * C_) + ct * 128) * H_;
    const float* qryb = qry + (size_t)b * Q_ * H_;

    for (int i = tid; i < 768; i += 512) smf[i] = attw[i];
    if (tid == 0) smf[SM_BIAS / 4] = attb[0];
    __syncthreads();

    // ---- cp.async stage A chunk (raw ctx [128 m][64 k], swizzled 16B units) ----
    auto cpA = [&](int kc) {
        uint32_t base = sb + A_OFF + (kc % 3) * 32768;
        #pragma unroll
        for (int i = 0; i < 4; i++) {
            int v = i * 512 + tid;
            int m = v >> 4, j = v & 15;
            uint32_t dst = base + m * 256 + ((j ^ (m & 7)) << 4);
            CPA16(dst, ctxb + m * 256 + kc * 64 + j * 4);
        }
    };
    // ---- B1 = qry * w_m (manual: LDG early, STS late) ----
    float4 qv[4];
    auto ldgB1 = [&](int kc) {
        #pragma unroll
        for (int i = 0; i < 4; i++) {
            int v = i * 512 + tid;
            int n = v >> 4, j = v & 15;
            qv[i] = *(const float4*)(qryb + n * 256 + kc * 64 + j * 4);
        }
    };
    auto stsB1 = [&](int kc) {
        const float* wm = smf + 512 + kc * 64;
        #pragma unroll
        for (int i = 0; i < 4; i++) {
            int v = i * 512 + tid;
            int n = v >> 4, j = v & 15;
            float4 w = *(const float4*)(wm + j * 4);
            float4 r = { qv[i].x * w.x, qv[i].y * w.y, qv[i].z * w.z, qv[i].w * w.w };
            *(float4*)(smem + (B1_OFF + (kc & 1) * 32768) + n * 256 + ((j ^ (n & 7)) << 4)) = r;
        }
    };

    cpA(0); CP_COMMIT();
    cpA(1); CP_COMMIT();
    ldgB1(0);

    // ---- rowc = ctx.w_c, rowq = qry.w_q (warp per row, 8 rows each) ----
    for (int i = 0; i < 8; i++) {
        int r = warp * 8 + i;
        float aq = 0.f, ac = 0.f;
        #pragma unroll
        for (int h = 0; h < 2; h++) {
            float4 q = *(const float4*)(qryb + r * H_ + h * 128 + lane * 4);
            float4 c = *(const float4*)(ctxb + r * H_ + h * 128 + lane * 4);
            float4 wc = *(const float4*)(smf + h * 128 + lane * 4);
            float4 wq = *(const float4*)(smf + 256 + h * 128 + lane * 4);
            aq += q.x * wq.x + q.y * wq.y + q.z * wq.z + q.w * wq.w;
            ac += c.x * wc.x + c.y * wc.y + c.z * wc.z + c.w * wc.w;
        }
        for (int o = 16; o; o >>= 1) {
            aq += __shfl_xor_sync(~0u, aq, o);
            ac += __shfl_xor_sync(~0u, ac, o);
        }
        if (lane == 0) { smf[SM_ROWQ / 4 + r] = aq; smf[SM_ROWC / 4 + r] = ac; }
    }

    CP_WAIT(1);                 // A(0) done
    stsB1(0);
    __syncthreads();

    // ---- GEMM1: sim = ctx @ (qry*w_m)^T ; M=128 N=128 K=256 (4 chunks) ----
    // warp tile 32(m) x 32(n):  acc1[mt 2][j 4][4]
    float acc1[2][4][4];
    #pragma unroll
    for (int mt = 0; mt < 2; mt++)
        #pragma unroll
        for (int j = 0; j < 4; j++)
            #pragma unroll
            for (int e = 0; e < 4; e++) acc1[mt][j][e] = 0.f;

    uint32_t rAb[2], xA[2], rBb[2], xB[2];
    #pragma unroll
    for (int mt = 0; mt < 2; mt++) {
        int row = mw * 32 + mt * 16 + gb * 8 + l7;
        rAb[mt] = row * 256; xA[mt] = row & 7;
    }
    #pragma unroll
    for (int p = 0; p < 2; p++) {
        int row = nw * 32 + p * 16 + gh * 8 + l7;
        rBb[p] = row * 256; xB[p] = row & 7;
    }

    for (int kc = 0; kc < 4; kc++) {
        if (kc < 3) ldgB1(kc + 1);
        uint32_t Ab = sb + A_OFF + (kc % 3) * 32768;
        uint32_t Bb = sb + B1_OFF + (kc & 1) * 32768;
        #pragma unroll
        for (int ks = 0; ks < 8; ks++) {
            uint32_t a[2][4], bf[2][4];
            #pragma unroll
            for (int mt = 0; mt < 2; mt++) {
                uint32_t u = 2 * ks + gh;
                LDSM4(a[mt][0], a[mt][1], a[mt][2], a[mt][3], Ab + rAb[mt] + ((u ^ xA[mt]) << 4));
            }
            #pragma unroll
            for (int p = 0; p < 2; p++) {
                uint32_t u = 2 * ks + gb;
                LDSM4(bf[p][0], bf[p][1], bf[p][2], bf[p][3], Bb + rBb[p] + ((u ^ xB[p]) << 4));
            }
            #pragma unroll
            for (int mt = 0; mt < 2; mt++)
                #pragma unroll
                for (int p = 0; p < 2; p++) {
                    mma8(acc1[mt][2 * p],     a[mt][0], a[mt][1], a[mt][2], a[mt][3], bf[p][0], bf[p][1]);
                    mma8(acc1[mt][2 * p + 1], a[mt][0], a[mt][1], a[mt][2], a[mt][3], bf[p][2], bf[p][3]);
                }
        }
        __syncthreads();
        if (kc < 3) {
            stsB1(kc + 1);
            if (kc < 2) { cpA(kc + 2); CP_COMMIT(); CP_WAIT(1); }
            else        { CP_WAIT(0); }
            __syncthreads();
        }
    }

    // ---- prefetch GEMM2 B chunk 0 (raw qry [128 q][64+4 pad]) ----
    auto cpB2 = [&](int nc) {
        uint32_t base = sb + B2_OFF + (nc & 1) * 34816;
        #pragma unroll
        for (int i = 0; i < 4; i++) {
            int v = i * 512 + tid;
            int q = v >> 4, j = v & 15;
            CPA16(base + q * 272 + j * 16, qryb + q * 256 + nc * 64 + j * 4);
        }
    };
    cpB2(0); CP_COMMIT();

    // ---- softmax (4-way n-warp partials) ----
    const float* rqv = smf + SM_ROWQ / 4;
    float vmax[4] = { -1e30f, -1e30f, -1e30f, -1e30f };
    #pragma unroll
    for (int mt = 0; mt < 2; mt++)
        #pragma unroll
        for (int jt = 0; jt < 4; jt++) {
            int c0 = nw * 32 + jt * 8 + 2 * (lane & 3);
            float r0 = rqv[c0], r1 = rqv[c0 + 1];
            vmax[2 * mt]     = fmaxf(vmax[2 * mt],     fmaxf(acc1[mt][jt][0] + r0, acc1[mt][jt][1] + r1));
            vmax[2 * mt + 1] = fmaxf(vmax[2 * mt + 1], fmaxf(acc1[mt][jt][2] + r0, acc1[mt][jt][3] + r1));
        }
    #pragma unroll
    for (int r = 0; r < 4; r++) {
        vmax[r] = fmaxf(vmax[r], __shfl_xor_sync(~0u, vmax[r], 1));
        vmax[r] = fmaxf(vmax[r], __shfl_xor_sync(~0u, vmax[r], 2));
    }
    if ((lane & 3) == 0)
        #pragma unroll
        for (int r = 0; r < 4; r++) {
            int row = mw * 32 + (r >> 1) * 16 + (r & 1) * 8 + (lane >> 2);
            smf[SM_SMAX / 4 + row * 4 + nw] = vmax[r];
        }
    __syncthreads();
    float rmax[4], rsum[4] = { 0.f, 0.f, 0.f, 0.f };
    #pragma unroll
    for (int r = 0; r < 4; r++) {
        int row = mw * 32 + (r >> 1) * 16 + (r & 1) * 8 + (lane >> 2);
        float m0 = fmaxf(smf[SM_SMAX / 4 + row * 4],     smf[SM_SMAX / 4 + row * 4 + 1]);
        float m1 = fmaxf(smf[SM_SMAX / 4 + row * 4 + 2], smf[SM_SMAX / 4 + row * 4 + 3]);
        rmax[r] = fmaxf(m0, m1);
    }
    #pragma unroll
    for (int mt = 0; mt < 2; mt++)
        #pragma unroll
        for (int jt = 0; jt < 4; jt++) {
            int c0 = nw * 32 + jt * 8 + 2 * (lane & 3);
            float r0 = rqv[c0], r1 = rqv[c0 + 1];
            float e0 = __expf(acc1[mt][jt][0] + r0 - rmax[2 * mt]);
            float e1 = __expf(acc1[mt][jt][1] + r1 - rmax[2 * mt]);
            float e2 = __expf(acc1[mt][jt][2] + r0 - rmax[2 * mt + 1]);
            float e3 = __expf(acc1[mt][jt][3] + r1 - rmax[2 * mt + 1]);
            rsum[2 * mt] += e0 + e1; rsum[2 * mt + 1] += e2 + e3;
            int rowA = mw * 32 + mt * 16 + (lane >> 2);
            int u = c0 >> 2;
            *(float2*)(smem + AL_OFF + rowA * 512 + ((u ^ (rowA & 7)) << 4) + (c0 & 3) * 4) = make_float2(e0, e1);
            int rowB = rowA + 8;
            *(float2*)(smem + AL_OFF + rowB * 512 + ((u ^ (rowB & 7)) << 4) + (c0 & 3) * 4) = make_float2(e2, e3);
        }
    #pragma unroll
    for (int r = 0; r < 4; r++) {
        rsum[r] += __shfl_xor_sync(~0u, rsum[r], 1);
        rsum[r] += __shfl_xor_sync(~0u, rsum[r], 2);
    }
    if ((lane & 3) == 0)
        #pragma unroll
        for (int r = 0; r < 4; r++) {
            int row = mw * 32 + (r >> 1) * 16 + (r & 1) * 8 + (lane >> 2);
            smf[SM_SSUM / 4 + row * 4 + nw] = rsum[r];
        }
    __syncthreads();
    if (nw == 0 && (lane & 3) == 0) {
        float bias = smf[SM_BIAS / 4];
        #pragma unroll
        for (int r = 0; r < 4; r++) {
            int row = mw * 32 + (r >> 1) * 16 + (r & 1) * 8 + (lane >> 2);
            float tot = smf[SM_SSUM / 4 + row * 4]     + smf[SM_SSUM / 4 + row * 4 + 1]
                      + smf[SM_SSUM / 4 + row * 4 + 2] + smf[SM_SSUM / 4 + row * 4 + 3];
            smf[SM_SINV / 4 + row] = 1.0f / tot;
            g_m[b * C_ + ct * 128 + row] = rmax[r] + smf[SM_ROWC / 4 + row] + bias;
        }
    }
    CP_WAIT(0);
    __syncthreads();

    // ---- GEMM2: D = E @ qry ; M=128, N=256 (4 chunks of 64), K=128 + epilogue ----
    float iv[4];
    #pragma unroll
    for (int r = 0; r < 4; r++) {
        int row = mw * 32 + (r >> 1) * 16 + (r & 1) * 8 + (lane >> 2);
        iv[r] = smf[SM_SINV / 4 + row];
    }
    uint32_t rA2b[2], xA2[2];
    #pragma unroll
    for (int mt = 0; mt < 2; mt++) {
        int row = mw * 32 + mt * 16 + gb * 8 + l7;
        rA2b[mt] = row * 512; xA2[mt] = row & 7;
    }
    const size_t obase = ((size_t)(b * C_) + ct * 128) * (4 * H_);

    for (int nc = 0; nc < 4; nc++) {
        if (nc < 3) { cpB2(nc + 1); CP_COMMIT(); }
        const float* B2f = (const float*)(smem + B2_OFF + (nc & 1) * 34816);
        float acc2[2][2][4];
        #pragma unroll
        for (int mt = 0; mt < 2; mt++)
            #pragma unroll
            for (int nt = 0; nt < 2; nt++)
                #pragma unroll
                for (int e = 0; e < 4; e++) acc2[mt][nt][e] = 0.f;
        #pragma unroll
        for (int ks = 0; ks < 16; ks++) {
            uint32_t a[2][4];
            #pragma unroll
            for (int mt = 0; mt < 2; mt++) {
                uint32_t u = 2 * ks + gh;
                LDSM4(a[mt][0], a[mt][1], a[mt][2], a[mt][3], sb + AL_OFF + rA2b[mt] + ((u ^ xA2[mt]) << 4));
            }
            int k0 = ks * 8 + (lane & 3);
            uint32_t bf0[2], bf1[2];
            #pragma unroll
            for (int nt = 0; nt < 2; nt++) {
                int n = nw * 16 + nt * 8 + (lane >> 2);
                bf0[nt] = __float_as_uint(B2f[k0 * 68 + n]);
                bf1[nt] = __float_as_uint(B2f[(k0 + 4) * 68 + n]);
            }
            #pragma unroll
            for (int mt = 0; mt < 2; mt++)
                #pragma unroll
                for (int nt = 0; nt < 2; nt++)
                    mma8(acc2[mt][nt], a[mt][0], a[mt][1], a[mt][2], a[mt][3], bf0[nt], bf1[nt]);
        }
        // epilogue: out0 = ctx, out1 = a, out2 = ctx*a  (quad-coalesced 32B)
        #pragma unroll
        for (int mt = 0; mt < 2; mt++)
            #pragma unroll
            for (int h = 0; h < 2; h++) {
                int row = mw * 32 + mt * 16 + h * 8 + (lane >> 2);
                float ivr = iv[mt * 2 + h];
                #pragma unroll
                for (int nt = 0; nt < 2; nt++) {
                    int col = nw * 16 + nt * 8 + 2 * (lane & 3);
                    float2 c = *(const float2*)(ctxb + row * 256 + nc * 64 + col);
                    float a0 = acc2[mt][nt][2 * h] * ivr;
                    float a1 = acc2[mt][nt][2 * h + 1] * ivr;
                    float* o = out + obase + (size_t)row * 1024 + nc * 64 + col;
                    *(float2*)o = c;
                    *(float2*)(o + 256) = make_float2(a0, a1);
                    *(float2*)(o + 512) = make_float2(c.x * a0, c.y * a1);
                }
            }
        if (nc < 3) CP_WAIT(0);
        __syncthreads();
    }
}

// ============================ K2 ============================
__global__ __launch_bounds__(256, 1)
void k2_beta(const float* __restrict__ ctx)
{
    __shared__ float smm[1024];
    __shared__ float se[128];
    __shared__ float red[8];
    const int tid = threadIdx.x, lane = tid & 31, warp = tid >> 5;
    const int b = blockIdx.x >> 3, ch = blockIdx.x & 7;

    float lm = -1e30f;
    for (int i = tid; i < 1024; i += 256) {
        float v = g_m[b * 1024 + i];
        smm[i] = v; lm = fmaxf(lm, v);
    }
    for (int o = 16; o; o >>= 1) lm = fmaxf(lm, __shfl_xor_sync(~0u, lm, o));
    if (lane == 0) red[warp] = lm;
    __syncthreads();
    float M = red[0];
    #pragma unroll
    for (int i = 1; i < 8; i++) M = fmaxf(M, red[i]);
    __syncthreads();
    if (tid < 128) se[tid] = __expf(smm[ch * 128 + tid] - M);
    __syncthreads();
    if (tid < 128) {
        float v = se[tid];
        for (int o = 16; o; o >>= 1) v += __shfl_xor_sync(~0u, v, o);
        if (lane == 0) red[warp] = v;
    }
    __syncthreads();
    if (tid == 0) g_zpart[blockIdx.x] = red[0] + red[1] + red[2] + red[3];

    const float* cb = ctx + ((size_t)b * 1024 + ch * 128) * 256;
    float acc = 0.f;
    #pragma unroll 16
    for (int c = 0; c < 128; c++) acc += se[c] * cb[(size_t)c * 256 + tid];
    g_bpart[(size_t)blockIdx.x * 256 + tid] = acc;
}

// ============================ K3 ============================
__global__ __launch_bounds__(256, 1)
void k3_cb(const float* __restrict__ ctx, float* __restrict__ out)
{
    __shared__ float bv[256];
    const int tid = threadIdx.x;
    const int b = blockIdx.x >> 3, ch = blockIdx.x & 7;
    float z = 0.f, a = 0.f;
    #pragma unroll
    for (int p = 0; p < 8; p++) {
        z += g_zpart[b * 8 + p];
        a += g_bpart[(size_t)(b * 8 + p) * 256 + tid];
    }
    bv[tid] = a / z;
    __syncthreads();
    const float* cb = ctx + ((size_t)b * 1024 + ch * 128) * 256;
    float* ob = out + ((size_t)(b * 1024) + ch * 128) * 1024 + 768;
    #pragma unroll 4
    for (int i = 0; i < 32; i++) {
        int f = i * 256 + tid;
        int row = f >> 6, c4 = (f & 63) * 4;
        float4 cv = *(const float4*)(cb + row * 256 + c4);
        float4 bb = *(const float4*)(bv + c4);
        float4 r = { cv.x * bb.x, cv.y * bb.y, cv.z * bb.z, cv.w * bb.w };
        *(float4*)(ob + (size_t)row * 1024 + c4) = r;
    }
}

extern "C" void kernel_launch(void* const* d_in, const int* in_sizes, int n_in,
                              void* d_out, int out_size)
{
    const float* ctx  = (const float*)d_in[0];
    const float* qry  = (const float*)d_in[2];
    const float* attw = (const float*)d_in[4];
    const float* attb = (const float*)d_in[5];
    float* out = (float*)d_out;

    cudaFuncSetAttribute(k1_main, cudaFuncAttributeMaxDynamicSharedMemorySize, SMEM_TOTAL);
    k1_main<<<512, 512, SMEM_TOTAL>>>(ctx, qry, attw, attb, out);
    k2_beta<<<512, 256>>>(ctx);
    k3_cb<<<512, 256>>>(ctx, out);
}

// round 6
// speedup vs baseline: 1.3678x; 1.1181x over previous
#include <cuda_runtime.h>
#include <cstdint>

#define B_ 64
#define C_ 1024
#define Q_ 128
#define H_ 256

// ---- scratch ----
__device__ float g_m[B_ * C_];
__device__ float g_bpart[B_ * 8 * H_];
__device__ float g_zpart[B_ * 8];

// ---- smem byte offsets ----
#define SM_W     0        // 768 f32 (w_c | w_q | w_m)
#define SM_ROWC  3072     // 128 f32
#define SM_ROWQ  3584     // 128 f32
#define SM_SMAX  4096     // 128x4 f32
#define SM_SSUM  6144     // 128x4 f32
#define SM_SINV  8192     // 128 f32
#define SM_BIAS  8704
#define A_OFF    12288    // 2 x 32KB double-buffer (A = ctx*w_m chunks)
#define AL_OFF   12288    // alpha 64KB overlays A ring after GEMM1
#define B1_OFF   77824    // 4 x 32KB resident raw-qry h-chunks (GEMM1 B + GEMM2 B)
#define SMEM_TOTAL 208896

__device__ __forceinline__ uint32_t smem_u32(const void* p) {
    uint32_t a; asm("{ .reg .u64 t; cvta.to.shared.u64 t, %1; cvt.u32.u64 %0, t; }" : "=r"(a) : "l"(p));
    return a;
}
__device__ __forceinline__ void mma8(float d[4], uint32_t a0, uint32_t a1, uint32_t a2, uint32_t a3,
                                     uint32_t b0, uint32_t b1) {
    asm volatile(
        "mma.sync.aligned.m16n8k8.row.col.f32.tf32.tf32.f32 "
        "{%0,%1,%2,%3}, {%4,%5,%6,%7}, {%8,%9}, {%0,%1,%2,%3};"
        : "+f"(d[0]), "+f"(d[1]), "+f"(d[2]), "+f"(d[3])
        : "r"(a0), "r"(a1), "r"(a2), "r"(a3), "r"(b0), "r"(b1));
}
#define LDSM4(r0, r1, r2, r3, addr) \
    asm volatile("ldmatrix.sync.aligned.m8n8.x4.shared.b16 {%0,%1,%2,%3}, [%4];" \
        : "=r"(r0), "=r"(r1), "=r"(r2), "=r"(r3) : "r"(addr))
#define CPA16(dst, src) \
    asm volatile("cp.async.cg.shared.global [%0], [%1], 16;" :: "r"(dst), "l"(src))
#define CP_COMMIT() asm volatile("cp.async.commit_group;" ::: "memory")
#define CP_WAIT(n)  asm volatile("cp.async.wait_group %0;" :: "n"(n) : "memory")

// ============================ K1 ============================
__global__ __launch_bounds__(512, 1)
void k1_main(const float* __restrict__ ctx, const float* __restrict__ qry,
             const float* __restrict__ attw, const float* __restrict__ attb,
             float* __restrict__ out)
{
    extern __shared__ __align__(1024) char smem[];
    float* smf = (float*)smem;
    const uint32_t sb = smem_u32(smem);
    const int tid = threadIdx.x, warp = tid >> 5, lane = tid & 31;
    const int mw = warp >> 2, nw = warp & 3;
    const int g = lane >> 3, l7 = lane & 7, gb = g & 1, gh = g >> 1;
    const int b = blockIdx.x >> 3, ct = blockIdx.x & 7;
    const float* ctxb = ctx + ((size_t)(b * C_) + ct * 128) * H_;
    const float* qryb = qry + (size_t)b * Q_ * H_;

    for (int i = tid; i < 768; i += 512) smf[i] = attw[i];
    if (tid == 0) smf[SM_BIAS / 4] = attb[0];
    __syncthreads();

    // ---- B1: raw qry h-chunk c -> resident slot c (swizzled, cp.async) ----
    auto cpB1 = [&](int c) {
        uint32_t base = sb + B1_OFF + c * 32768;
        #pragma unroll
        for (int i = 0; i < 4; i++) {
            int v = i * 512 + tid;
            int q = v >> 4, j = v & 15;
            CPA16(base + q * 256 + ((j ^ (q & 7)) << 4), qryb + q * 256 + c * 64 + j * 4);
        }
    };
    // ---- A = ctx * w_m chunk (LDG early, STS late, double-buffered) ----
    float4 av[4];
    auto ldgA = [&](int kc) {
        #pragma unroll
        for (int i = 0; i < 4; i++) {
            int v = i * 512 + tid;
            int m = v >> 4, j = v & 15;
            av[i] = *(const float4*)(ctxb + m * 256 + kc * 64 + j * 4);
        }
    };
    auto stsA = [&](int kc) {
        const float* wm = smf + 512 + kc * 64;
        #pragma unroll
        for (int i = 0; i < 4; i++) {
            int v = i * 512 + tid;
            int m = v >> 4, j = v & 15;
            float4 w = *(const float4*)(wm + j * 4);
            float4 r = { av[i].x * w.x, av[i].y * w.y, av[i].z * w.z, av[i].w * w.w };
            *(float4*)(smem + A_OFF + (kc & 1) * 32768 + m * 256 + ((j ^ (m & 7)) << 4)) = r;
        }
    };

    cpB1(0); cpB1(1); cpB1(2); cpB1(3); CP_COMMIT();
    ldgA(0);

    // ---- rowc = ctx.w_c, rowq = qry.w_q (warp per row, 8 rows each) ----
    for (int i = 0; i < 8; i++) {
        int r = warp * 8 + i;
        float aq = 0.f, ac = 0.f;
        #pragma unroll
        for (int h = 0; h < 2; h++) {
            float4 q = *(const float4*)(qryb + r * H_ + h * 128 + lane * 4);
            float4 c = *(const float4*)(ctxb + r * H_ + h * 128 + lane * 4);
            float4 wc = *(const float4*)(smf + h * 128 + lane * 4);
            float4 wq = *(const float4*)(smf + 256 + h * 128 + lane * 4);
            aq += q.x * wq.x + q.y * wq.y + q.z * wq.z + q.w * wq.w;
            ac += c.x * wc.x + c.y * wc.y + c.z * wc.z + c.w * wc.w;
        }
        for (int o = 16; o; o >>= 1) {
            aq += __shfl_xor_sync(~0u, aq, o);
            ac += __shfl_xor_sync(~0u, ac, o);
        }
        if (lane == 0) { smf[SM_ROWQ / 4 + r] = aq; smf[SM_ROWC / 4 + r] = ac; }
    }

    stsA(0);
    CP_WAIT(0);
    __syncthreads();

    // ---- GEMM1: sim = (ctx*w_m) @ qry^T ; M=128 N=128 K=256 ----
    float acc1[2][4][4];
    #pragma unroll
    for (int mt = 0; mt < 2; mt++)
        #pragma unroll
        for (int j = 0; j < 4; j++)
            #pragma unroll
            for (int e = 0; e < 4; e++) acc1[mt][j][e] = 0.f;

    uint32_t rAb[2], xA[2], rBb[2], xB[2];
    #pragma unroll
    for (int mt = 0; mt < 2; mt++) {
        int row = mw * 32 + mt * 16 + gb * 8 + l7;
        rAb[mt] = row * 256; xA[mt] = row & 7;
    }
    #pragma unroll
    for (int p = 0; p < 2; p++) {
        int row = nw * 32 + p * 16 + gh * 8 + l7;
        rBb[p] = row * 256; xB[p] = row & 7;
    }

    #pragma unroll
    for (int kc = 0; kc < 4; kc++) {
        if (kc < 3) ldgA(kc + 1);
        uint32_t Ab = sb + A_OFF + (kc & 1) * 32768;
        uint32_t Bb = sb + B1_OFF + kc * 32768;
        #pragma unroll
        for (int ks = 0; ks < 8; ks++) {
            uint32_t a[2][4], bf[2][4];
            #pragma unroll
            for (int mt = 0; mt < 2; mt++) {
                uint32_t u = 2 * ks + gh;
                LDSM4(a[mt][0], a[mt][1], a[mt][2], a[mt][3], Ab + rAb[mt] + ((u ^ xA[mt]) << 4));
            }
            #pragma unroll
            for (int p = 0; p < 2; p++) {
                uint32_t u = 2 * ks + gb;
                LDSM4(bf[p][0], bf[p][1], bf[p][2], bf[p][3], Bb + rBb[p] + ((u ^ xB[p]) << 4));
            }
            #pragma unroll
            for (int mt = 0; mt < 2; mt++)
                #pragma unroll
                for (int p = 0; p < 2; p++) {
                    mma8(acc1[mt][2 * p],     a[mt][0], a[mt][1], a[mt][2], a[mt][3], bf[p][0], bf[p][1]);
                    mma8(acc1[mt][2 * p + 1], a[mt][0], a[mt][1], a[mt][2], a[mt][3], bf[p][2], bf[p][3]);
                }
        }
        if (kc < 3) stsA(kc + 1);
        __syncthreads();
    }

    // ---- softmax (4-way n-warp partials); alpha -> AL_OFF (overlays A ring) ----
    const float* rqv = smf + SM_ROWQ / 4;
    float vmax[4] = { -1e30f, -1e30f, -1e30f, -1e30f };
    #pragma unroll
    for (int mt = 0; mt < 2; mt++)
        #pragma unroll
        for (int jt = 0; jt < 4; jt++) {
            int c0 = nw * 32 + jt * 8 + 2 * (lane & 3);
            float r0 = rqv[c0], r1 = rqv[c0 + 1];
            vmax[2 * mt]     = fmaxf(vmax[2 * mt],     fmaxf(acc1[mt][jt][0] + r0, acc1[mt][jt][1] + r1));
            vmax[2 * mt + 1] = fmaxf(vmax[2 * mt + 1], fmaxf(acc1[mt][jt][2] + r0, acc1[mt][jt][3] + r1));
        }
    #pragma unroll
    for (int r = 0; r < 4; r++) {
        vmax[r] = fmaxf(vmax[r], __shfl_xor_sync(~0u, vmax[r], 1));
        vmax[r] = fmaxf(vmax[r], __shfl_xor_sync(~0u, vmax[r], 2));
    }
    if ((lane & 3) == 0)
        #pragma unroll
        for (int r = 0; r < 4; r++) {
            int row = mw * 32 + (r >> 1) * 16 + (r & 1) * 8 + (lane >> 2);
            smf[SM_SMAX / 4 + row * 4 + nw] = vmax[r];
        }
    __syncthreads();
    float rmax[4], rsum[4] = { 0.f, 0.f, 0.f, 0.f };
    #pragma unroll
    for (int r = 0; r < 4; r++) {
        int row = mw * 32 + (r >> 1) * 16 + (r & 1) * 8 + (lane >> 2);
        float m0 = fmaxf(smf[SM_SMAX / 4 + row * 4],     smf[SM_SMAX / 4 + row * 4 + 1]);
        float m1 = fmaxf(smf[SM_SMAX / 4 + row * 4 + 2], smf[SM_SMAX / 4 + row * 4 + 3]);
        rmax[r] = fmaxf(m0, m1);
    }
    #pragma unroll
    for (int mt = 0; mt < 2; mt++)
        #pragma unroll
        for (int jt = 0; jt < 4; jt++) {
            int c0 = nw * 32 + jt * 8 + 2 * (lane & 3);
            float r0 = rqv[c0], r1 = rqv[c0 + 1];
            float e0 = __expf(acc1[mt][jt][0] + r0 - rmax[2 * mt]);
            float e1 = __expf(acc1[mt][jt][1] + r1 - rmax[2 * mt]);
            float e2 = __expf(acc1[mt][jt][2] + r0 - rmax[2 * mt + 1]);
            float e3 = __expf(acc1[mt][jt][3] + r1 - rmax[2 * mt + 1]);
            rsum[2 * mt] += e0 + e1; rsum[2 * mt + 1] += e2 + e3;
            int rowA = mw * 32 + mt * 16 + (lane >> 2);
            int u = c0 >> 2;
            *(float2*)(smem + AL_OFF + rowA * 512 + ((u ^ (rowA & 7)) << 4) + (c0 & 3) * 4) = make_float2(e0, e1);
            int rowB = rowA + 8;
            *(float2*)(smem + AL_OFF + rowB * 512 + ((u ^ (rowB & 7)) << 4) + (c0 & 3) * 4) = make_float2(e2, e3);
        }
    #pragma unroll
    for (int r = 0; r < 4; r++) {
        rsum[r] += __shfl_xor_sync(~0u, rsum[r], 1);
        rsum[r] += __shfl_xor_sync(~0u, rsum[r], 2);
    }
    if ((lane & 3) == 0)
        #pragma unroll
        for (int r = 0; r < 4; r++) {
            int row = mw * 32 + (r >> 1) * 16 + (r & 1) * 8 + (lane >> 2);
            smf[SM_SSUM / 4 + row * 4 + nw] = rsum[r];
        }
    __syncthreads();
    if (nw == 0 && (lane & 3) == 0) {
        float bias = smf[SM_BIAS / 4];
        #pragma unroll
        for (int r = 0; r < 4; r++) {
            int row = mw * 32 + (r >> 1) * 16 + (r & 1) * 8 + (lane >> 2);
            float tot = smf[SM_SSUM / 4 + row * 4]     + smf[SM_SSUM / 4 + row * 4 + 1]
                      + smf[SM_SSUM / 4 + row * 4 + 2] + smf[SM_SSUM / 4 + row * 4 + 3];
            smf[SM_SINV / 4 + row] = 1.0f / tot;
            g_m[b * C_ + ct * 128 + row] = rmax[r] + smf[SM_ROWC / 4 + row] + bias;
        }
    }
    __syncthreads();

    // ---- GEMM2: D = E @ qry ; ks-outer, all 4 n-chunks live; B = resident qry slots ----
    float iv[4];
    #pragma unroll
    for (int r = 0; r < 4; r++) {
        int row = mw * 32 + (r >> 1) * 16 + (r & 1) * 8 + (lane >> 2);
        iv[r] = smf[SM_SINV / 4 + row];
    }
    uint32_t rA2b[2], xA2[2];
    #pragma unroll
    for (int mt = 0; mt < 2; mt++) {
        int row = mw * 32 + mt * 16 + gb * 8 + l7;
        rA2b[mt] = row * 512; xA2[mt] = row & 7;
    }
    // B-frag addressing into swizzled qry slots: h' = nw*16+nt*8+(lane>>2)
    uint32_t ubase[2];
    #pragma unroll
    for (int nt = 0; nt < 2; nt++) {
        int hp = nw * 16 + nt * 8 + (lane >> 2);
        ubase[nt] = (uint32_t)(hp >> 2);
    }
    const uint32_t bq0 = sb + B1_OFF + (lane & 3) * 256 + ((lane >> 2) & 3) * 4;
    const uint32_t r0x = lane & 3;

    float acc2[4][2][2][4];
    #pragma unroll
    for (int nc = 0; nc < 4; nc++)
        #pragma unroll
        for (int mt = 0; mt < 2; mt++)
            #pragma unroll
            for (int nt = 0; nt < 2; nt++)
                #pragma unroll
                for (int e = 0; e < 4; e++) acc2[nc][mt][nt][e] = 0.f;

    #pragma unroll
    for (int ks = 0; ks < 16; ks++) {
        uint32_t a[2][4];
        #pragma unroll
        for (int mt = 0; mt < 2; mt++) {
            uint32_t u = 2 * ks + gh;
            LDSM4(a[mt][0], a[mt][1], a[mt][2], a[mt][3], sb + AL_OFF + rA2b[mt] + ((u ^ xA2[mt]) << 4));
        }
        #pragma unroll
        for (int nc = 0; nc < 4; nc++) {
            uint32_t bf0[2], bf1[2];
            #pragma unroll
            for (int nt = 0; nt < 2; nt++) {
                uint32_t base = bq0 + nc * 32768 + ks * 2048;
                bf0[nt] = *(const uint32_t*)(smem + (base - sb) + ((ubase[nt] ^ r0x) << 4));
                bf1[nt] = *(const uint32_t*)(smem + (base - sb) + 1024 + ((ubase[nt] ^ (r0x + 4)) << 4));
            }
            #pragma unroll
            for (int mt = 0; mt < 2; mt++)
                #pragma unroll
                for (int nt = 0; nt < 2; nt++)
                    mma8(acc2[nc][mt][nt], a[mt][0], a[mt][1], a[mt][2], a[mt][3], bf0[nt], bf1[nt]);
        }
    }

    // ---- epilogue: out0 = ctx, out1 = a, out2 = ctx*a ----
    const size_t obase = ((size_t)(b * C_) + ct * 128) * (4 * H_);
    #pragma unroll
    for (int mt = 0; mt < 2; mt++)
        #pragma unroll
        for (int h = 0; h < 2; h++) {
            int row = mw * 32 + mt * 16 + h * 8 + (lane >> 2);
            float ivr = iv[mt * 2 + h];
            #pragma unroll
            for (int nc = 0; nc < 4; nc++)
                #pragma unroll
                for (int nt = 0; nt < 2; nt++) {
                    int col = nc * 64 + nw * 16 + nt * 8 + 2 * (lane & 3);
                    float2 c = *(const float2*)(ctxb + row * 256 + col);
                    float a0 = acc2[nc][mt][nt][2 * h] * ivr;
                    float a1 = acc2[nc][mt][nt][2 * h + 1] * ivr;
                    float* o = out + obase + (size_t)row * 1024 + col;
                    *(float2*)o = c;
                    *(float2*)(o + 256) = make_float2(a0, a1);
                    *(float2*)(o + 512) = make_float2(c.x * a0, c.y * a1);
                }
        }
}

// ============================ K2 ============================
__global__ __launch_bounds__(256, 1)
void k2_beta(const float* __restrict__ ctx)
{
    __shared__ float smm[1024];
    __shared__ float se[128];
    __shared__ float red[8];
    const int tid = threadIdx.x, lane = tid & 31, warp = tid >> 5;
    const int b = blockIdx.x >> 3, ch = blockIdx.x & 7;

    float lm = -1e30f;
    for (int i = tid; i < 1024; i += 256) {
        float v = g_m[b * 1024 + i];
        smm[i] = v; lm = fmaxf(lm, v);
    }
    for (int o = 16; o; o >>= 1) lm = fmaxf(lm, __shfl_xor_sync(~0u, lm, o));
    if (lane == 0) red[warp] = lm;
    __syncthreads();
    float M = red[0];
    #pragma unroll
    for (int i = 1; i < 8; i++) M = fmaxf(M, red[i]);
    __syncthreads();
    if (tid < 128) se[tid] = __expf(smm[ch * 128 + tid] - M);
    __syncthreads();
    if (tid < 128) {
        float v = se[tid];
        for (int o = 16; o; o >>= 1) v += __shfl_xor_sync(~0u, v, o);
        if (lane == 0) red[warp] = v;
    }
    __syncthreads();
    if (tid == 0) g_zpart[blockIdx.x] = red[0] + red[1] + red[2] + red[3];

    const float* cb = ctx + ((size_t)b * 1024 + ch * 128) * 256;
    float acc = 0.f;
    #pragma unroll 16
    for (int c = 0; c < 128; c++) acc += se[c] * cb[(size_t)c * 256 + tid];
    g_bpart[(size_t)blockIdx.x * 256 + tid] = acc;
}

// ============================ K3 ============================
__global__ __launch_bounds__(256, 1)
void k3_cb(const float* __restrict__ ctx, float* __restrict__ out)
{
    __shared__ float bv[256];
    const int tid = threadIdx.x;
    const int b = blockIdx.x >> 3, ch = blockIdx.x & 7;
    float z = 0.f, a = 0.f;
    #pragma unroll
    for (int p = 0; p < 8; p++) {
        z += g_zpart[b * 8 + p];
        a += g_bpart[(size_t)(b * 8 + p) * 256 + tid];
    }
    bv[tid] = a / z;
    __syncthreads();
    const float* cb = ctx + ((size_t)b * 1024 + ch * 128) * 256;
    float* ob = out + ((size_t)(b * 1024) + ch * 128) * 1024 + 768;
    #pragma unroll 4
    for (int i = 0; i < 32; i++) {
        int f = i * 256 + tid;
        int row = f >> 6, c4 = (f & 63) * 4;
        float4 cv = *(const float4*)(cb + row * 256 + c4);
        float4 bb = *(const float4*)(bv + c4);
        float4 r = { cv.x * bb.x, cv.y * bb.y, cv.z * bb.z, cv.w * bb.w };
        *(float4*)(ob + (size_t)row * 1024 + c4) = r;
    }
}

extern "C" void kernel_launch(void* const* d_in, const int* in_sizes, int n_in,
                              void* d_out, int out_size)
{
    const float* ctx  = (const float*)d_in[0];
    const float* qry  = (const float*)d_in[2];
    const float* attw = (const float*)d_in[4];
    const float* attb = (const float*)d_in[5];
    float* out = (float*)d_out;

    cudaFuncSetAttribute(k1_main, cudaFuncAttributeMaxDynamicSharedMemorySize, SMEM_TOTAL);
    k1_main<<<512, 512, SMEM_TOTAL>>>(ctx, qry, attw, attb, out);
    k2_beta<<<512, 256>>>(ctx);
    k3_cb<<<512, 256>>>(ctx, out);
}

// round 7
// speedup vs baseline: 1.6685x; 1.2199x over previous
#include <cuda_runtime.h>
#include <cstdint>

#define B_ 64
#define C_ 1024
#define Q_ 128
#define H_ 256

// ---- scratch ----
__device__ float g_m[B_ * C_];
__device__ float g_bpart[B_ * 8 * H_];
__device__ float g_zpart[B_ * 8];

// ---- smem byte offsets ----
#define SM_W     0        // 768 f32 (w_c | w_q | w_m)
#define SM_ROWC  3072     // 128 f32
#define SM_ROWQ  3584     // 128 f32
#define SM_SMAX  4096     // 128x4 f32
#define SM_SSUM  6144     // 128x4 f32
#define SM_SINV  8192     // 128 f32
#define SM_BIAS  8704
#define A_OFF    12288    // 2 x 16KB double-buffer (A = ctx*w_m fp16 chunks)
#define AL_OFF   12288    // alpha fp16 [128][128] 32KB, overlays A after GEMM1
#define B1_OFF   45056    // 4 x 16KB resident fp16 qry h-chunks ([q][64h] each)
#define SMEM_TOTAL 110592

__device__ __forceinline__ uint32_t smem_u32(const void* p) {
    uint32_t a; asm("{ .reg .u64 t; cvta.to.shared.u64 t, %1; cvt.u32.u64 %0, t; }" : "=r"(a) : "l"(p));
    return a;
}
__device__ __forceinline__ uint32_t pack2(float lo, float hi) {   // f16x2 {lo, hi}
    uint32_t r; asm("cvt.rn.f16x2.f32 %0, %1, %2;" : "=r"(r) : "f"(hi), "f"(lo)); return r;
}
__device__ __forceinline__ void mma16(float d[4], uint32_t a0, uint32_t a1, uint32_t a2, uint32_t a3,
                                      uint32_t b0, uint32_t b1) {
    asm volatile(
        "mma.sync.aligned.m16n8k16.row.col.f32.f16.f16.f32 "
        "{%0,%1,%2,%3}, {%4,%5,%6,%7}, {%8,%9}, {%0,%1,%2,%3};"
        : "+f"(d[0]), "+f"(d[1]), "+f"(d[2]), "+f"(d[3])
        : "r"(a0), "r"(a1), "r"(a2), "r"(a3), "r"(b0), "r"(b1));
}
#define LDSM4(r0, r1, r2, r3, addr) \
    asm volatile("ldmatrix.sync.aligned.m8n8.x4.shared.b16 {%0,%1,%2,%3}, [%4];" \
        : "=r"(r0), "=r"(r1), "=r"(r2), "=r"(r3) : "r"(addr))
#define LDSM4T(r0, r1, r2, r3, addr) \
    asm volatile("ldmatrix.sync.aligned.m8n8.x4.trans.shared.b16 {%0,%1,%2,%3}, [%4];" \
        : "=r"(r0), "=r"(r1), "=r"(r2), "=r"(r3) : "r"(addr))

// ============================ K1 ============================
__global__ __launch_bounds__(512, 1)
void k1_main(const float* __restrict__ ctx, const float* __restrict__ qry,
             const float* __restrict__ attw, const float* __restrict__ attb,
             float* __restrict__ out)
{
    extern __shared__ __align__(1024) char smem[];
    float* smf = (float*)smem;
    const uint32_t sb = smem_u32(smem);
    const int tid = threadIdx.x, warp = tid >> 5, lane = tid & 31;
    const int mw = warp >> 2, nw = warp & 3;
    const int g = lane >> 3, l7 = lane & 7, gb = g & 1, gh = g >> 1;
    const int b = blockIdx.x >> 3, ct = blockIdx.x & 7;
    const float* ctxb = ctx + ((size_t)(b * C_) + ct * 128) * H_;
    const float* qryb = qry + (size_t)b * Q_ * H_;

    for (int i = tid; i < 768; i += 512) smf[i] = attw[i];
    if (tid == 0) smf[SM_BIAS / 4] = attb[0];
    __syncthreads();

    // ---- A = ctx*w_m fp16 chunk (LDG early, cvt+STS late, double-buffered) ----
    float4 av[4];
    auto ldgA = [&](int kc) {
        #pragma unroll
        for (int i = 0; i < 4; i++) {
            int v = i * 512 + tid;
            int m = v >> 4, j = v & 15;
            av[i] = *(const float4*)(ctxb + m * 256 + kc * 64 + j * 4);
        }
    };
    auto stsA = [&](int kc) {
        const float* wm = smf + 512 + kc * 64;
        #pragma unroll
        for (int i = 0; i < 4; i++) {
            int v = i * 512 + tid;
            int m = v >> 4, j = v & 15;
            float4 w = *(const float4*)(wm + j * 4);
            uint32_t p0 = pack2(av[i].x * w.x, av[i].y * w.y);
            uint32_t p1 = pack2(av[i].z * w.z, av[i].w * w.w);
            *(uint2*)(smem + A_OFF + (kc & 1) * 16384 + m * 128
                      + (((j >> 1) ^ (m & 7)) << 4) + (j & 1) * 8) = make_uint2(p0, p1);
        }
    };

    ldgA(0);

    // ---- rowc/rowq dots + FREE fp16 staging of qry into B1 slots ----
    for (int i = 0; i < 8; i++) {
        int r = warp * 8 + i;
        float4 q1 = *(const float4*)(qryb + r * H_ + lane * 4);
        float4 q2 = *(const float4*)(qryb + r * H_ + 128 + lane * 4);
        float4 c1 = *(const float4*)(ctxb + r * H_ + lane * 4);
        float4 c2 = *(const float4*)(ctxb + r * H_ + 128 + lane * 4);
        // stage qry rows to fp16 slots: slot = h/64, [q][64h] rows of 128B
        int j = lane & 15, s1 = lane >> 4;
        uint32_t off = r * 128 + (((j >> 1) ^ (r & 7)) << 4) + (j & 1) * 8;
        *(uint2*)(smem + B1_OFF + s1 * 16384 + off) =
            make_uint2(pack2(q1.x, q1.y), pack2(q1.z, q1.w));
        *(uint2*)(smem + B1_OFF + (2 + s1) * 16384 + off) =
            make_uint2(pack2(q2.x, q2.y), pack2(q2.z, q2.w));

        float4 wc1 = *(const float4*)(smf + lane * 4);
        float4 wc2 = *(const float4*)(smf + 128 + lane * 4);
        float4 wq1 = *(const float4*)(smf + 256 + lane * 4);
        float4 wq2 = *(const float4*)(smf + 256 + 128 + lane * 4);
        float aq = q1.x * wq1.x + q1.y * wq1.y + q1.z * wq1.z + q1.w * wq1.w
                 + q2.x * wq2.x + q2.y * wq2.y + q2.z * wq2.z + q2.w * wq2.w;
        float ac = c1.x * wc1.x + c1.y * wc1.y + c1.z * wc1.z + c1.w * wc1.w
                 + c2.x * wc2.x + c2.y * wc2.y + c2.z * wc2.z + c2.w * wc2.w;
        for (int o = 16; o; o >>= 1) {
            aq += __shfl_xor_sync(~0u, aq, o);
            ac += __shfl_xor_sync(~0u, ac, o);
        }
        if (lane == 0) { smf[SM_ROWQ / 4 + r] = aq; smf[SM_ROWC / 4 + r] = ac; }
    }

    stsA(0);
    __syncthreads();

    // ---- GEMM1: sim = (ctx*w_m) @ qry^T fp16 ; M=128 N=128 K=256 ----
    float acc1[2][4][4];
    #pragma unroll
    for (int mt = 0; mt < 2; mt++)
        #pragma unroll
        for (int j = 0; j < 4; j++)
            #pragma unroll
            for (int e = 0; e < 4; e++) acc1[mt][j][e] = 0.f;

    uint32_t rAb[2], xA[2], rBb[2], xB[2];
    #pragma unroll
    for (int mt = 0; mt < 2; mt++) {
        int row = mw * 32 + mt * 16 + gb * 8 + l7;   // A pattern: gb row-sel, gh unit-sel
        rAb[mt] = row * 128; xA[mt] = row & 7;
    }
    #pragma unroll
    for (int p = 0; p < 2; p++) {
        int row = nw * 32 + p * 16 + gh * 8 + l7;    // B pattern: gh row-sel, gb unit-sel
        rBb[p] = row * 128; xB[p] = row & 7;
    }

    #pragma unroll
    for (int kc = 0; kc < 4; kc++) {
        if (kc < 3) ldgA(kc + 1);
        uint32_t Ab = sb + A_OFF + (kc & 1) * 16384;
        uint32_t Bb = sb + B1_OFF + kc * 16384;
        #pragma unroll
        for (int ks = 0; ks < 4; ks++) {             // 4 k16-steps per 64-chunk
            uint32_t a[2][4], bf[2][4];
            #pragma unroll
            for (int mt = 0; mt < 2; mt++) {
                uint32_t u = 2 * ks + gh;
                LDSM4(a[mt][0], a[mt][1], a[mt][2], a[mt][3], Ab + rAb[mt] + ((u ^ xA[mt]) << 4));
            }
            #pragma unroll
            for (int p = 0; p < 2; p++) {
                uint32_t u = 2 * ks + gb;
                LDSM4(bf[p][0], bf[p][1], bf[p][2], bf[p][3], Bb + rBb[p] + ((u ^ xB[p]) << 4));
            }
            #pragma unroll
            for (int mt = 0; mt < 2; mt++)
                #pragma unroll
                for (int p = 0; p < 2; p++) {
                    mma16(acc1[mt][2 * p],     a[mt][0], a[mt][1], a[mt][2], a[mt][3], bf[p][0], bf[p][1]);
                    mma16(acc1[mt][2 * p + 1], a[mt][0], a[mt][1], a[mt][2], a[mt][3], bf[p][2], bf[p][3]);
                }
        }
        if (kc < 3) stsA(kc + 1);
        __syncthreads();
    }

    // ---- softmax; alpha fp16 -> AL_OFF ([128 m][128 q], 256B rows) ----
    const float* rqv = smf + SM_ROWQ / 4;
    float vmax[4] = { -1e30f, -1e30f, -1e30f, -1e30f };
    #pragma unroll
    for (int mt = 0; mt < 2; mt++)
        #pragma unroll
        for (int jt = 0; jt < 4; jt++) {
            int c0 = nw * 32 + jt * 8 + 2 * (lane & 3);
            float r0 = rqv[c0], r1 = rqv[c0 + 1];
            vmax[2 * mt]     = fmaxf(vmax[2 * mt],     fmaxf(acc1[mt][jt][0] + r0, acc1[mt][jt][1] + r1));
            vmax[2 * mt + 1] = fmaxf(vmax[2 * mt + 1], fmaxf(acc1[mt][jt][2] + r0, acc1[mt][jt][3] + r1));
        }
    #pragma unroll
    for (int r = 0; r < 4; r++) {
        vmax[r] = fmaxf(vmax[r], __shfl_xor_sync(~0u, vmax[r], 1));
        vmax[r] = fmaxf(vmax[r], __shfl_xor_sync(~0u, vmax[r], 2));
    }
    if ((lane & 3) == 0)
        #pragma unroll
        for (int r = 0; r < 4; r++) {
            int row = mw * 32 + (r >> 1) * 16 + (r & 1) * 8 + (lane >> 2);
            smf[SM_SMAX / 4 + row * 4 + nw] = vmax[r];
        }
    __syncthreads();
    float rmax[4], rsum[4] = { 0.f, 0.f, 0.f, 0.f };
    #pragma unroll
    for (int r = 0; r < 4; r++) {
        int row = mw * 32 + (r >> 1) * 16 + (r & 1) * 8 + (lane >> 2);
        float m0 = fmaxf(smf[SM_SMAX / 4 + row * 4],     smf[SM_SMAX / 4 + row * 4 + 1]);
        float m1 = fmaxf(smf[SM_SMAX / 4 + row * 4 + 2], smf[SM_SMAX / 4 + row * 4 + 3]);
        rmax[r] = fmaxf(m0, m1);
    }
    #pragma unroll
    for (int mt = 0; mt < 2; mt++)
        #pragma unroll
        for (int jt = 0; jt < 4; jt++) {
            int c0 = nw * 32 + jt * 8 + 2 * (lane & 3);
            float r0 = rqv[c0], r1 = rqv[c0 + 1];
            float e0 = __expf(acc1[mt][jt][0] + r0 - rmax[2 * mt]);
            float e1 = __expf(acc1[mt][jt][1] + r1 - rmax[2 * mt]);
            float e2 = __expf(acc1[mt][jt][2] + r0 - rmax[2 * mt + 1]);
            float e3 = __expf(acc1[mt][jt][3] + r1 - rmax[2 * mt + 1]);
            rsum[2 * mt] += e0 + e1; rsum[2 * mt + 1] += e2 + e3;
            int rowA = mw * 32 + mt * 16 + (lane >> 2);
            int rowB = rowA + 8;
            int unit = nw * 4 + jt;
            *(uint32_t*)(smem + AL_OFF + rowA * 256 + ((unit ^ (rowA & 7)) << 4) + (lane & 3) * 4)
                = pack2(e0, e1);
            *(uint32_t*)(smem + AL_OFF + rowB * 256 + ((unit ^ (rowB & 7)) << 4) + (lane & 3) * 4)
                = pack2(e2, e3);
        }
    #pragma unroll
    for (int r = 0; r < 4; r++) {
        rsum[r] += __shfl_xor_sync(~0u, rsum[r], 1);
        rsum[r] += __shfl_xor_sync(~0u, rsum[r], 2);
    }
    if ((lane & 3) == 0)
        #pragma unroll
        for (int r = 0; r < 4; r++) {
            int row = mw * 32 + (r >> 1) * 16 + (r & 1) * 8 + (lane >> 2);
            smf[SM_SSUM / 4 + row * 4 + nw] = rsum[r];
        }
    __syncthreads();
    if (nw == 0 && (lane & 3) == 0) {
        float bias = smf[SM_BIAS / 4];
        #pragma unroll
        for (int r = 0; r < 4; r++) {
            int row = mw * 32 + (r >> 1) * 16 + (r & 1) * 8 + (lane >> 2);
            float tot = smf[SM_SSUM / 4 + row * 4]     + smf[SM_SSUM / 4 + row * 4 + 1]
                      + smf[SM_SSUM / 4 + row * 4 + 2] + smf[SM_SSUM / 4 + row * 4 + 3];
            smf[SM_SINV / 4 + row] = 1.0f / tot;
            g_m[b * C_ + ct * 128 + row] = rmax[r] + smf[SM_ROWC / 4 + row] + bias;
        }
    }
    __syncthreads();

    // ---- GEMM2: D = E @ qry fp16 ; warp n-tile = 64 (slot nw), K=128 ----
    float iv[4];
    #pragma unroll
    for (int r = 0; r < 4; r++) {
        int row = mw * 32 + (r >> 1) * 16 + (r & 1) * 8 + (lane >> 2);
        iv[r] = smf[SM_SINV / 4 + row];
    }
    uint32_t rA2b[2], xA2[2];
    #pragma unroll
    for (int mt = 0; mt < 2; mt++) {
        int row = mw * 32 + mt * 16 + gb * 8 + l7;
        rA2b[mt] = row * 256; xA2[mt] = row & 7;
    }
    const uint32_t Bs = sb + B1_OFF + nw * 16384;
    const int qbase = gb * 8 + l7;

    float acc2[8][2][4];
    #pragma unroll
    for (int j = 0; j < 8; j++)
        #pragma unroll
        for (int mt = 0; mt < 2; mt++)
            #pragma unroll
            for (int e = 0; e < 4; e++) acc2[j][mt][e] = 0.f;

    #pragma unroll
    for (int s = 0; s < 8; s++) {
        uint32_t a[2][4];
        #pragma unroll
        for (int mt = 0; mt < 2; mt++) {
            uint32_t u = 2 * s + gh;
            LDSM4(a[mt][0], a[mt][1], a[mt][2], a[mt][3],
                  sb + AL_OFF + rA2b[mt] + ((u ^ xA2[mt]) << 4));
        }
        uint32_t bt[4][4];
        uint32_t qrow = (uint32_t)(s * 16 + qbase);
        #pragma unroll
        for (int t = 0; t < 4; t++) {
            uint32_t u = 2 * t + gh;
            LDSM4T(bt[t][0], bt[t][1], bt[t][2], bt[t][3],
                   Bs + qrow * 128 + ((u ^ (uint32_t)l7) << 4));
        }
        #pragma unroll
        for (int mt = 0; mt < 2; mt++)
            #pragma unroll
            for (int t = 0; t < 4; t++) {
                mma16(acc2[2 * t][mt],     a[mt][0], a[mt][1], a[mt][2], a[mt][3], bt[t][0], bt[t][1]);
                mma16(acc2[2 * t + 1][mt], a[mt][0], a[mt][1], a[mt][2], a[mt][3], bt[t][2], bt[t][3]);
            }
    }

    // ---- epilogue: out0 = ctx, out1 = a, out2 = ctx*a ----
    const size_t obase = ((size_t)(b * C_) + ct * 128) * (4 * H_);
    #pragma unroll
    for (int mt = 0; mt < 2; mt++)
        #pragma unroll
        for (int h = 0; h < 2; h++) {
            int row = mw * 32 + mt * 16 + h * 8 + (lane >> 2);
            float ivr = iv[mt * 2 + h];
            #pragma unroll
            for (int j = 0; j < 8; j++) {
                int col = nw * 64 + j * 8 + 2 * (lane & 3);
                float2 c = *(const float2*)(ctxb + row * 256 + col);
                float a0 = acc2[j][mt][2 * h] * ivr;
                float a1 = acc2[j][mt][2 * h + 1] * ivr;
                float* o = out + obase + (size_t)row * 1024 + col;
                *(float2*)o = c;
                *(float2*)(o + 256) = make_float2(a0, a1);
                *(float2*)(o + 512) = make_float2(c.x * a0, c.y * a1);
            }
        }
}

// ============================ K2 ============================
__global__ __launch_bounds__(256, 1)
void k2_beta(const float* __restrict__ ctx)
{
    __shared__ float smm[1024];
    __shared__ float se[128];
    __shared__ float red[8];
    const int tid = threadIdx.x, lane = tid & 31, warp = tid >> 5;
    const int b = blockIdx.x >> 3, ch = blockIdx.x & 7;

    float lm = -1e30f;
    for (int i = tid; i < 1024; i += 256) {
        float v = g_m[b * 1024 + i];
        smm[i] = v; lm = fmaxf(lm, v);
    }
    for (int o = 16; o; o >>= 1) lm = fmaxf(lm, __shfl_xor_sync(~0u, lm, o));
    if (lane == 0) red[warp] = lm;
    __syncthreads();
    float M = red[0];
    #pragma unroll
    for (int i = 1; i < 8; i++) M = fmaxf(M, red[i]);
    __syncthreads();
    if (tid < 128) se[tid] = __expf(smm[ch * 128 + tid] - M);
    __syncthreads();
    if (tid < 128) {
        float v = se[tid];
        for (int o = 16; o; o >>= 1) v += __shfl_xor_sync(~0u, v, o);
        if (lane == 0) red[warp] = v;
    }
    __syncthreads();
    if (tid == 0) g_zpart[blockIdx.x] = red[0] + red[1] + red[2] + red[3];

    const float* cb = ctx + ((size_t)b * 1024 + ch * 128) * 256;
    float acc = 0.f;
    #pragma unroll 16
    for (int c = 0; c < 128; c++) acc += se[c] * cb[(size_t)c * 256 + tid];
    g_bpart[(size_t)blockIdx.x * 256 + tid] = acc;
}

// ============================ K3 ============================
__global__ __launch_bounds__(256, 1)
void k3_cb(const float* __restrict__ ctx, float* __restrict__ out)
{
    __shared__ float bv[256];
    const int tid = threadIdx.x;
    const int b = blockIdx.x >> 3, ch = blockIdx.x & 7;
    float z = 0.f, a = 0.f;
    #pragma unroll
    for (int p = 0; p < 8; p++) {
        z += g_zpart[b * 8 + p];
        a += g_bpart[(size_t)(b * 8 + p) * 256 + tid];
    }
    bv[tid] = a / z;
    __syncthreads();
    const float* cb = ctx + ((size_t)b * 1024 + ch * 128) * 256;
    float* ob = out + ((size_t)(b * 1024) + ch * 128) * 1024 + 768;
    #pragma unroll 4
    for (int i = 0; i < 32; i++) {
        int f = i * 256 + tid;
        int row = f >> 6, c4 = (f & 63) * 4;
        float4 cv = *(const float4*)(cb + row * 256 + c4);
        float4 bb = *(const float4*)(bv + c4);
        float4 r = { cv.x * bb.x, cv.y * bb.y, cv.z * bb.z, cv.w * bb.w };
        *(float4*)(ob + (size_t)row * 1024 + c4) = r;
    }
}

extern "C" void kernel_launch(void* const* d_in, const int* in_sizes, int n_in,
                              void* d_out, int out_size)
{
    const float* ctx  = (const float*)d_in[0];
    const float* qry  = (const float*)d_in[2];
    const float* attw = (const float*)d_in[4];
    const float* attb = (const float*)d_in[5];
    float* out = (float*)d_out;

    cudaFuncSetAttribute(k1_main, cudaFuncAttributeMaxDynamicSharedMemorySize, SMEM_TOTAL);
    k1_main<<<512, 512, SMEM_TOTAL>>>(ctx, qry, attw, attb, out);
    k2_beta<<<512, 256>>>(ctx);
    k3_cb<<<512, 256>>>(ctx, out);
}

// round 8
// speedup vs baseline: 1.6977x; 1.0175x over previous
#include <cuda_runtime.h>
#include <cstdint>

#define B_ 64
#define C_ 1024
#define Q_ 128
#define H_ 256

// ---- scratch ----
__device__ float g_m[B_ * C_];
__device__ float g_bpart[B_ * 8 * H_];
__device__ float g_zpart[B_ * 8];

// ---- smem byte offsets ----
#define SM_W     0        // 768 f32 (w_c | w_q | w_m)
#define SM_ROWC  3072     // 128 f32
#define SM_ROWQ  3584     // 128 f32
#define SM_SMAX  4096     // 128x4 f32
#define SM_SSUM  6144     // 128x4 f32
#define SM_SINV  8192     // 128 f32
#define SM_BIAS  8704
#define A_OFF    12288    // 4 x 16KB resident fp16 (ctx*w_m) h-chunks
#define AL_OFF   12288    // alpha fp16 [128][128] 32KB, overlays A after GEMM1
#define B1_OFF   77824    // 4 x 16KB resident fp16 qry h-chunks ([q][64h] each)
#define SMEM_TOTAL 143360

__device__ __forceinline__ uint32_t smem_u32(const void* p) {
    uint32_t a; asm("{ .reg .u64 t; cvta.to.shared.u64 t, %1; cvt.u32.u64 %0, t; }" : "=r"(a) : "l"(p));
    return a;
}
__device__ __forceinline__ uint32_t pack2(float lo, float hi) {   // f16x2 {lo, hi}
    uint32_t r; asm("cvt.rn.f16x2.f32 %0, %1, %2;" : "=r"(r) : "f"(hi), "f"(lo)); return r;
}
__device__ __forceinline__ void mma16(float d[4], uint32_t a0, uint32_t a1, uint32_t a2, uint32_t a3,
                                      uint32_t b0, uint32_t b1) {
    asm volatile(
        "mma.sync.aligned.m16n8k16.row.col.f32.f16.f16.f32 "
        "{%0,%1,%2,%3}, {%4,%5,%6,%7}, {%8,%9}, {%0,%1,%2,%3};"
        : "+f"(d[0]), "+f"(d[1]), "+f"(d[2]), "+f"(d[3])
        : "r"(a0), "r"(a1), "r"(a2), "r"(a3), "r"(b0), "r"(b1));
}
#define LDSM4(r0, r1, r2, r3, addr) \
    asm volatile("ldmatrix.sync.aligned.m8n8.x4.shared.b16 {%0,%1,%2,%3}, [%4];" \
        : "=r"(r0), "=r"(r1), "=r"(r2), "=r"(r3) : "r"(addr))
#define LDSM4T(r0, r1, r2, r3, addr) \
    asm volatile("ldmatrix.sync.aligned.m8n8.x4.trans.shared.b16 {%0,%1,%2,%3}, [%4];" \
        : "=r"(r0), "=r"(r1), "=r"(r2), "=r"(r3) : "r"(addr))

// ============================ K1 ============================
__global__ __launch_bounds__(512, 1)
void k1_main(const float* __restrict__ ctx, const float* __restrict__ qry,
             const float* __restrict__ attw, const float* __restrict__ attb,
             float* __restrict__ out)
{
    extern __shared__ __align__(1024) char smem[];
    float* smf = (float*)smem;
    const uint32_t sb = smem_u32(smem);
    const int tid = threadIdx.x, warp = tid >> 5, lane = tid & 31;
    const int mw = warp >> 2, nw = warp & 3;
    const int g = lane >> 3, l7 = lane & 7, gb = g & 1, gh = g >> 1;
    const int b = blockIdx.x >> 3, ct = blockIdx.x & 7;
    const float* ctxb = ctx + ((size_t)(b * C_) + ct * 128) * H_;
    const float* qryb = qry + (size_t)b * Q_ * H_;

    for (int i = tid; i < 768; i += 512) smf[i] = attw[i];
    if (tid == 0) smf[SM_BIAS / 4] = attb[0];
    __syncthreads();

    // ---- Phase A0: dot products + stage ALL fp16 operands from in-flight regs ----
    {
        const float4 wc1 = *(const float4*)(smf + lane * 4);
        const float4 wc2 = *(const float4*)(smf + 128 + lane * 4);
        const float4 wq1 = *(const float4*)(smf + 256 + lane * 4);
        const float4 wq2 = *(const float4*)(smf + 256 + 128 + lane * 4);
        const float4 wm1 = *(const float4*)(smf + 512 + lane * 4);
        const float4 wm2 = *(const float4*)(smf + 512 + 128 + lane * 4);
        const int j = lane & 15, s1 = lane >> 4;
        for (int i = 0; i < 8; i++) {
            int r = warp * 8 + i;
            float4 q1 = *(const float4*)(qryb + r * H_ + lane * 4);
            float4 q2 = *(const float4*)(qryb + r * H_ + 128 + lane * 4);
            float4 c1 = *(const float4*)(ctxb + r * H_ + lane * 4);
            float4 c2 = *(const float4*)(ctxb + r * H_ + 128 + lane * 4);
            uint32_t off = r * 128 + (((j >> 1) ^ (r & 7)) << 4) + (j & 1) * 8;
            // qry -> B1 slots
            *(uint2*)(smem + B1_OFF + s1 * 16384 + off) =
                make_uint2(pack2(q1.x, q1.y), pack2(q1.z, q1.w));
            *(uint2*)(smem + B1_OFF + (2 + s1) * 16384 + off) =
                make_uint2(pack2(q2.x, q2.y), pack2(q2.z, q2.w));
            // ctx*w_m -> A slots
            *(uint2*)(smem + A_OFF + s1 * 16384 + off) =
                make_uint2(pack2(c1.x * wm1.x, c1.y * wm1.y), pack2(c1.z * wm1.z, c1.w * wm1.w));
            *(uint2*)(smem + A_OFF + (2 + s1) * 16384 + off) =
                make_uint2(pack2(c2.x * wm2.x, c2.y * wm2.y), pack2(c2.z * wm2.z, c2.w * wm2.w));

            float aq = q1.x * wq1.x + q1.y * wq1.y + q1.z * wq1.z + q1.w * wq1.w
                     + q2.x * wq2.x + q2.y * wq2.y + q2.z * wq2.z + q2.w * wq2.w;
            float ac = c1.x * wc1.x + c1.y * wc1.y + c1.z * wc1.z + c1.w * wc1.w
                     + c2.x * wc2.x + c2.y * wc2.y + c2.z * wc2.z + c2.w * wc2.w;
            for (int o = 16; o; o >>= 1) {
                aq += __shfl_xor_sync(~0u, aq, o);
                ac += __shfl_xor_sync(~0u, ac, o);
            }
            if (lane == 0) { smf[SM_ROWQ / 4 + r] = aq; smf[SM_ROWC / 4 + r] = ac; }
        }
    }
    __syncthreads();

    // ---- GEMM1: sim = (ctx*w_m) @ qry^T fp16 ; barrier-free 16 k-steps ----
    float acc1[2][4][4];
    #pragma unroll
    for (int mt = 0; mt < 2; mt++)
        #pragma unroll
        for (int j = 0; j < 4; j++)
            #pragma unroll
            for (int e = 0; e < 4; e++) acc1[mt][j][e] = 0.f;

    uint32_t rAb[2], xA[2], rBb[2], xB[2];
    #pragma unroll
    for (int mt = 0; mt < 2; mt++) {
        int row = mw * 32 + mt * 16 + gb * 8 + l7;
        rAb[mt] = row * 128; xA[mt] = row & 7;
    }
    #pragma unroll
    for (int p = 0; p < 2; p++) {
        int row = nw * 32 + p * 16 + gh * 8 + l7;
        rBb[p] = row * 128; xB[p] = row & 7;
    }

    #pragma unroll
    for (int kc = 0; kc < 4; kc++) {
        uint32_t Ab = sb + A_OFF + kc * 16384;
        uint32_t Bb = sb + B1_OFF + kc * 16384;
        #pragma unroll
        for (int ks = 0; ks < 4; ks++) {
            uint32_t a[2][4], bf[2][4];
            #pragma unroll
            for (int mt = 0; mt < 2; mt++) {
                uint32_t u = 2 * ks + gh;
                LDSM4(a[mt][0], a[mt][1], a[mt][2], a[mt][3], Ab + rAb[mt] + ((u ^ xA[mt]) << 4));
            }
            #pragma unroll
            for (int p = 0; p < 2; p++) {
                uint32_t u = 2 * ks + gb;
                LDSM4(bf[p][0], bf[p][1], bf[p][2], bf[p][3], Bb + rBb[p] + ((u ^ xB[p]) << 4));
            }
            #pragma unroll
            for (int mt = 0; mt < 2; mt++)
                #pragma unroll
                for (int p = 0; p < 2; p++) {
                    mma16(acc1[mt][2 * p],     a[mt][0], a[mt][1], a[mt][2], a[mt][3], bf[p][0], bf[p][1]);
                    mma16(acc1[mt][2 * p + 1], a[mt][0], a[mt][1], a[mt][2], a[mt][3], bf[p][2], bf[p][3]);
                }
        }
    }

    // ---- softmax; alpha fp16 -> AL_OFF (overlays A; sync below fences GEMM1 reads) ----
    const float* rqv = smf + SM_ROWQ / 4;
    float vmax[4] = { -1e30f, -1e30f, -1e30f, -1e30f };
    #pragma unroll
    for (int mt = 0; mt < 2; mt++)
        #pragma unroll
        for (int jt = 0; jt < 4; jt++) {
            int c0 = nw * 32 + jt * 8 + 2 * (lane & 3);
            float r0 = rqv[c0], r1 = rqv[c0 + 1];
            vmax[2 * mt]     = fmaxf(vmax[2 * mt],     fmaxf(acc1[mt][jt][0] + r0, acc1[mt][jt][1] + r1));
            vmax[2 * mt + 1] = fmaxf(vmax[2 * mt + 1], fmaxf(acc1[mt][jt][2] + r0, acc1[mt][jt][3] + r1));
        }
    #pragma unroll
    for (int r = 0; r < 4; r++) {
        vmax[r] = fmaxf(vmax[r], __shfl_xor_sync(~0u, vmax[r], 1));
        vmax[r] = fmaxf(vmax[r], __shfl_xor_sync(~0u, vmax[r], 2));
    }
    if ((lane & 3) == 0)
        #pragma unroll
        for (int r = 0; r < 4; r++) {
            int row = mw * 32 + (r >> 1) * 16 + (r & 1) * 8 + (lane >> 2);
            smf[SM_SMAX / 4 + row * 4 + nw] = vmax[r];
        }
    __syncthreads();
    float rmax[4], rsum[4] = { 0.f, 0.f, 0.f, 0.f };
    #pragma unroll
    for (int r = 0; r < 4; r++) {
        int row = mw * 32 + (r >> 1) * 16 + (r & 1) * 8 + (lane >> 2);
        float m0 = fmaxf(smf[SM_SMAX / 4 + row * 4],     smf[SM_SMAX / 4 + row * 4 + 1]);
        float m1 = fmaxf(smf[SM_SMAX / 4 + row * 4 + 2], smf[SM_SMAX / 4 + row * 4 + 3]);
        rmax[r] = fmaxf(m0, m1);
    }
    #pragma unroll
    for (int mt = 0; mt < 2; mt++)
        #pragma unroll
        for (int jt = 0; jt < 4; jt++) {
            int c0 = nw * 32 + jt * 8 + 2 * (lane & 3);
            float r0 = rqv[c0], r1 = rqv[c0 + 1];
            float e0 = __expf(acc1[mt][jt][0] + r0 - rmax[2 * mt]);
            float e1 = __expf(acc1[mt][jt][1] + r1 - rmax[2 * mt]);
            float e2 = __expf(acc1[mt][jt][2] + r0 - rmax[2 * mt + 1]);
            float e3 = __expf(acc1[mt][jt][3] + r1 - rmax[2 * mt + 1]);
            rsum[2 * mt] += e0 + e1; rsum[2 * mt + 1] += e2 + e3;
            int rowA = mw * 32 + mt * 16 + (lane >> 2);
            int rowB = rowA + 8;
            int unit = nw * 4 + jt;
            *(uint32_t*)(smem + AL_OFF + rowA * 256 + ((unit ^ (rowA & 7)) << 4) + (lane & 3) * 4)
                = pack2(e0, e1);
            *(uint32_t*)(smem + AL_OFF + rowB * 256 + ((unit ^ (rowB & 7)) << 4) + (lane & 3) * 4)
                = pack2(e2, e3);
        }
    #pragma unroll
    for (int r = 0; r < 4; r++) {
        rsum[r] += __shfl_xor_sync(~0u, rsum[r], 1);
        rsum[r] += __shfl_xor_sync(~0u, rsum[r], 2);
    }
    if ((lane & 3) == 0)
        #pragma unroll
        for (int r = 0; r < 4; r++) {
            int row = mw * 32 + (r >> 1) * 16 + (r & 1) * 8 + (lane >> 2);
            smf[SM_SSUM / 4 + row * 4 + nw] = rsum[r];
        }
    __syncthreads();
    if (nw == 0 && (lane & 3) == 0) {
        float bias = smf[SM_BIAS / 4];
        #pragma unroll
        for (int r = 0; r < 4; r++) {
            int row = mw * 32 + (r >> 1) * 16 + (r & 1) * 8 + (lane >> 2);
            float tot = smf[SM_SSUM / 4 + row * 4]     + smf[SM_SSUM / 4 + row * 4 + 1]
                      + smf[SM_SSUM / 4 + row * 4 + 2] + smf[SM_SSUM / 4 + row * 4 + 3];
            smf[SM_SINV / 4 + row] = 1.0f / tot;
            g_m[b * C_ + ct * 128 + row] = rmax[r] + smf[SM_ROWC / 4 + row] + bias;
        }
    }
    __syncthreads();

    // ---- GEMM2: D = E @ qry fp16 ; warp n-tile = 64 (slot nw), K=128 ----
    float iv[4];
    #pragma unroll
    for (int r = 0; r < 4; r++) {
        int row = mw * 32 + (r >> 1) * 16 + (r & 1) * 8 + (lane >> 2);
        iv[r] = smf[SM_SINV / 4 + row];
    }
    uint32_t rA2b[2], xA2[2];
    #pragma unroll
    for (int mt = 0; mt < 2; mt++) {
        int row = mw * 32 + mt * 16 + gb * 8 + l7;
        rA2b[mt] = row * 256; xA2[mt] = row & 7;
    }
    const uint32_t Bs = sb + B1_OFF + nw * 16384;
    const int qbase = gb * 8 + l7;

    float acc2[8][2][4];
    #pragma unroll
    for (int j = 0; j < 8; j++)
        #pragma unroll
        for (int mt = 0; mt < 2; mt++)
            #pragma unroll
            for (int e = 0; e < 4; e++) acc2[j][mt][e] = 0.f;

    #pragma unroll
    for (int s = 0; s < 8; s++) {
        uint32_t a[2][4];
        #pragma unroll
        for (int mt = 0; mt < 2; mt++) {
            uint32_t u = 2 * s + gh;
            LDSM4(a[mt][0], a[mt][1], a[mt][2], a[mt][3],
                  sb + AL_OFF + rA2b[mt] + ((u ^ xA2[mt]) << 4));
        }
        uint32_t bt[4][4];
        uint32_t qrow = (uint32_t)(s * 16 + qbase);
        #pragma unroll
        for (int t = 0; t < 4; t++) {
            uint32_t u = 2 * t + gh;
            LDSM4T(bt[t][0], bt[t][1], bt[t][2], bt[t][3],
                   Bs + qrow * 128 + ((u ^ (uint32_t)l7) << 4));
        }
        #pragma unroll
        for (int mt = 0; mt < 2; mt++)
            #pragma unroll
            for (int t = 0; t < 4; t++) {
                mma16(acc2[2 * t][mt],     a[mt][0], a[mt][1], a[mt][2], a[mt][3], bt[t][0], bt[t][1]);
                mma16(acc2[2 * t + 1][mt], a[mt][0], a[mt][1], a[mt][2], a[mt][3], bt[t][2], bt[t][3]);
            }
    }

    // ---- epilogue: out0 = ctx, out1 = a, out2 = ctx*a ----
    const size_t obase = ((size_t)(b * C_) + ct * 128) * (4 * H_);
    #pragma unroll
    for (int mt = 0; mt < 2; mt++)
        #pragma unroll
        for (int h = 0; h < 2; h++) {
            int row = mw * 32 + mt * 16 + h * 8 + (lane >> 2);
            float ivr = iv[mt * 2 + h];
            #pragma unroll
            for (int j = 0; j < 8; j++) {
                int col = nw * 64 + j * 8 + 2 * (lane & 3);
                float2 c = *(const float2*)(ctxb + row * 256 + col);
                float a0 = acc2[j][mt][2 * h] * ivr;
                float a1 = acc2[j][mt][2 * h + 1] * ivr;
                float* o = out + obase + (size_t)row * 1024 + col;
                *(float2*)o = c;
                *(float2*)(o + 256) = make_float2(a0, a1);
                *(float2*)(o + 512) = make_float2(c.x * a0, c.y * a1);
            }
        }
}

// ============================ K2 ============================
__global__ __launch_bounds__(256, 1)
void k2_beta(const float* __restrict__ ctx)
{
    __shared__ float smm[1024];
    __shared__ float se[128];
    __shared__ float red[8];
    const int tid = threadIdx.x, lane = tid & 31, warp = tid >> 5;
    const int b = blockIdx.x >> 3, ch = blockIdx.x & 7;

    float lm = -1e30f;
    for (int i = tid; i < 1024; i += 256) {
        float v = g_m[b * 1024 + i];
        smm[i] = v; lm = fmaxf(lm, v);
    }
    for (int o = 16; o; o >>= 1) lm = fmaxf(lm, __shfl_xor_sync(~0u, lm, o));
    if (lane == 0) red[warp] = lm;
    __syncthreads();
    float M = red[0];
    #pragma unroll
    for (int i = 1; i < 8; i++) M = fmaxf(M, red[i]);
    __syncthreads();
    if (tid < 128) se[tid] = __expf(smm[ch * 128 + tid] - M);
    __syncthreads();
    if (tid < 128) {
        float v = se[tid];
        for (int o = 16; o; o >>= 1) v += __shfl_xor_sync(~0u, v, o);
        if (lane == 0) red[warp] = v;
    }
    __syncthreads();
    if (tid == 0) g_zpart[blockIdx.x] = red[0] + red[1] + red[2] + red[3];

    const float* cb = ctx + ((size_t)b * 1024 + ch * 128) * 256;
    float acc = 0.f;
    #pragma unroll 16
    for (int c = 0; c < 128; c++) acc += se[c] * cb[(size_t)c * 256 + tid];
    g_bpart[(size_t)blockIdx.x * 256 + tid] = acc;
}

// ============================ K3 ============================
__global__ __launch_bounds__(256, 1)
void k3_cb(const float* __restrict__ ctx, float* __restrict__ out)
{
    __shared__ float bv[256];
    const int tid = threadIdx.x;
    const int b = blockIdx.x >> 3, ch = blockIdx.x & 7;
    float z = 0.f, a = 0.f;
    #pragma unroll
    for (int p = 0; p < 8; p++) {
        z += g_zpart[b * 8 + p];
        a += g_bpart[(size_t)(b * 8 + p) * 256 + tid];
    }
    bv[tid] = a / z;
    __syncthreads();
    const float* cb = ctx + ((size_t)b * 1024 + ch * 128) * 256;
    float* ob = out + ((size_t)(b * 1024) + ch * 128) * 1024 + 768;
    #pragma unroll 4
    for (int i = 0; i < 32; i++) {
        int f = i * 256 + tid;
        int row = f >> 6, c4 = (f & 63) * 4;
        float4 cv = *(const float4*)(cb + row * 256 + c4);
        float4 bb = *(const float4*)(bv + c4);
        float4 r = { cv.x * bb.x, cv.y * bb.y, cv.z * bb.z, cv.w * bb.w };
        *(float4*)(ob + (size_t)row * 1024 + c4) = r;
    }
}

extern "C" void kernel_launch(void* const* d_in, const int* in_sizes, int n_in,
                              void* d_out, int out_size)
{
    const float* ctx  = (const float*)d_in[0];
    const float* qry  = (const float*)d_in[2];
    const float* attw = (const float*)d_in[4];
    const float* attb = (const float*)d_in[5];
    float* out = (float*)d_out;

    cudaFuncSetAttribute(k1_main, cudaFuncAttributeMaxDynamicSharedMemorySize, SMEM_TOTAL);
    k1_main<<<512, 512, SMEM_TOTAL>>>(ctx, qry, attw, attb, out);
    k2_beta<<<512, 256>>>(ctx);
    k3_cb<<<512, 256>>>(ctx, out);
}

// round 9
// speedup vs baseline: 1.8067x; 1.0642x over previous
#include <cuda_runtime.h>
#include <cstdint>

#define B_ 64
#define C_ 1024
#define Q_ 128
#define H_ 256

// ---- scratch ----
__device__ float g_m[B_ * C_];
__device__ float g_bpart[B_ * 8 * H_];
__device__ float g_zpart[B_ * 8];

// ---- smem byte offsets (per-CTA, 64-row m-tile) ----
#define SM_W     0        // 768 f32
#define SM_ROWC  3072     // 64 f32
#define SM_ROWQ  3328     // 128 f32
#define SM_SMAX  3840     // 64x4 f32
#define SM_SSUM  4864     // 64x4 f32
#define SM_SINV  5888     // 64 f32
#define SM_BIAS  6144
#define A_OFF    8192     // 4 x 8KB resident fp16 (ctx*w_m) h-chunks (64 rows)
#define AL_OFF   8192     // alpha fp16 [64][128] 16KB, overlays A after GEMM1
#define B1_OFF   40960    // 4 x 16KB resident fp16 qry h-chunks ([128 q][64h])
#define SMEM_TOTAL 106496

__device__ __forceinline__ uint32_t smem_u32(const void* p) {
    uint32_t a; asm("{ .reg .u64 t; cvta.to.shared.u64 t, %1; cvt.u32.u64 %0, t; }" : "=r"(a) : "l"(p));
    return a;
}
__device__ __forceinline__ uint32_t pack2(float lo, float hi) {
    uint32_t r; asm("cvt.rn.f16x2.f32 %0, %1, %2;" : "=r"(r) : "f"(hi), "f"(lo)); return r;
}
__device__ __forceinline__ void mma16(float d[4], uint32_t a0, uint32_t a1, uint32_t a2, uint32_t a3,
                                      uint32_t b0, uint32_t b1) {
    asm volatile(
        "mma.sync.aligned.m16n8k16.row.col.f32.f16.f16.f32 "
        "{%0,%1,%2,%3}, {%4,%5,%6,%7}, {%8,%9}, {%0,%1,%2,%3};"
        : "+f"(d[0]), "+f"(d[1]), "+f"(d[2]), "+f"(d[3])
        : "r"(a0), "r"(a1), "r"(a2), "r"(a3), "r"(b0), "r"(b1));
}
#define LDSM4(r0, r1, r2, r3, addr) \
    asm volatile("ldmatrix.sync.aligned.m8n8.x4.shared.b16 {%0,%1,%2,%3}, [%4];" \
        : "=r"(r0), "=r"(r1), "=r"(r2), "=r"(r3) : "r"(addr))
#define LDSM4T(r0, r1, r2, r3, addr) \
    asm volatile("ldmatrix.sync.aligned.m8n8.x4.trans.shared.b16 {%0,%1,%2,%3}, [%4];" \
        : "=r"(r0), "=r"(r1), "=r"(r2), "=r"(r3) : "r"(addr))

// ============================ K1 ============================
__global__ __launch_bounds__(256, 2)
void k1_main(const float* __restrict__ ctx, const float* __restrict__ qry,
             const float* __restrict__ attw, const float* __restrict__ attb,
             float* __restrict__ out)
{
    extern __shared__ __align__(1024) char smem[];
    float* smf = (float*)smem;
    const uint32_t sb = smem_u32(smem);
    const int tid = threadIdx.x, warp = tid >> 5, lane = tid & 31;
    const int mw = warp >> 2, nw = warp & 3;
    const int g = lane >> 3, l7 = lane & 7, gb = g & 1, gh = g >> 1;
    const int b = blockIdx.x >> 4, ct = blockIdx.x & 15;
    const float* ctxb = ctx + ((size_t)(b * C_) + ct * 64) * H_;
    const float* qryb = qry + (size_t)b * Q_ * H_;

    for (int i = tid; i < 768; i += 256) smf[i] = attw[i];
    if (tid == 0) smf[SM_BIAS / 4] = attb[0];
    __syncthreads();

    // ---- Phase A0: stage qry (128 rows) + ctx*w_m (64 rows) fp16, dots ----
    {
        const float4 wc1 = *(const float4*)(smf + lane * 4);
        const float4 wc2 = *(const float4*)(smf + 128 + lane * 4);
        const float4 wq1 = *(const float4*)(smf + 256 + lane * 4);
        const float4 wq2 = *(const float4*)(smf + 256 + 128 + lane * 4);
        const float4 wm1 = *(const float4*)(smf + 512 + lane * 4);
        const float4 wm2 = *(const float4*)(smf + 512 + 128 + lane * 4);
        const int j = lane & 15, s1 = lane >> 4;
        #pragma unroll 4
        for (int i = 0; i < 16; i++) {          // qry rows
            int r = warp * 16 + i;
            float4 q1 = *(const float4*)(qryb + r * H_ + lane * 4);
            float4 q2 = *(const float4*)(qryb + r * H_ + 128 + lane * 4);
            uint32_t off = r * 128 + (((j >> 1) ^ (r & 7)) << 4) + (j & 1) * 8;
            *(uint2*)(smem + B1_OFF + s1 * 16384 + off) =
                make_uint2(pack2(q1.x, q1.y), pack2(q1.z, q1.w));
            *(uint2*)(smem + B1_OFF + (2 + s1) * 16384 + off) =
                make_uint2(pack2(q2.x, q2.y), pack2(q2.z, q2.w));
            float aq = q1.x * wq1.x + q1.y * wq1.y + q1.z * wq1.z + q1.w * wq1.w
                     + q2.x * wq2.x + q2.y * wq2.y + q2.z * wq2.z + q2.w * wq2.w;
            for (int o = 16; o; o >>= 1) aq += __shfl_xor_sync(~0u, aq, o);
            if (lane == 0) smf[SM_ROWQ / 4 + r] = aq;
        }
        #pragma unroll 4
        for (int i = 0; i < 8; i++) {           // ctx rows
            int r = warp * 8 + i;
            float4 c1 = *(const float4*)(ctxb + r * H_ + lane * 4);
            float4 c2 = *(const float4*)(ctxb + r * H_ + 128 + lane * 4);
            uint32_t off = r * 128 + (((j >> 1) ^ (r & 7)) << 4) + (j & 1) * 8;
            *(uint2*)(smem + A_OFF + s1 * 8192 + off) =
                make_uint2(pack2(c1.x * wm1.x, c1.y * wm1.y), pack2(c1.z * wm1.z, c1.w * wm1.w));
            *(uint2*)(smem + A_OFF + (2 + s1) * 8192 + off) =
                make_uint2(pack2(c2.x * wm2.x, c2.y * wm2.y), pack2(c2.z * wm2.z, c2.w * wm2.w));
            float ac = c1.x * wc1.x + c1.y * wc1.y + c1.z * wc1.z + c1.w * wc1.w
                     + c2.x * wc2.x + c2.y * wc2.y + c2.z * wc2.z + c2.w * wc2.w;
            for (int o = 16; o; o >>= 1) ac += __shfl_xor_sync(~0u, ac, o);
            if (lane == 0) smf[SM_ROWC / 4 + r] = ac;
        }
    }
    __syncthreads();

    // ---- GEMM1: sim = (ctx*w_m) @ qry^T ; M=64 N=128 K=256, barrier-free ----
    float acc1[2][4][4];
    #pragma unroll
    for (int mt = 0; mt < 2; mt++)
        #pragma unroll
        for (int j = 0; j < 4; j++)
            #pragma unroll
            for (int e = 0; e < 4; e++) acc1[mt][j][e] = 0.f;

    uint32_t rAb[2], xA[2], rBb[2], xB[2];
    #pragma unroll
    for (int mt = 0; mt < 2; mt++) {
        int row = mw * 32 + mt * 16 + gb * 8 + l7;       // 0..63
        rAb[mt] = row * 128; xA[mt] = row & 7;
    }
    #pragma unroll
    for (int p = 0; p < 2; p++) {
        int row = nw * 32 + p * 16 + gh * 8 + l7;        // 0..127
        rBb[p] = row * 128; xB[p] = row & 7;
    }

    #pragma unroll
    for (int kc = 0; kc < 4; kc++) {
        uint32_t Ab = sb + A_OFF + kc * 8192;
        uint32_t Bb = sb + B1_OFF + kc * 16384;
        #pragma unroll
        for (int ks = 0; ks < 4; ks++) {
            uint32_t a[2][4], bf[2][4];
            #pragma unroll
            for (int mt = 0; mt < 2; mt++) {
                uint32_t u = 2 * ks + gh;
                LDSM4(a[mt][0], a[mt][1], a[mt][2], a[mt][3], Ab + rAb[mt] + ((u ^ xA[mt]) << 4));
            }
            #pragma unroll
            for (int p = 0; p < 2; p++) {
                uint32_t u = 2 * ks + gb;
                LDSM4(bf[p][0], bf[p][1], bf[p][2], bf[p][3], Bb + rBb[p] + ((u ^ xB[p]) << 4));
            }
            #pragma unroll
            for (int mt = 0; mt < 2; mt++)
                #pragma unroll
                for (int p = 0; p < 2; p++) {
                    mma16(acc1[mt][2 * p],     a[mt][0], a[mt][1], a[mt][2], a[mt][3], bf[p][0], bf[p][1]);
                    mma16(acc1[mt][2 * p + 1], a[mt][0], a[mt][1], a[mt][2], a[mt][3], bf[p][2], bf[p][3]);
                }
        }
    }

    // ---- softmax; alpha fp16 -> AL_OFF (overlays A) ----
    const float* rqv = smf + SM_ROWQ / 4;
    float vmax[4] = { -1e30f, -1e30f, -1e30f, -1e30f };
    #pragma unroll
    for (int mt = 0; mt < 2; mt++)
        #pragma unroll
        for (int jt = 0; jt < 4; jt++) {
            int c0 = nw * 32 + jt * 8 + 2 * (lane & 3);
            float r0 = rqv[c0], r1 = rqv[c0 + 1];
            vmax[2 * mt]     = fmaxf(vmax[2 * mt],     fmaxf(acc1[mt][jt][0] + r0, acc1[mt][jt][1] + r1));
            vmax[2 * mt + 1] = fmaxf(vmax[2 * mt + 1], fmaxf(acc1[mt][jt][2] + r0, acc1[mt][jt][3] + r1));
        }
    #pragma unroll
    for (int r = 0; r < 4; r++) {
        vmax[r] = fmaxf(vmax[r], __shfl_xor_sync(~0u, vmax[r], 1));
        vmax[r] = fmaxf(vmax[r], __shfl_xor_sync(~0u, vmax[r], 2));
    }
    if ((lane & 3) == 0)
        #pragma unroll
        for (int r = 0; r < 4; r++) {
            int row = mw * 32 + (r >> 1) * 16 + (r & 1) * 8 + (lane >> 2);
            smf[SM_SMAX / 4 + row * 4 + nw] = vmax[r];
        }
    __syncthreads();
    float rmax[4], rsum[4] = { 0.f, 0.f, 0.f, 0.f };
    #pragma unroll
    for (int r = 0; r < 4; r++) {
        int row = mw * 32 + (r >> 1) * 16 + (r & 1) * 8 + (lane >> 2);
        float m0 = fmaxf(smf[SM_SMAX / 4 + row * 4],     smf[SM_SMAX / 4 + row * 4 + 1]);
        float m1 = fmaxf(smf[SM_SMAX / 4 + row * 4 + 2], smf[SM_SMAX / 4 + row * 4 + 3]);
        rmax[r] = fmaxf(m0, m1);
    }
    #pragma unroll
    for (int mt = 0; mt < 2; mt++)
        #pragma unroll
        for (int jt = 0; jt < 4; jt++) {
            int c0 = nw * 32 + jt * 8 + 2 * (lane & 3);
            float r0 = rqv[c0], r1 = rqv[c0 + 1];
            float e0 = __expf(acc1[mt][jt][0] + r0 - rmax[2 * mt]);
            float e1 = __expf(acc1[mt][jt][1] + r1 - rmax[2 * mt]);
            float e2 = __expf(acc1[mt][jt][2] + r0 - rmax[2 * mt + 1]);
            float e3 = __expf(acc1[mt][jt][3] + r1 - rmax[2 * mt + 1]);
            rsum[2 * mt] += e0 + e1; rsum[2 * mt + 1] += e2 + e3;
            int rowA = mw * 32 + mt * 16 + (lane >> 2);
            int rowB = rowA + 8;
            int unit = nw * 4 + jt;
            *(uint32_t*)(smem + AL_OFF + rowA * 256 + ((unit ^ (rowA & 7)) << 4) + (lane & 3) * 4)
                = pack2(e0, e1);
            *(uint32_t*)(smem + AL_OFF + rowB * 256 + ((unit ^ (rowB & 7)) << 4) + (lane & 3) * 4)
                = pack2(e2, e3);
        }
    #pragma unroll
    for (int r = 0; r < 4; r++) {
        rsum[r] += __shfl_xor_sync(~0u, rsum[r], 1);
        rsum[r] += __shfl_xor_sync(~0u, rsum[r], 2);
    }
    if ((lane & 3) == 0)
        #pragma unroll
        for (int r = 0; r < 4; r++) {
            int row = mw * 32 + (r >> 1) * 16 + (r & 1) * 8 + (lane >> 2);
            smf[SM_SSUM / 4 + row * 4 + nw] = rsum[r];
        }
    __syncthreads();
    if (nw == 0 && (lane & 3) == 0) {
        float bias = smf[SM_BIAS / 4];
        #pragma unroll
        for (int r = 0; r < 4; r++) {
            int row = mw * 32 + (r >> 1) * 16 + (r & 1) * 8 + (lane >> 2);
            float tot = smf[SM_SSUM / 4 + row * 4]     + smf[SM_SSUM / 4 + row * 4 + 1]
                      + smf[SM_SSUM / 4 + row * 4 + 2] + smf[SM_SSUM / 4 + row * 4 + 3];
            smf[SM_SINV / 4 + row] = 1.0f / tot;
            g_m[b * C_ + ct * 64 + row] = rmax[r] + smf[SM_ROWC / 4 + row] + bias;
        }
    }
    __syncthreads();

    // ---- GEMM2: D = E @ qry ; M=64, warp n-tile 64 (slot nw), K=128 ----
    float iv[4];
    #pragma unroll
    for (int r = 0; r < 4; r++) {
        int row = mw * 32 + (r >> 1) * 16 + (r & 1) * 8 + (lane >> 2);
        iv[r] = smf[SM_SINV / 4 + row];
    }
    uint32_t rA2b[2], xA2[2];
    #pragma unroll
    for (int mt = 0; mt < 2; mt++) {
        int row = mw * 32 + mt * 16 + gb * 8 + l7;
        rA2b[mt] = row * 256; xA2[mt] = row & 7;
    }
    const uint32_t Bs = sb + B1_OFF + nw * 16384;
    const int qbase = gb * 8 + l7;

    float acc2[8][2][4];
    #pragma unroll
    for (int j = 0; j < 8; j++)
        #pragma unroll
        for (int mt = 0; mt < 2; mt++)
            #pragma unroll
            for (int e = 0; e < 4; e++) acc2[j][mt][e] = 0.f;

    #pragma unroll
    for (int s = 0; s < 8; s++) {
        uint32_t a[2][4];
        #pragma unroll
        for (int mt = 0; mt < 2; mt++) {
            uint32_t u = 2 * s + gh;
            LDSM4(a[mt][0], a[mt][1], a[mt][2], a[mt][3],
                  sb + AL_OFF + rA2b[mt] + ((u ^ xA2[mt]) << 4));
        }
        uint32_t bt[4][4];
        uint32_t qrow = (uint32_t)(s * 16 + qbase);
        #pragma unroll
        for (int t = 0; t < 4; t++) {
            uint32_t u = 2 * t + gh;
            LDSM4T(bt[t][0], bt[t][1], bt[t][2], bt[t][3],
                   Bs + qrow * 128 + ((u ^ (uint32_t)l7) << 4));
        }
        #pragma unroll
        for (int mt = 0; mt < 2; mt++)
            #pragma unroll
            for (int t = 0; t < 4; t++) {
                mma16(acc2[2 * t][mt],     a[mt][0], a[mt][1], a[mt][2], a[mt][3], bt[t][0], bt[t][1]);
                mma16(acc2[2 * t + 1][mt], a[mt][0], a[mt][1], a[mt][2], a[mt][3], bt[t][2], bt[t][3]);
            }
    }

    // ---- epilogue: out0 = ctx, out1 = a, out2 = ctx*a ----
    const size_t obase = ((size_t)(b * C_) + ct * 64) * (4 * H_);
    #pragma unroll
    for (int mt = 0; mt < 2; mt++)
        #pragma unroll
        for (int h = 0; h < 2; h++) {
            int row = mw * 32 + mt * 16 + h * 8 + (lane >> 2);
            float ivr = iv[mt * 2 + h];
            #pragma unroll
            for (int j = 0; j < 8; j++) {
                int col = nw * 64 + j * 8 + 2 * (lane & 3);
                float2 c = *(const float2*)(ctxb + row * 256 + col);
                float a0 = acc2[j][mt][2 * h] * ivr;
                float a1 = acc2[j][mt][2 * h + 1] * ivr;
                float* o = out + obase + (size_t)row * 1024 + col;
                *(float2*)o = c;
                *(float2*)(o + 256) = make_float2(a0, a1);
                *(float2*)(o + 512) = make_float2(c.x * a0, c.y * a1);
            }
        }
}

// ============================ K2 ============================
__global__ __launch_bounds__(256, 1)
void k2_beta(const float* __restrict__ ctx)
{
    __shared__ float smm[1024];
    __shared__ float se[128];
    __shared__ float red[8];
    const int tid = threadIdx.x, lane = tid & 31, warp = tid >> 5;
    const int b = blockIdx.x >> 3, ch = blockIdx.x & 7;

    float lm = -1e30f;
    for (int i = tid; i < 1024; i += 256) {
        float v = g_m[b * 1024 + i];
        smm[i] = v; lm = fmaxf(lm, v);
    }
    for (int o = 16; o; o >>= 1) lm = fmaxf(lm, __shfl_xor_sync(~0u, lm, o));
    if (lane == 0) red[warp] = lm;
    __syncthreads();
    float M = red[0];
    #pragma unroll
    for (int i = 1; i < 8; i++) M = fmaxf(M, red[i]);
    __syncthreads();
    if (tid < 128) se[tid] = __expf(smm[ch * 128 + tid] - M);
    __syncthreads();
    if (tid < 128) {
        float v = se[tid];
        for (int o = 16; o; o >>= 1) v += __shfl_xor_sync(~0u, v, o);
        if (lane == 0) red[warp] = v;
    }
    __syncthreads();
    if (tid == 0) g_zpart[blockIdx.x] = red[0] + red[1] + red[2] + red[3];

    const float* cb = ctx + ((size_t)b * 1024 + ch * 128) * 256;
    float acc = 0.f;
    #pragma unroll 16
    for (int c = 0; c < 128; c++) acc += se[c] * cb[(size_t)c * 256 + tid];
    g_bpart[(size_t)blockIdx.x * 256 + tid] = acc;
}

// ============================ K3 ============================
__global__ __launch_bounds__(256, 1)
void k3_cb(const float* __restrict__ ctx, float* __restrict__ out)
{
    __shared__ float bv[256];
    const int tid = threadIdx.x;
    const int b = blockIdx.x >> 3, ch = blockIdx.x & 7;
    float z = 0.f, a = 0.f;
    #pragma unroll
    for (int p = 0; p < 8; p++) {
        z += g_zpart[b * 8 + p];
        a += g_bpart[(size_t)(b * 8 + p) * 256 + tid];
    }
    bv[tid] = a / z;
    __syncthreads();
    const float* cb = ctx + ((size_t)b * 1024 + ch * 128) * 256;
    float* ob = out + ((size_t)(b * 1024) + ch * 128) * 1024 + 768;
    #pragma unroll 4
    for (int i = 0; i < 32; i++) {
        int f = i * 256 + tid;
        int row = f >> 6, c4 = (f & 63) * 4;
        float4 cv = *(const float4*)(cb + row * 256 + c4);
        float4 bb = *(const float4*)(bv + c4);
        float4 r = { cv.x * bb.x, cv.y * bb.y, cv.z * bb.z, cv.w * bb.w };
        *(float4*)(ob + (size_t)row * 1024 + c4) = r;
    }
}

extern "C" void kernel_launch(void* const* d_in, const int* in_sizes, int n_in,
                              void* d_out, int out_size)
{
    const float* ctx  = (const float*)d_in[0];
    const float* qry  = (const float*)d_in[2];
    const float* attw = (const float*)d_in[4];
    const float* attb = (const float*)d_in[5];
    float* out = (float*)d_out;

    cudaFuncSetAttribute(k1_main, cudaFuncAttributeMaxDynamicSharedMemorySize, SMEM_TOTAL);
    k1_main<<<1024, 256, SMEM_TOTAL>>>(ctx, qry, attw, attb, out);
    k2_beta<<<512, 256>>>(ctx);
    k3_cb<<<512, 256>>>(ctx, out);
}

// round 10
// speedup vs baseline: 1.8071x; 1.0003x over previous
#include <cuda_runtime.h>
#include <cstdint>

#define B_ 64
#define C_ 1024
#define Q_ 128
#define H_ 256

// ---- scratch ----
__device__ float g_m[B_ * C_];
__device__ float g_bpart[B_ * 8 * H_];
__device__ float g_zpart[B_ * 8];

// ---- smem byte offsets (per-CTA, 64-row m-tile) ----
#define SM_W     0        // 768 f32
#define SM_ROWC  3072     // 64 f32
#define SM_ROWQ  3328     // 128 f32
#define SM_SMAX  3840     // 64x4 f32
#define SM_SSUM  4864     // 64x4 f32
#define SM_SINV  5888     // 64 f32
#define SM_BIAS  6144
#define A_OFF    8192     // 4 x 8KB resident fp16 (ctx*w_m) h-chunks (64 rows)
#define AL_OFF   8192     // alpha fp16 [64][128] 16KB, overlays A after GEMM1
#define B1_OFF   40960    // 4 x 16KB resident fp16 qry h-chunks ([128 q][64h])
#define SMEM_TOTAL 106496

__device__ __forceinline__ uint32_t smem_u32(const void* p) {
    uint32_t a; asm("{ .reg .u64 t; cvta.to.shared.u64 t, %1; cvt.u32.u64 %0, t; }" : "=r"(a) : "l"(p));
    return a;
}
__device__ __forceinline__ uint32_t pack2(float lo, float hi) {
    uint32_t r; asm("cvt.rn.f16x2.f32 %0, %1, %2;" : "=r"(r) : "f"(hi), "f"(lo)); return r;
}
__device__ __forceinline__ void mma16(float d[4], uint32_t a0, uint32_t a1, uint32_t a2, uint32_t a3,
                                      uint32_t b0, uint32_t b1) {
    asm volatile(
        "mma.sync.aligned.m16n8k16.row.col.f32.f16.f16.f32 "
        "{%0,%1,%2,%3}, {%4,%5,%6,%7}, {%8,%9}, {%0,%1,%2,%3};"
        : "+f"(d[0]), "+f"(d[1]), "+f"(d[2]), "+f"(d[3])
        : "r"(a0), "r"(a1), "r"(a2), "r"(a3), "r"(b0), "r"(b1));
}
#define LDSM4(r0, r1, r2, r3, addr) \
    asm volatile("ldmatrix.sync.aligned.m8n8.x4.shared.b16 {%0,%1,%2,%3}, [%4];" \
        : "=r"(r0), "=r"(r1), "=r"(r2), "=r"(r3) : "r"(addr))
#define LDSM4T(r0, r1, r2, r3, addr) \
    asm volatile("ldmatrix.sync.aligned.m8n8.x4.trans.shared.b16 {%0,%1,%2,%3}, [%4];" \
        : "=r"(r0), "=r"(r1), "=r"(r2), "=r"(r3) : "r"(addr))

// ============================ K1 ============================
__global__ __launch_bounds__(256, 2)
void k1_main(const float* __restrict__ ctx, const float* __restrict__ qry,
             const float* __restrict__ attw, const float* __restrict__ attb,
             float* __restrict__ out)
{
    extern __shared__ __align__(1024) char smem[];
    float* smf = (float*)smem;
    const uint32_t sb = smem_u32(smem);
    const int tid = threadIdx.x, warp = tid >> 5, lane = tid & 31;
    const int mw = warp >> 2, nw = warp & 3;
    const int g = lane >> 3, l7 = lane & 7, gb = g & 1, gh = g >> 1;
    const int b = blockIdx.x >> 3, chalf = blockIdx.x & 7;
    const float* qryb = qry + (size_t)b * Q_ * H_;

    for (int i = tid; i < 768; i += 256) smf[i] = attw[i];
    if (tid == 0) smf[SM_BIAS / 4] = attb[0];
    __syncthreads();

    const float4 wc1 = *(const float4*)(smf + lane * 4);
    const float4 wc2 = *(const float4*)(smf + 128 + lane * 4);
    const float4 wm1 = *(const float4*)(smf + 512 + lane * 4);
    const float4 wm2 = *(const float4*)(smf + 512 + 128 + lane * 4);
    const int j = lane & 15, s1 = lane >> 4;

    // ---- stage qry fp16 (once per CTA) + rowq dots ----
    {
        const float4 wq1 = *(const float4*)(smf + 256 + lane * 4);
        const float4 wq2 = *(const float4*)(smf + 256 + 128 + lane * 4);
        #pragma unroll 4
        for (int i = 0; i < 16; i++) {
            int r = warp * 16 + i;
            float4 q1 = *(const float4*)(qryb + r * H_ + lane * 4);
            float4 q2 = *(const float4*)(qryb + r * H_ + 128 + lane * 4);
            uint32_t off = r * 128 + (((j >> 1) ^ (r & 7)) << 4) + (j & 1) * 8;
            *(uint2*)(smem + B1_OFF + s1 * 16384 + off) =
                make_uint2(pack2(q1.x, q1.y), pack2(q1.z, q1.w));
            *(uint2*)(smem + B1_OFF + (2 + s1) * 16384 + off) =
                make_uint2(pack2(q2.x, q2.y), pack2(q2.z, q2.w));
            float aq = q1.x * wq1.x + q1.y * wq1.y + q1.z * wq1.z + q1.w * wq1.w
                     + q2.x * wq2.x + q2.y * wq2.y + q2.z * wq2.z + q2.w * wq2.w;
            for (int o = 16; o; o >>= 1) aq += __shfl_xor_sync(~0u, aq, o);
            if (lane == 0) smf[SM_ROWQ / 4 + r] = aq;
        }
    }

    for (int cc = 0; cc < 2; cc++) {
        const int ct = chalf * 2 + cc;
        const float* ctxb = ctx + ((size_t)(b * C_) + ct * 64) * H_;
        const size_t obase = ((size_t)(b * C_) + ct * 64) * (4 * H_);

        // ---- A0: stage ctx*w_m fp16 (64 rows), rowc dots, out chunk0 = ctx ----
        #pragma unroll 4
        for (int i = 0; i < 8; i++) {
            int r = warp * 8 + i;
            float4 c1 = *(const float4*)(ctxb + r * H_ + lane * 4);
            float4 c2 = *(const float4*)(ctxb + r * H_ + 128 + lane * 4);
            uint32_t off = r * 128 + (((j >> 1) ^ (r & 7)) << 4) + (j & 1) * 8;
            *(uint2*)(smem + A_OFF + s1 * 8192 + off) =
                make_uint2(pack2(c1.x * wm1.x, c1.y * wm1.y), pack2(c1.z * wm1.z, c1.w * wm1.w));
            *(uint2*)(smem + A_OFF + (2 + s1) * 8192 + off) =
                make_uint2(pack2(c2.x * wm2.x, c2.y * wm2.y), pack2(c2.z * wm2.z, c2.w * wm2.w));
            // out chunk 0 = raw ctx (coalesced float4, from in-flight regs)
            *(float4*)(out + obase + (size_t)r * 1024 + lane * 4) = c1;
            *(float4*)(out + obase + (size_t)r * 1024 + 128 + lane * 4) = c2;
            float ac = c1.x * wc1.x + c1.y * wc1.y + c1.z * wc1.z + c1.w * wc1.w
                     + c2.x * wc2.x + c2.y * wc2.y + c2.z * wc2.z + c2.w * wc2.w;
            for (int o = 16; o; o >>= 1) ac += __shfl_xor_sync(~0u, ac, o);
            if (lane == 0) smf[SM_ROWC / 4 + r] = ac;
        }
        __syncthreads();

        // ---- GEMM1: sim = (ctx*w_m) @ qry^T ; M=64 N=128 K=256, barrier-free ----
        float acc1[2][4][4];
        #pragma unroll
        for (int mt = 0; mt < 2; mt++)
            #pragma unroll
            for (int jj = 0; jj < 4; jj++)
                #pragma unroll
                for (int e = 0; e < 4; e++) acc1[mt][jj][e] = 0.f;

        uint32_t rAb[2], xA[2], rBb[2], xB[2];
        #pragma unroll
        for (int mt = 0; mt < 2; mt++) {
            int row = mw * 32 + mt * 16 + gb * 8 + l7;
            rAb[mt] = row * 128; xA[mt] = row & 7;
        }
        #pragma unroll
        for (int p = 0; p < 2; p++) {
            int row = nw * 32 + p * 16 + gh * 8 + l7;
            rBb[p] = row * 128; xB[p] = row & 7;
        }

        #pragma unroll
        for (int kc = 0; kc < 4; kc++) {
            uint32_t Ab = sb + A_OFF + kc * 8192;
            uint32_t Bb = sb + B1_OFF + kc * 16384;
            #pragma unroll
            for (int ks = 0; ks < 4; ks++) {
                uint32_t a[2][4], bf[2][4];
                #pragma unroll
                for (int mt = 0; mt < 2; mt++) {
                    uint32_t u = 2 * ks + gh;
                    LDSM4(a[mt][0], a[mt][1], a[mt][2], a[mt][3], Ab + rAb[mt] + ((u ^ xA[mt]) << 4));
                }
                #pragma unroll
                for (int p = 0; p < 2; p++) {
                    uint32_t u = 2 * ks + gb;
                    LDSM4(bf[p][0], bf[p][1], bf[p][2], bf[p][3], Bb + rBb[p] + ((u ^ xB[p]) << 4));
                }
                #pragma unroll
                for (int mt = 0; mt < 2; mt++)
                    #pragma unroll
                    for (int p = 0; p < 2; p++) {
                        mma16(acc1[mt][2 * p],     a[mt][0], a[mt][1], a[mt][2], a[mt][3], bf[p][0], bf[p][1]);
                        mma16(acc1[mt][2 * p + 1], a[mt][0], a[mt][1], a[mt][2], a[mt][3], bf[p][2], bf[p][3]);
                    }
            }
        }

        // ---- softmax; alpha fp16 -> AL_OFF (overlays A) ----
        const float* rqv = smf + SM_ROWQ / 4;
        float vmax[4] = { -1e30f, -1e30f, -1e30f, -1e30f };
        #pragma unroll
        for (int mt = 0; mt < 2; mt++)
            #pragma unroll
            for (int jt = 0; jt < 4; jt++) {
                int c0 = nw * 32 + jt * 8 + 2 * (lane & 3);
                float r0 = rqv[c0], r1 = rqv[c0 + 1];
                vmax[2 * mt]     = fmaxf(vmax[2 * mt],     fmaxf(acc1[mt][jt][0] + r0, acc1[mt][jt][1] + r1));
                vmax[2 * mt + 1] = fmaxf(vmax[2 * mt + 1], fmaxf(acc1[mt][jt][2] + r0, acc1[mt][jt][3] + r1));
            }
        #pragma unroll
        for (int r = 0; r < 4; r++) {
            vmax[r] = fmaxf(vmax[r], __shfl_xor_sync(~0u, vmax[r], 1));
            vmax[r] = fmaxf(vmax[r], __shfl_xor_sync(~0u, vmax[r], 2));
        }
        if ((lane & 3) == 0)
            #pragma unroll
            for (int r = 0; r < 4; r++) {
                int row = mw * 32 + (r >> 1) * 16 + (r & 1) * 8 + (lane >> 2);
                smf[SM_SMAX / 4 + row * 4 + nw] = vmax[r];
            }
        __syncthreads();
        float rmax[4], rsum[4] = { 0.f, 0.f, 0.f, 0.f };
        #pragma unroll
        for (int r = 0; r < 4; r++) {
            int row = mw * 32 + (r >> 1) * 16 + (r & 1) * 8 + (lane >> 2);
            float m0 = fmaxf(smf[SM_SMAX / 4 + row * 4],     smf[SM_SMAX / 4 + row * 4 + 1]);
            float m1 = fmaxf(smf[SM_SMAX / 4 + row * 4 + 2], smf[SM_SMAX / 4 + row * 4 + 3]);
            rmax[r] = fmaxf(m0, m1);
        }
        #pragma unroll
        for (int mt = 0; mt < 2; mt++)
            #pragma unroll
            for (int jt = 0; jt < 4; jt++) {
                int c0 = nw * 32 + jt * 8 + 2 * (lane & 3);
                float r0 = rqv[c0], r1 = rqv[c0 + 1];
                float e0 = __expf(acc1[mt][jt][0] + r0 - rmax[2 * mt]);
                float e1 = __expf(acc1[mt][jt][1] + r1 - rmax[2 * mt]);
                float e2 = __expf(acc1[mt][jt][2] + r0 - rmax[2 * mt + 1]);
                float e3 = __expf(acc1[mt][jt][3] + r1 - rmax[2 * mt + 1]);
                rsum[2 * mt] += e0 + e1; rsum[2 * mt + 1] += e2 + e3;
                int rowA = mw * 32 + mt * 16 + (lane >> 2);
                int rowB = rowA + 8;
                int unit = nw * 4 + jt;
                *(uint32_t*)(smem + AL_OFF + rowA * 256 + ((unit ^ (rowA & 7)) << 4) + (lane & 3) * 4)
                    = pack2(e0, e1);
                *(uint32_t*)(smem + AL_OFF + rowB * 256 + ((unit ^ (rowB & 7)) << 4) + (lane & 3) * 4)
                    = pack2(e2, e3);
            }
        #pragma unroll
        for (int r = 0; r < 4; r++) {
            rsum[r] += __shfl_xor_sync(~0u, rsum[r], 1);
            rsum[r] += __shfl_xor_sync(~0u, rsum[r], 2);
        }
        if ((lane & 3) == 0)
            #pragma unroll
            for (int r = 0; r < 4; r++) {
                int row = mw * 32 + (r >> 1) * 16 + (r & 1) * 8 + (lane >> 2);
                smf[SM_SSUM / 4 + row * 4 + nw] = rsum[r];
            }
        __syncthreads();
        if (nw == 0 && (lane & 3) == 0) {
            float bias = smf[SM_BIAS / 4];
            #pragma unroll
            for (int r = 0; r < 4; r++) {
                int row = mw * 32 + (r >> 1) * 16 + (r & 1) * 8 + (lane >> 2);
                float tot = smf[SM_SSUM / 4 + row * 4]     + smf[SM_SSUM / 4 + row * 4 + 1]
                          + smf[SM_SSUM / 4 + row * 4 + 2] + smf[SM_SSUM / 4 + row * 4 + 3];
                smf[SM_SINV / 4 + row] = 1.0f / tot;
                g_m[b * C_ + ct * 64 + row] = rmax[r] + smf[SM_ROWC / 4 + row] + bias;
            }
        }
        __syncthreads();

        // ---- GEMM2: D = E @ qry ; M=64, warp n-tile 64 (slot nw), K=128 ----
        float iv[4];
        #pragma unroll
        for (int r = 0; r < 4; r++) {
            int row = mw * 32 + (r >> 1) * 16 + (r & 1) * 8 + (lane >> 2);
            iv[r] = smf[SM_SINV / 4 + row];
        }
        uint32_t rA2b[2], xA2[2];
        #pragma unroll
        for (int mt = 0; mt < 2; mt++) {
            int row = mw * 32 + mt * 16 + gb * 8 + l7;
            rA2b[mt] = row * 256; xA2[mt] = row & 7;
        }
        const uint32_t Bs = sb + B1_OFF + nw * 16384;
        const int qbase = gb * 8 + l7;

        float acc2[8][2][4];
        #pragma unroll
        for (int jj = 0; jj < 8; jj++)
            #pragma unroll
            for (int mt = 0; mt < 2; mt++)
                #pragma unroll
                for (int e = 0; e < 4; e++) acc2[jj][mt][e] = 0.f;

        #pragma unroll
        for (int s = 0; s < 8; s++) {
            uint32_t a[2][4];
            #pragma unroll
            for (int mt = 0; mt < 2; mt++) {
                uint32_t u = 2 * s + gh;
                LDSM4(a[mt][0], a[mt][1], a[mt][2], a[mt][3],
                      sb + AL_OFF + rA2b[mt] + ((u ^ xA2[mt]) << 4));
            }
            uint32_t bt[4][4];
            uint32_t qrow = (uint32_t)(s * 16 + qbase);
            #pragma unroll
            for (int t = 0; t < 4; t++) {
                uint32_t u = 2 * t + gh;
                LDSM4T(bt[t][0], bt[t][1], bt[t][2], bt[t][3],
                       Bs + qrow * 128 + ((u ^ (uint32_t)l7) << 4));
            }
            #pragma unroll
            for (int mt = 0; mt < 2; mt++)
                #pragma unroll
                for (int t = 0; t < 4; t++) {
                    mma16(acc2[2 * t][mt],     a[mt][0], a[mt][1], a[mt][2], a[mt][3], bt[t][0], bt[t][1]);
                    mma16(acc2[2 * t + 1][mt], a[mt][0], a[mt][1], a[mt][2], a[mt][3], bt[t][2], bt[t][3]);
                }
        }

        // ---- epilogue: out1 = a, out2 = ctx*a ----
        #pragma unroll
        for (int mt = 0; mt < 2; mt++)
            #pragma unroll
            for (int h = 0; h < 2; h++) {
                int row = mw * 32 + mt * 16 + h * 8 + (lane >> 2);
                float ivr = iv[mt * 2 + h];
                #pragma unroll
                for (int jj = 0; jj < 8; jj++) {
                    int col = nw * 64 + jj * 8 + 2 * (lane & 3);
                    float2 c = *(const float2*)(ctxb + row * 256 + col);
                    float a0 = acc2[jj][mt][2 * h] * ivr;
                    float a1 = acc2[jj][mt][2 * h + 1] * ivr;
                    float* o = out + obase + (size_t)row * 1024 + col;
                    *(float2*)(o + 256) = make_float2(a0, a1);
                    *(float2*)(o + 512) = make_float2(c.x * a0, c.y * a1);
                }
            }
        __syncthreads();   // protect A region restage next iteration
    }
}

// ============================ K2 ============================
__global__ __launch_bounds__(256, 1)
void k2_beta(const float* __restrict__ ctx)
{
    __shared__ float smm[1024];
    __shared__ float se[128];
    __shared__ float red[8];
    const int tid = threadIdx.x, lane = tid & 31, warp = tid >> 5;
    const int b = blockIdx.x >> 3, ch = blockIdx.x & 7;

    float lm = -1e30f;
    for (int i = tid; i < 1024; i += 256) {
        float v = g_m[b * 1024 + i];
        smm[i] = v; lm = fmaxf(lm, v);
    }
    for (int o = 16; o; o >>= 1) lm = fmaxf(lm, __shfl_xor_sync(~0u, lm, o));
    if (lane == 0) red[warp] = lm;
    __syncthreads();
    float M = red[0];
    #pragma unroll
    for (int i = 1; i < 8; i++) M = fmaxf(M, red[i]);
    __syncthreads();
    if (tid < 128) se[tid] = __expf(smm[ch * 128 + tid] - M);
    __syncthreads();
    if (tid < 128) {
        float v = se[tid];
        for (int o = 16; o; o >>= 1) v += __shfl_xor_sync(~0u, v, o);
        if (lane == 0) red[warp] = v;
    }
    __syncthreads();
    if (tid == 0) g_zpart[blockIdx.x] = red[0] + red[1] + red[2] + red[3];

    const float* cb = ctx + ((size_t)b * 1024 + ch * 128) * 256;
    float acc = 0.f;
    #pragma unroll 16
    for (int c = 0; c < 128; c++) acc += se[c] * cb[(size_t)c * 256 + tid];
    g_bpart[(size_t)blockIdx.x * 256 + tid] = acc;
}

// ============================ K3 ============================
__global__ __launch_bounds__(256, 1)
void k3_cb(const float* __restrict__ ctx, float* __restrict__ out)
{
    __shared__ float bv[256];
    const int tid = threadIdx.x;
    const int b = blockIdx.x >> 3, ch = blockIdx.x & 7;
    float z = 0.f, a = 0.f;
    #pragma unroll
    for (int p = 0; p < 8; p++) {
        z += g_zpart[b * 8 + p];
        a += g_bpart[(size_t)(b * 8 + p) * 256 + tid];
    }
    bv[tid] = a / z;
    __syncthreads();
    const float* cb = ctx + ((size_t)b * 1024 + ch * 128) * 256;
    float* ob = out + ((size_t)(b * 1024) + ch * 128) * 1024 + 768;
    #pragma unroll 4
    for (int i = 0; i < 32; i++) {
        int f = i * 256 + tid;
        int row = f >> 6, c4 = (f & 63) * 4;
        float4 cv = *(const float4*)(cb + row * 256 + c4);
        float4 bb = *(const float4*)(bv + c4);
        float4 r = { cv.x * bb.x, cv.y * bb.y, cv.z * bb.z, cv.w * bb.w };
        *(float4*)(ob + (size_t)row * 1024 + c4) = r;
    }
}

extern "C" void kernel_launch(void* const* d_in, const int* in_sizes, int n_in,
                              void* d_out, int out_size)
{
    const float* ctx  = (const float*)d_in[0];
    const float* qry  = (const float*)d_in[2];
    const float* attw = (const float*)d_in[4];
    const float* attb = (const float*)d_in[5];
    float* out = (float*)d_out;

    cudaFuncSetAttribute(k1_main, cudaFuncAttributeMaxDynamicSharedMemorySize, SMEM_TOTAL);
    k1_main<<<512, 256, SMEM_TOTAL>>>(ctx, qry, attw, attb, out);
    k2_beta<<<512, 256>>>(ctx);
    k3_cb<<<512, 256>>>(ctx, out);
}

// round 11
// speedup vs baseline: 1.8706x; 1.0351x over previous
#include <cuda_runtime.h>
#include <cstdint>

#define B_ 64
#define C_ 1024
#define Q_ 128
#define H_ 256

// ---- scratch ----
__device__ float g_m[B_ * C_];
__device__ float g_bpart[B_ * 8 * H_];
__device__ float g_zpart[B_ * 8];

// ---- smem byte offsets (per-CTA, 64-row m-tile) ----
#define SM_W     0        // 768 f32
#define SM_ROWC  3072     // 64 f32
#define SM_ROWQ  3328     // 128 f32
#define SM_SMAX  3840     // 64x4 f32
#define SM_SSUM  4864     // 64x4 f32
#define SM_SINV  5888     // 64 f32
#define SM_BIAS  6144
#define A_OFF    8192     // 4 x 8KB resident fp16 (ctx*w_m) h-chunks (64 rows)
#define AL_OFF   8192     // alpha fp16 [64][128] 16KB, overlays A after GEMM1
#define EPI_OFF  8192     // fp32 a-tile stage [32][260] (33280B), overlays A+alpha
#define EPI_STR  1040     // 260 floats: conflict-free row stride
#define B1_OFF   43008    // 4 x 16KB resident fp16 qry h-chunks ([128 q][64h])
#define SMEM_TOTAL 108544

__device__ __forceinline__ uint32_t smem_u32(const void* p) {
    uint32_t a; asm("{ .reg .u64 t; cvta.to.shared.u64 t, %1; cvt.u32.u64 %0, t; }" : "=r"(a) : "l"(p));
    return a;
}
__device__ __forceinline__ uint32_t pack2(float lo, float hi) {
    uint32_t r; asm("cvt.rn.f16x2.f32 %0, %1, %2;" : "=r"(r) : "f"(hi), "f"(lo)); return r;
}
__device__ __forceinline__ void mma16(float d[4], uint32_t a0, uint32_t a1, uint32_t a2, uint32_t a3,
                                      uint32_t b0, uint32_t b1) {
    asm volatile(
        "mma.sync.aligned.m16n8k16.row.col.f32.f16.f16.f32 "
        "{%0,%1,%2,%3}, {%4,%5,%6,%7}, {%8,%9}, {%0,%1,%2,%3};"
        : "+f"(d[0]), "+f"(d[1]), "+f"(d[2]), "+f"(d[3])
        : "r"(a0), "r"(a1), "r"(a2), "r"(a3), "r"(b0), "r"(b1));
}
#define LDSM4(r0, r1, r2, r3, addr) \
    asm volatile("ldmatrix.sync.aligned.m8n8.x4.shared.b16 {%0,%1,%2,%3}, [%4];" \
        : "=r"(r0), "=r"(r1), "=r"(r2), "=r"(r3) : "r"(addr))
#define LDSM4T(r0, r1, r2, r3, addr) \
    asm volatile("ldmatrix.sync.aligned.m8n8.x4.trans.shared.b16 {%0,%1,%2,%3}, [%4];" \
        : "=r"(r0), "=r"(r1), "=r"(r2), "=r"(r3) : "r"(addr))

// ============================ K1 ============================
__global__ __launch_bounds__(256, 2)
void k1_main(const float* __restrict__ ctx, const float* __restrict__ qry,
             const float* __restrict__ attw, const float* __restrict__ attb,
             float* __restrict__ out)
{
    extern __shared__ __align__(1024) char smem[];
    float* smf = (float*)smem;
    const uint32_t sb = smem_u32(smem);
    const int tid = threadIdx.x, warp = tid >> 5, lane = tid & 31;
    const int mw = warp >> 2, nw = warp & 3;
    const int g = lane >> 3, l7 = lane & 7, gb = g & 1, gh = g >> 1;
    const int b = blockIdx.x >> 3, chalf = blockIdx.x & 7;
    const float* qryb = qry + (size_t)b * Q_ * H_;

    for (int i = tid; i < 768; i += 256) smf[i] = attw[i];
    if (tid == 0) smf[SM_BIAS / 4] = attb[0];
    __syncthreads();

    const float4 wc1 = *(const float4*)(smf + lane * 4);
    const float4 wc2 = *(const float4*)(smf + 128 + lane * 4);
    const float4 wm1 = *(const float4*)(smf + 512 + lane * 4);
    const float4 wm2 = *(const float4*)(smf + 512 + 128 + lane * 4);
    const int j = lane & 15, s1 = lane >> 4;

    // ---- stage qry fp16 (once per CTA) + rowq dots ----
    {
        const float4 wq1 = *(const float4*)(smf + 256 + lane * 4);
        const float4 wq2 = *(const float4*)(smf + 256 + 128 + lane * 4);
        #pragma unroll 4
        for (int i = 0; i < 16; i++) {
            int r = warp * 16 + i;
            float4 q1 = *(const float4*)(qryb + r * H_ + lane * 4);
            float4 q2 = *(const float4*)(qryb + r * H_ + 128 + lane * 4);
            uint32_t off = r * 128 + (((j >> 1) ^ (r & 7)) << 4) + (j & 1) * 8;
            *(uint2*)(smem + B1_OFF + s1 * 16384 + off) =
                make_uint2(pack2(q1.x, q1.y), pack2(q1.z, q1.w));
            *(uint2*)(smem + B1_OFF + (2 + s1) * 16384 + off) =
                make_uint2(pack2(q2.x, q2.y), pack2(q2.z, q2.w));
            float aq = q1.x * wq1.x + q1.y * wq1.y + q1.z * wq1.z + q1.w * wq1.w
                     + q2.x * wq2.x + q2.y * wq2.y + q2.z * wq2.z + q2.w * wq2.w;
            for (int o = 16; o; o >>= 1) aq += __shfl_xor_sync(~0u, aq, o);
            if (lane == 0) smf[SM_ROWQ / 4 + r] = aq;
        }
    }

    for (int cc = 0; cc < 2; cc++) {
        const int ct = chalf * 2 + cc;
        const float* ctxb = ctx + ((size_t)(b * C_) + ct * 64) * H_;
        const size_t obase = ((size_t)(b * C_) + ct * 64) * (4 * H_);

        // ---- A0: stage ctx*w_m fp16 (64 rows), rowc dots, out chunk0 = ctx ----
        #pragma unroll 4
        for (int i = 0; i < 8; i++) {
            int r = warp * 8 + i;
            float4 c1 = *(const float4*)(ctxb + r * H_ + lane * 4);
            float4 c2 = *(const float4*)(ctxb + r * H_ + 128 + lane * 4);
            uint32_t off = r * 128 + (((j >> 1) ^ (r & 7)) << 4) + (j & 1) * 8;
            *(uint2*)(smem + A_OFF + s1 * 8192 + off) =
                make_uint2(pack2(c1.x * wm1.x, c1.y * wm1.y), pack2(c1.z * wm1.z, c1.w * wm1.w));
            *(uint2*)(smem + A_OFF + (2 + s1) * 8192 + off) =
                make_uint2(pack2(c2.x * wm2.x, c2.y * wm2.y), pack2(c2.z * wm2.z, c2.w * wm2.w));
            *(float4*)(out + obase + (size_t)r * 1024 + lane * 4) = c1;
            *(float4*)(out + obase + (size_t)r * 1024 + 128 + lane * 4) = c2;
            float ac = c1.x * wc1.x + c1.y * wc1.y + c1.z * wc1.z + c1.w * wc1.w
                     + c2.x * wc2.x + c2.y * wc2.y + c2.z * wc2.z + c2.w * wc2.w;
            for (int o = 16; o; o >>= 1) ac += __shfl_xor_sync(~0u, ac, o);
            if (lane == 0) smf[SM_ROWC / 4 + r] = ac;
        }
        __syncthreads();

        // ---- GEMM1: sim = (ctx*w_m) @ qry^T ; M=64 N=128 K=256, barrier-free ----
        float acc1[2][4][4];
        #pragma unroll
        for (int mt = 0; mt < 2; mt++)
            #pragma unroll
            for (int jj = 0; jj < 4; jj++)
                #pragma unroll
                for (int e = 0; e < 4; e++) acc1[mt][jj][e] = 0.f;

        uint32_t rAb[2], xA[2], rBb[2], xB[2];
        #pragma unroll
        for (int mt = 0; mt < 2; mt++) {
            int row = mw * 32 + mt * 16 + gb * 8 + l7;
            rAb[mt] = row * 128; xA[mt] = row & 7;
        }
        #pragma unroll
        for (int p = 0; p < 2; p++) {
            int row = nw * 32 + p * 16 + gh * 8 + l7;
            rBb[p] = row * 128; xB[p] = row & 7;
        }

        #pragma unroll
        for (int kc = 0; kc < 4; kc++) {
            uint32_t Ab = sb + A_OFF + kc * 8192;
            uint32_t Bb = sb + B1_OFF + kc * 16384;
            #pragma unroll
            for (int ks = 0; ks < 4; ks++) {
                uint32_t a[2][4], bf[2][4];
                #pragma unroll
                for (int mt = 0; mt < 2; mt++) {
                    uint32_t u = 2 * ks + gh;
                    LDSM4(a[mt][0], a[mt][1], a[mt][2], a[mt][3], Ab + rAb[mt] + ((u ^ xA[mt]) << 4));
                }
                #pragma unroll
                for (int p = 0; p < 2; p++) {
                    uint32_t u = 2 * ks + gb;
                    LDSM4(bf[p][0], bf[p][1], bf[p][2], bf[p][3], Bb + rBb[p] + ((u ^ xB[p]) << 4));
                }
                #pragma unroll
                for (int mt = 0; mt < 2; mt++)
                    #pragma unroll
                    for (int p = 0; p < 2; p++) {
                        mma16(acc1[mt][2 * p],     a[mt][0], a[mt][1], a[mt][2], a[mt][3], bf[p][0], bf[p][1]);
                        mma16(acc1[mt][2 * p + 1], a[mt][0], a[mt][1], a[mt][2], a[mt][3], bf[p][2], bf[p][3]);
                    }
            }
        }

        // ---- softmax; alpha fp16 -> AL_OFF (overlays A) ----
        const float* rqv = smf + SM_ROWQ / 4;
        float vmax[4] = { -1e30f, -1e30f, -1e30f, -1e30f };
        #pragma unroll
        for (int mt = 0; mt < 2; mt++)
            #pragma unroll
            for (int jt = 0; jt < 4; jt++) {
                int c0 = nw * 32 + jt * 8 + 2 * (lane & 3);
                float r0 = rqv[c0], r1 = rqv[c0 + 1];
                vmax[2 * mt]     = fmaxf(vmax[2 * mt],     fmaxf(acc1[mt][jt][0] + r0, acc1[mt][jt][1] + r1));
                vmax[2 * mt + 1] = fmaxf(vmax[2 * mt + 1], fmaxf(acc1[mt][jt][2] + r0, acc1[mt][jt][3] + r1));
            }
        #pragma unroll
        for (int r = 0; r < 4; r++) {
            vmax[r] = fmaxf(vmax[r], __shfl_xor_sync(~0u, vmax[r], 1));
            vmax[r] = fmaxf(vmax[r], __shfl_xor_sync(~0u, vmax[r], 2));
        }
        if ((lane & 3) == 0)
            #pragma unroll
            for (int r = 0; r < 4; r++) {
                int row = mw * 32 + (r >> 1) * 16 + (r & 1) * 8 + (lane >> 2);
                smf[SM_SMAX / 4 + row * 4 + nw] = vmax[r];
            }
        __syncthreads();
        float rmax[4], rsum[4] = { 0.f, 0.f, 0.f, 0.f };
        #pragma unroll
        for (int r = 0; r < 4; r++) {
            int row = mw * 32 + (r >> 1) * 16 + (r & 1) * 8 + (lane >> 2);
            float m0 = fmaxf(smf[SM_SMAX / 4 + row * 4],     smf[SM_SMAX / 4 + row * 4 + 1]);
            float m1 = fmaxf(smf[SM_SMAX / 4 + row * 4 + 2], smf[SM_SMAX / 4 + row * 4 + 3]);
            rmax[r] = fmaxf(m0, m1);
        }
        #pragma unroll
        for (int mt = 0; mt < 2; mt++)
            #pragma unroll
            for (int jt = 0; jt < 4; jt++) {
                int c0 = nw * 32 + jt * 8 + 2 * (lane & 3);
                float r0 = rqv[c0], r1 = rqv[c0 + 1];
                float e0 = __expf(acc1[mt][jt][0] + r0 - rmax[2 * mt]);
                float e1 = __expf(acc1[mt][jt][1] + r1 - rmax[2 * mt]);
                float e2 = __expf(acc1[mt][jt][2] + r0 - rmax[2 * mt + 1]);
                float e3 = __expf(acc1[mt][jt][3] + r1 - rmax[2 * mt + 1]);
                rsum[2 * mt] += e0 + e1; rsum[2 * mt + 1] += e2 + e3;
                int rowA = mw * 32 + mt * 16 + (lane >> 2);
                int rowB = rowA + 8;
                int unit = nw * 4 + jt;
                *(uint32_t*)(smem + AL_OFF + rowA * 256 + ((unit ^ (rowA & 7)) << 4) + (lane & 3) * 4)
                    = pack2(e0, e1);
                *(uint32_t*)(smem + AL_OFF + rowB * 256 + ((unit ^ (rowB & 7)) << 4) + (lane & 3) * 4)
                    = pack2(e2, e3);
            }
        #pragma unroll
        for (int r = 0; r < 4; r++) {
            rsum[r] += __shfl_xor_sync(~0u, rsum[r], 1);
            rsum[r] += __shfl_xor_sync(~0u, rsum[r], 2);
        }
        if ((lane & 3) == 0)
            #pragma unroll
            for (int r = 0; r < 4; r++) {
                int row = mw * 32 + (r >> 1) * 16 + (r & 1) * 8 + (lane >> 2);
                smf[SM_SSUM / 4 + row * 4 + nw] = rsum[r];
            }
        __syncthreads();
        if (nw == 0 && (lane & 3) == 0) {
            float bias = smf[SM_BIAS / 4];
            #pragma unroll
            for (int r = 0; r < 4; r++) {
                int row = mw * 32 + (r >> 1) * 16 + (r & 1) * 8 + (lane >> 2);
                float tot = smf[SM_SSUM / 4 + row * 4]     + smf[SM_SSUM / 4 + row * 4 + 1]
                          + smf[SM_SSUM / 4 + row * 4 + 2] + smf[SM_SSUM / 4 + row * 4 + 3];
                smf[SM_SINV / 4 + row] = 1.0f / tot;
                g_m[b * C_ + ct * 64 + row] = rmax[r] + smf[SM_ROWC / 4 + row] + bias;
            }
        }
        __syncthreads();

        // ---- GEMM2: D = E @ qry ; M=64, warp n-tile 64 (slot nw), K=128 ----
        float iv[4];
        #pragma unroll
        for (int r = 0; r < 4; r++) {
            int row = mw * 32 + (r >> 1) * 16 + (r & 1) * 8 + (lane >> 2);
            iv[r] = smf[SM_SINV / 4 + row];
        }
        uint32_t rA2b[2], xA2[2];
        #pragma unroll
        for (int mt = 0; mt < 2; mt++) {
            int row = mw * 32 + mt * 16 + gb * 8 + l7;
            rA2b[mt] = row * 256; xA2[mt] = row & 7;
        }
        const uint32_t Bs = sb + B1_OFF + nw * 16384;
        const int qbase = gb * 8 + l7;

        float acc2[8][2][4];
        #pragma unroll
        for (int jj = 0; jj < 8; jj++)
            #pragma unroll
            for (int mt = 0; mt < 2; mt++)
                #pragma unroll
                for (int e = 0; e < 4; e++) acc2[jj][mt][e] = 0.f;

        #pragma unroll
        for (int s = 0; s < 8; s++) {
            uint32_t a[2][4];
            #pragma unroll
            for (int mt = 0; mt < 2; mt++) {
                uint32_t u = 2 * s + gh;
                LDSM4(a[mt][0], a[mt][1], a[mt][2], a[mt][3],
                      sb + AL_OFF + rA2b[mt] + ((u ^ xA2[mt]) << 4));
            }
            uint32_t bt[4][4];
            uint32_t qrow = (uint32_t)(s * 16 + qbase);
            #pragma unroll
            for (int t = 0; t < 4; t++) {
                uint32_t u = 2 * t + gh;
                LDSM4T(bt[t][0], bt[t][1], bt[t][2], bt[t][3],
                       Bs + qrow * 128 + ((u ^ (uint32_t)l7) << 4));
            }
            #pragma unroll
            for (int mt = 0; mt < 2; mt++)
                #pragma unroll
                for (int t = 0; t < 4; t++) {
                    mma16(acc2[2 * t][mt],     a[mt][0], a[mt][1], a[mt][2], a[mt][3], bt[t][0], bt[t][1]);
                    mma16(acc2[2 * t + 1][mt], a[mt][0], a[mt][1], a[mt][2], a[mt][3], bt[t][2], bt[t][3]);
                }
        }
        __syncthreads();   // all GEMM2 alpha reads done before EPI overwrite

        // ---- epilogue: stage a-tile (fp32) per 32-row half, drain coalesced ----
        #pragma unroll
        for (int p = 0; p < 2; p++) {
            if (mw == p) {
                #pragma unroll
                for (int mt = 0; mt < 2; mt++)
                    #pragma unroll
                    for (int h = 0; h < 2; h++) {
                        int rl = mt * 16 + h * 8 + (lane >> 2);
                        float ivr = iv[mt * 2 + h];
                        #pragma unroll
                        for (int jj = 0; jj < 8; jj++) {
                            int col = nw * 64 + jj * 8 + 2 * (lane & 3);
                            *(float2*)(smem + EPI_OFF + rl * EPI_STR + col * 4) =
                                make_float2(acc2[jj][mt][2 * h] * ivr,
                                            acc2[jj][mt][2 * h + 1] * ivr);
                        }
                    }
            }
            __syncthreads();
            #pragma unroll
            for (int i = 0; i < 8; i++) {
                int idx = i * 256 + tid;
                int rl = idx >> 6, c4 = (idx & 63) * 4;
                float4 av = *(const float4*)(smem + EPI_OFF + rl * EPI_STR + c4 * 4);
                int row = p * 32 + rl;
                float4 cv = *(const float4*)(ctxb + row * 256 + c4);
                float* o = out + obase + (size_t)row * 1024 + c4;
                *(float4*)(o + 256) = av;
                *(float4*)(o + 512) = make_float4(cv.x * av.x, cv.y * av.y,
                                                  cv.z * av.z, cv.w * av.w);
            }
            __syncthreads();
        }
    }
}

// ============================ K2 ============================
__global__ __launch_bounds__(256, 1)
void k2_beta(const float* __restrict__ ctx)
{
    __shared__ float smm[1024];
    __shared__ float se[128];
    __shared__ float red[8];
    const int tid = threadIdx.x, lane = tid & 31, warp = tid >> 5;
    const int b = blockIdx.x >> 3, ch = blockIdx.x & 7;

    float lm = -1e30f;
    for (int i = tid; i < 1024; i += 256) {
        float v = g_m[b * 1024 + i];
        smm[i] = v; lm = fmaxf(lm, v);
    }
    for (int o = 16; o; o >>= 1) lm = fmaxf(lm, __shfl_xor_sync(~0u, lm, o));
    if (lane == 0) red[warp] = lm;
    __syncthreads();
    float M = red[0];
    #pragma unroll
    for (int i = 1; i < 8; i++) M = fmaxf(M, red[i]);
    __syncthreads();
    if (tid < 128) se[tid] = __expf(smm[ch * 128 + tid] - M);
    __syncthreads();
    if (tid < 128) {
        float v = se[tid];
        for (int o = 16; o; o >>= 1) v += __shfl_xor_sync(~0u, v, o);
        if (lane == 0) red[warp] = v;
    }
    __syncthreads();
    if (tid == 0) g_zpart[blockIdx.x] = red[0] + red[1] + red[2] + red[3];

    const float* cb = ctx + ((size_t)b * 1024 + ch * 128) * 256;
    float acc = 0.f;
    #pragma unroll 16
    for (int c = 0; c < 128; c++) acc += se[c] * cb[(size_t)c * 256 + tid];
    g_bpart[(size_t)blockIdx.x * 256 + tid] = acc;
}

// ============================ K3 ============================
__global__ __launch_bounds__(256, 1)
void k3_cb(const float* __restrict__ ctx, float* __restrict__ out)
{
    __shared__ float bv[256];
    const int tid = threadIdx.x;
    const int b = blockIdx.x >> 3, ch = blockIdx.x & 7;
    float z = 0.f, a = 0.f;
    #pragma unroll
    for (int p = 0; p < 8; p++) {
        z += g_zpart[b * 8 + p];
        a += g_bpart[(size_t)(b * 8 + p) * 256 + tid];
    }
    bv[tid] = a / z;
    __syncthreads();
    const float* cb = ctx + ((size_t)b * 1024 + ch * 128) * 256;
    float* ob = out + ((size_t)(b * 1024) + ch * 128) * 1024 + 768;
    #pragma unroll 4
    for (int i = 0; i < 32; i++) {
        int f = i * 256 + tid;
        int row = f >> 6, c4 = (f & 63) * 4;
        float4 cv = *(const float4*)(cb + row * 256 + c4);
        float4 bb = *(const float4*)(bv + c4);
        float4 r = { cv.x * bb.x, cv.y * bb.y, cv.z * bb.z, cv.w * bb.w };
        *(float4*)(ob + (size_t)row * 1024 + c4) = r;
    }
}

extern "C" void kernel_launch(void* const* d_in, const int* in_sizes, int n_in,
                              void* d_out, int out_size)
{
    const float* ctx  = (const float*)d_in[0];
    const float* qry  = (const float*)d_in[2];
    const float* attw = (const float*)d_in[4];
    const float* attb = (const float*)d_in[5];
    float* out = (float*)d_out;

    cudaFuncSetAttribute(k1_main, cudaFuncAttributeMaxDynamicSharedMemorySize, SMEM_TOTAL);
    k1_main<<<512, 256, SMEM_TOTAL>>>(ctx, qry, attw, attb, out);
    k2_beta<<<512, 256>>>(ctx);
    k3_cb<<<512, 256>>>(ctx, out);
}

// round 12
// speedup vs baseline: 1.8996x; 1.0155x over previous
#include <cuda_runtime.h>
#include <cstdint>

#define B_ 64
#define C_ 1024
#define Q_ 128
#define H_ 256

// ---- scratch ----
__device__ float g_spart[B_ * 16 * H_];   // per-chunk beta-weighted ctx partial sums
__device__ float g_Ml[B_ * 16];           // per-chunk local max of m
__device__ float g_zl[B_ * 16];           // per-chunk local denominator

// ---- smem byte offsets (per-CTA, 64-row m-tile) ----
#define SM_W     0        // 768 f32
#define SM_ROWC  3072     // 64 f32
#define SM_ROWQ  3328     // 128 f32
#define SM_SMAX  3840     // 64x4 f32
#define SM_SSUM  4864     // 64x4 f32
#define SM_SINV  5888     // 64 f32
#define SM_BIAS  6144
#define SM_M     6400     // 64 f32: m values (rmax+rowc+bias)
#define SM_WB    6656     // 64 f32: w = exp(m - Ml)
#define SM_ZML   6912     // 4 f32: {max0, max1, zsum0, zsum1}
#define A_OFF    8192     // 4 x 8KB resident fp16 (ctx*w_m) h-chunks (64 rows)
#define AL_OFF   8192     // alpha fp16 [64][128] 16KB, overlays A after GEMM1
#define EPI_OFF  8192     // fp32 a-tile stage [32][260] (33280B), overlays A+alpha
#define EPI_STR  1040
#define B1_OFF   43008    // 4 x 16KB resident fp16 qry h-chunks
#define SP_OFF   108544   // 4 x 256 f32 s-partial reduction (4KB)
#define SMEM_TOTAL 112640

__device__ __forceinline__ uint32_t smem_u32(const void* p) {
    uint32_t a; asm("{ .reg .u64 t; cvta.to.shared.u64 t, %1; cvt.u32.u64 %0, t; }" : "=r"(a) : "l"(p));
    return a;
}
__device__ __forceinline__ uint32_t pack2(float lo, float hi) {
    uint32_t r; asm("cvt.rn.f16x2.f32 %0, %1, %2;" : "=r"(r) : "f"(hi), "f"(lo)); return r;
}
__device__ __forceinline__ void mma16(float d[4], uint32_t a0, uint32_t a1, uint32_t a2, uint32_t a3,
                                      uint32_t b0, uint32_t b1) {
    asm volatile(
        "mma.sync.aligned.m16n8k16.row.col.f32.f16.f16.f32 "
        "{%0,%1,%2,%3}, {%4,%5,%6,%7}, {%8,%9}, {%0,%1,%2,%3};"
        : "+f"(d[0]), "+f"(d[1]), "+f"(d[2]), "+f"(d[3])
        : "r"(a0), "r"(a1), "r"(a2), "r"(a3), "r"(b0), "r"(b1));
}
#define LDSM4(r0, r1, r2, r3, addr) \
    asm volatile("ldmatrix.sync.aligned.m8n8.x4.shared.b16 {%0,%1,%2,%3}, [%4];" \
        : "=r"(r0), "=r"(r1), "=r"(r2), "=r"(r3) : "r"(addr))
#define LDSM4T(r0, r1, r2, r3, addr) \
    asm volatile("ldmatrix.sync.aligned.m8n8.x4.trans.shared.b16 {%0,%1,%2,%3}, [%4];" \
        : "=r"(r0), "=r"(r1), "=r"(r2), "=r"(r3) : "r"(addr))

// ============================ K1 ============================
__global__ __launch_bounds__(256, 2)
void k1_main(const float* __restrict__ ctx, const float* __restrict__ qry,
             const float* __restrict__ attw, const float* __restrict__ attb,
             float* __restrict__ out)
{
    extern __shared__ __align__(1024) char smem[];
    float* smf = (float*)smem;
    const uint32_t sb = smem_u32(smem);
    const int tid = threadIdx.x, warp = tid >> 5, lane = tid & 31;
    const int mw = warp >> 2, nw = warp & 3;
    const int g = lane >> 3, l7 = lane & 7, gb = g & 1, gh = g >> 1;
    const int b = blockIdx.x >> 3, chalf = blockIdx.x & 7;
    const float* qryb = qry + (size_t)b * Q_ * H_;

    for (int i = tid; i < 768; i += 256) smf[i] = attw[i];
    if (tid == 0) smf[SM_BIAS / 4] = attb[0];
    __syncthreads();

    const float4 wc1 = *(const float4*)(smf + lane * 4);
    const float4 wc2 = *(const float4*)(smf + 128 + lane * 4);
    const float4 wm1 = *(const float4*)(smf + 512 + lane * 4);
    const float4 wm2 = *(const float4*)(smf + 512 + 128 + lane * 4);
    const int j = lane & 15, s1 = lane >> 4;

    // ---- stage qry fp16 (once per CTA) + rowq dots ----
    {
        const float4 wq1 = *(const float4*)(smf + 256 + lane * 4);
        const float4 wq2 = *(const float4*)(smf + 256 + 128 + lane * 4);
        #pragma unroll 4
        for (int i = 0; i < 16; i++) {
            int r = warp * 16 + i;
            float4 q1 = *(const float4*)(qryb + r * H_ + lane * 4);
            float4 q2 = *(const float4*)(qryb + r * H_ + 128 + lane * 4);
            uint32_t off = r * 128 + (((j >> 1) ^ (r & 7)) << 4) + (j & 1) * 8;
            *(uint2*)(smem + B1_OFF + s1 * 16384 + off) =
                make_uint2(pack2(q1.x, q1.y), pack2(q1.z, q1.w));
            *(uint2*)(smem + B1_OFF + (2 + s1) * 16384 + off) =
                make_uint2(pack2(q2.x, q2.y), pack2(q2.z, q2.w));
            float aq = q1.x * wq1.x + q1.y * wq1.y + q1.z * wq1.z + q1.w * wq1.w
                     + q2.x * wq2.x + q2.y * wq2.y + q2.z * wq2.z + q2.w * wq2.w;
            for (int o = 16; o; o >>= 1) aq += __shfl_xor_sync(~0u, aq, o);
            if (lane == 0) smf[SM_ROWQ / 4 + r] = aq;
        }
    }

    for (int cc = 0; cc < 2; cc++) {
        const int ct = chalf * 2 + cc;
        const int chunk_idx = b * 16 + ct;
        const float* ctxb = ctx + ((size_t)(b * C_) + ct * 64) * H_;
        const size_t obase = ((size_t)(b * C_) + ct * 64) * (4 * H_);

        // ---- A0: stage ctx*w_m fp16 (64 rows), rowc dots, out chunk0 = ctx ----
        #pragma unroll 4
        for (int i = 0; i < 8; i++) {
            int r = warp * 8 + i;
            float4 c1 = *(const float4*)(ctxb + r * H_ + lane * 4);
            float4 c2 = *(const float4*)(ctxb + r * H_ + 128 + lane * 4);
            uint32_t off = r * 128 + (((j >> 1) ^ (r & 7)) << 4) + (j & 1) * 8;
            *(uint2*)(smem + A_OFF + s1 * 8192 + off) =
                make_uint2(pack2(c1.x * wm1.x, c1.y * wm1.y), pack2(c1.z * wm1.z, c1.w * wm1.w));
            *(uint2*)(smem + A_OFF + (2 + s1) * 8192 + off) =
                make_uint2(pack2(c2.x * wm2.x, c2.y * wm2.y), pack2(c2.z * wm2.z, c2.w * wm2.w));
            *(float4*)(out + obase + (size_t)r * 1024 + lane * 4) = c1;
            *(float4*)(out + obase + (size_t)r * 1024 + 128 + lane * 4) = c2;
            float ac = c1.x * wc1.x + c1.y * wc1.y + c1.z * wc1.z + c1.w * wc1.w
                     + c2.x * wc2.x + c2.y * wc2.y + c2.z * wc2.z + c2.w * wc2.w;
            for (int o = 16; o; o >>= 1) ac += __shfl_xor_sync(~0u, ac, o);
            if (lane == 0) smf[SM_ROWC / 4 + r] = ac;
        }
        __syncthreads();

        // ---- GEMM1: sim = (ctx*w_m) @ qry^T ; M=64 N=128 K=256, barrier-free ----
        float acc1[2][4][4];
        #pragma unroll
        for (int mt = 0; mt < 2; mt++)
            #pragma unroll
            for (int jj = 0; jj < 4; jj++)
                #pragma unroll
                for (int e = 0; e < 4; e++) acc1[mt][jj][e] = 0.f;

        uint32_t rAb[2], xA[2], rBb[2], xB[2];
        #pragma unroll
        for (int mt = 0; mt < 2; mt++) {
            int row = mw * 32 + mt * 16 + gb * 8 + l7;
            rAb[mt] = row * 128; xA[mt] = row & 7;
        }
        #pragma unroll
        for (int p = 0; p < 2; p++) {
            int row = nw * 32 + p * 16 + gh * 8 + l7;
            rBb[p] = row * 128; xB[p] = row & 7;
        }

        #pragma unroll
        for (int kc = 0; kc < 4; kc++) {
            uint32_t Ab = sb + A_OFF + kc * 8192;
            uint32_t Bb = sb + B1_OFF + kc * 16384;
            #pragma unroll
            for (int ks = 0; ks < 4; ks++) {
                uint32_t a[2][4], bf[2][4];
                #pragma unroll
                for (int mt = 0; mt < 2; mt++) {
                    uint32_t u = 2 * ks + gh;
                    LDSM4(a[mt][0], a[mt][1], a[mt][2], a[mt][3], Ab + rAb[mt] + ((u ^ xA[mt]) << 4));
                }
                #pragma unroll
                for (int p = 0; p < 2; p++) {
                    uint32_t u = 2 * ks + gb;
                    LDSM4(bf[p][0], bf[p][1], bf[p][2], bf[p][3], Bb + rBb[p] + ((u ^ xB[p]) << 4));
                }
                #pragma unroll
                for (int mt = 0; mt < 2; mt++)
                    #pragma unroll
                    for (int p = 0; p < 2; p++) {
                        mma16(acc1[mt][2 * p],     a[mt][0], a[mt][1], a[mt][2], a[mt][3], bf[p][0], bf[p][1]);
                        mma16(acc1[mt][2 * p + 1], a[mt][0], a[mt][1], a[mt][2], a[mt][3], bf[p][2], bf[p][3]);
                    }
            }
        }

        // ---- softmax; alpha fp16 -> AL_OFF (overlays A) ----
        const float* rqv = smf + SM_ROWQ / 4;
        float vmax[4] = { -1e30f, -1e30f, -1e30f, -1e30f };
        #pragma unroll
        for (int mt = 0; mt < 2; mt++)
            #pragma unroll
            for (int jt = 0; jt < 4; jt++) {
                int c0 = nw * 32 + jt * 8 + 2 * (lane & 3);
                float r0 = rqv[c0], r1 = rqv[c0 + 1];
                vmax[2 * mt]     = fmaxf(vmax[2 * mt],     fmaxf(acc1[mt][jt][0] + r0, acc1[mt][jt][1] + r1));
                vmax[2 * mt + 1] = fmaxf(vmax[2 * mt + 1], fmaxf(acc1[mt][jt][2] + r0, acc1[mt][jt][3] + r1));
            }
        #pragma unroll
        for (int r = 0; r < 4; r++) {
            vmax[r] = fmaxf(vmax[r], __shfl_xor_sync(~0u, vmax[r], 1));
            vmax[r] = fmaxf(vmax[r], __shfl_xor_sync(~0u, vmax[r], 2));
        }
        if ((lane & 3) == 0)
            #pragma unroll
            for (int r = 0; r < 4; r++) {
                int row = mw * 32 + (r >> 1) * 16 + (r & 1) * 8 + (lane >> 2);
                smf[SM_SMAX / 4 + row * 4 + nw] = vmax[r];
            }
        __syncthreads();
        float rmax[4], rsum[4] = { 0.f, 0.f, 0.f, 0.f };
        #pragma unroll
        for (int r = 0; r < 4; r++) {
            int row = mw * 32 + (r >> 1) * 16 + (r & 1) * 8 + (lane >> 2);
            float m0 = fmaxf(smf[SM_SMAX / 4 + row * 4],     smf[SM_SMAX / 4 + row * 4 + 1]);
            float m1 = fmaxf(smf[SM_SMAX / 4 + row * 4 + 2], smf[SM_SMAX / 4 + row * 4 + 3]);
            rmax[r] = fmaxf(m0, m1);
        }
        #pragma unroll
        for (int mt = 0; mt < 2; mt++)
            #pragma unroll
            for (int jt = 0; jt < 4; jt++) {
                int c0 = nw * 32 + jt * 8 + 2 * (lane & 3);
                float r0 = rqv[c0], r1 = rqv[c0 + 1];
                float e0 = __expf(acc1[mt][jt][0] + r0 - rmax[2 * mt]);
                float e1 = __expf(acc1[mt][jt][1] + r1 - rmax[2 * mt]);
                float e2 = __expf(acc1[mt][jt][2] + r0 - rmax[2 * mt + 1]);
                float e3 = __expf(acc1[mt][jt][3] + r1 - rmax[2 * mt + 1]);
                rsum[2 * mt] += e0 + e1; rsum[2 * mt + 1] += e2 + e3;
                int rowA = mw * 32 + mt * 16 + (lane >> 2);
                int rowB = rowA + 8;
                int unit = nw * 4 + jt;
                *(uint32_t*)(smem + AL_OFF + rowA * 256 + ((unit ^ (rowA & 7)) << 4) + (lane & 3) * 4)
                    = pack2(e0, e1);
                *(uint32_t*)(smem + AL_OFF + rowB * 256 + ((unit ^ (rowB & 7)) << 4) + (lane & 3) * 4)
                    = pack2(e2, e3);
            }
        #pragma unroll
        for (int r = 0; r < 4; r++) {
            rsum[r] += __shfl_xor_sync(~0u, rsum[r], 1);
            rsum[r] += __shfl_xor_sync(~0u, rsum[r], 2);
        }
        if ((lane & 3) == 0)
            #pragma unroll
            for (int r = 0; r < 4; r++) {
                int row = mw * 32 + (r >> 1) * 16 + (r & 1) * 8 + (lane >> 2);
                smf[SM_SSUM / 4 + row * 4 + nw] = rsum[r];
            }
        __syncthreads();
        if (nw == 0 && (lane & 3) == 0) {
            float bias = smf[SM_BIAS / 4];
            #pragma unroll
            for (int r = 0; r < 4; r++) {
                int row = mw * 32 + (r >> 1) * 16 + (r & 1) * 8 + (lane >> 2);
                float tot = smf[SM_SSUM / 4 + row * 4]     + smf[SM_SSUM / 4 + row * 4 + 1]
                          + smf[SM_SSUM / 4 + row * 4 + 2] + smf[SM_SSUM / 4 + row * 4 + 3];
                smf[SM_SINV / 4 + row] = 1.0f / tot;
                smf[SM_M / 4 + row] = rmax[r] + smf[SM_ROWC / 4 + row] + bias;
            }
        }
        __syncthreads();

        // ---- beta prep: Ml = max m, w = exp(m-Ml), zl = sum w ----
        if (tid < 64) {
            float vm = smf[SM_M / 4 + tid];
            for (int o = 16; o; o >>= 1) vm = fmaxf(vm, __shfl_xor_sync(~0u, vm, o));
            if ((tid & 31) == 0) smf[SM_ZML / 4 + (tid >> 5)] = vm;
        }
        __syncthreads();
        const float Ml = fmaxf(smf[SM_ZML / 4], smf[SM_ZML / 4 + 1]);
        if (tid < 64) {
            float wv = __expf(smf[SM_M / 4 + tid] - Ml);
            smf[SM_WB / 4 + tid] = wv;
            for (int o = 16; o; o >>= 1) wv += __shfl_xor_sync(~0u, wv, o);
            if ((tid & 31) == 0) smf[SM_ZML / 4 + 2 + (tid >> 5)] = wv;
        }
        __syncthreads();
        if (tid == 0) {
            g_Ml[chunk_idx] = Ml;
            g_zl[chunk_idx] = smf[SM_ZML / 4 + 2] + smf[SM_ZML / 4 + 3];
        }

        // ---- GEMM2: D = E @ qry ; M=64, warp n-tile 64 (slot nw), K=128 ----
        float iv[4];
        #pragma unroll
        for (int r = 0; r < 4; r++) {
            int row = mw * 32 + (r >> 1) * 16 + (r & 1) * 8 + (lane >> 2);
            iv[r] = smf[SM_SINV / 4 + row];
        }
        uint32_t rA2b[2], xA2[2];
        #pragma unroll
        for (int mt = 0; mt < 2; mt++) {
            int row = mw * 32 + mt * 16 + gb * 8 + l7;
            rA2b[mt] = row * 256; xA2[mt] = row & 7;
        }
        const uint32_t Bs = sb + B1_OFF + nw * 16384;
        const int qbase = gb * 8 + l7;

        float acc2[8][2][4];
        #pragma unroll
        for (int jj = 0; jj < 8; jj++)
            #pragma unroll
            for (int mt = 0; mt < 2; mt++)
                #pragma unroll
                for (int e = 0; e < 4; e++) acc2[jj][mt][e] = 0.f;

        #pragma unroll
        for (int s = 0; s < 8; s++) {
            uint32_t a[2][4];
            #pragma unroll
            for (int mt = 0; mt < 2; mt++) {
                uint32_t u = 2 * s + gh;
                LDSM4(a[mt][0], a[mt][1], a[mt][2], a[mt][3],
                      sb + AL_OFF + rA2b[mt] + ((u ^ xA2[mt]) << 4));
            }
            uint32_t bt[4][4];
            uint32_t qrow = (uint32_t)(s * 16 + qbase);
            #pragma unroll
            for (int t = 0; t < 4; t++) {
                uint32_t u = 2 * t + gh;
                LDSM4T(bt[t][0], bt[t][1], bt[t][2], bt[t][3],
                       Bs + qrow * 128 + ((u ^ (uint32_t)l7) << 4));
            }
            #pragma unroll
            for (int mt = 0; mt < 2; mt++)
                #pragma unroll
                for (int t = 0; t < 4; t++) {
                    mma16(acc2[2 * t][mt],     a[mt][0], a[mt][1], a[mt][2], a[mt][3], bt[t][0], bt[t][1]);
                    mma16(acc2[2 * t + 1][mt], a[mt][0], a[mt][1], a[mt][2], a[mt][3], bt[t][2], bt[t][3]);
                }
        }
        __syncthreads();   // all GEMM2 alpha reads done before EPI overwrite

        // ---- epilogue: stage a-tile per 32-row half, drain coalesced,
        //      accumulate beta-weighted ctx partials (s_l) on the fly ----
        float sacc[4] = { 0.f, 0.f, 0.f, 0.f };
        #pragma unroll
        for (int p = 0; p < 2; p++) {
            if (mw == p) {
                #pragma unroll
                for (int mt = 0; mt < 2; mt++)
                    #pragma unroll
                    for (int h = 0; h < 2; h++) {
                        int rl = mt * 16 + h * 8 + (lane >> 2);
                        float ivr = iv[mt * 2 + h];
                        #pragma unroll
                        for (int jj = 0; jj < 8; jj++) {
                            int col = nw * 64 + jj * 8 + 2 * (lane & 3);
                            *(float2*)(smem + EPI_OFF + rl * EPI_STR + col * 4) =
                                make_float2(acc2[jj][mt][2 * h] * ivr,
                                            acc2[jj][mt][2 * h + 1] * ivr);
                        }
                    }
            }
            __syncthreads();
            #pragma unroll
            for (int i = 0; i < 8; i++) {
                int idx = i * 256 + tid;
                int rl = idx >> 6, c4 = (idx & 63) * 4;
                float4 av = *(const float4*)(smem + EPI_OFF + rl * EPI_STR + c4 * 4);
                int row = p * 32 + rl;
                float4 cv = *(const float4*)(ctxb + row * 256 + c4);
                float wr = smf[SM_WB / 4 + row];
                sacc[0] += wr * cv.x; sacc[1] += wr * cv.y;
                sacc[2] += wr * cv.z; sacc[3] += wr * cv.w;
                float* o = out + obase + (size_t)row * 1024 + c4;
                *(float4*)(o + 256) = av;
                *(float4*)(o + 512) = make_float4(cv.x * av.x, cv.y * av.y,
                                                  cv.z * av.z, cv.w * av.w);
            }
            __syncthreads();
        }
        // reduce s partials: 4 row-groups x 256 cols
        *(float4*)(smem + SP_OFF + (tid >> 6) * 1024 + (tid & 63) * 16) =
            make_float4(sacc[0], sacc[1], sacc[2], sacc[3]);
        __syncthreads();
        {
            float s = *(const float*)(smem + SP_OFF + tid * 4)
                    + *(const float*)(smem + SP_OFF + 1024 + tid * 4)
                    + *(const float*)(smem + SP_OFF + 2048 + tid * 4)
                    + *(const float*)(smem + SP_OFF + 3072 + tid * 4);
            g_spart[(size_t)chunk_idx * 256 + tid] = s;
        }
        __syncthreads();
    }
}

// ============================ K3: combine + out3 ============================
__global__ __launch_bounds__(256, 1)
void k3_cb(const float* __restrict__ ctx, float* __restrict__ out)
{
    __shared__ float coef[16];
    __shared__ float bv[256];
    __shared__ float dsh;
    const int tid = threadIdx.x;
    const int b = blockIdx.x >> 3, ch = blockIdx.x & 7;

    if (tid < 32) {
        float ml = (tid < 16) ? g_Ml[b * 16 + tid] : -1e30f;
        float M = ml;
        for (int o = 8; o; o >>= 1) M = fmaxf(M, __shfl_xor_sync(~0u, M, o));
        M = __shfl_sync(~0u, M, 0);
        float cf = (tid < 16) ? __expf(ml - M) : 0.f;
        if (tid < 16) coef[tid] = cf;
        float dz = (tid < 16) ? cf * g_zl[b * 16 + tid] : 0.f;
        for (int o = 8; o; o >>= 1) dz += __shfl_xor_sync(~0u, dz, o);
        if (tid == 0) dsh = dz;
    }
    __syncthreads();
    {
        float acc = 0.f;
        #pragma unroll
        for (int l = 0; l < 16; l++)
            acc += coef[l] * g_spart[(size_t)(b * 16 + l) * 256 + tid];
        bv[tid] = acc / dsh;
    }
    __syncthreads();
    const float* cb = ctx + ((size_t)b * 1024 + ch * 128) * 256;
    float* ob = out + ((size_t)(b * 1024) + ch * 128) * 1024 + 768;
    #pragma unroll 4
    for (int i = 0; i < 32; i++) {
        int f = i * 256 + tid;
        int row = f >> 6, c4 = (f & 63) * 4;
        float4 cv = *(const float4*)(cb + row * 256 + c4);
        float4 bb = *(const float4*)(bv + c4);
        float4 r = { cv.x * bb.x, cv.y * bb.y, cv.z * bb.z, cv.w * bb.w };
        *(float4*)(ob + (size_t)row * 1024 + c4) = r;
    }
}

extern "C" void kernel_launch(void* const* d_in, const int* in_sizes, int n_in,
                              void* d_out, int out_size)
{
    const float* ctx  = (const float*)d_in[0];
    const float* qry  = (const float*)d_in[2];
    const float* attw = (const float*)d_in[4];
    const float* attb = (const float*)d_in[5];
    float* out = (float*)d_out;

    cudaFuncSetAttribute(k1_main, cudaFuncAttributeMaxDynamicSharedMemorySize, SMEM_TOTAL);
    k1_main<<<512, 256, SMEM_TOTAL>>>(ctx, qry, attw, attb, out);
    k3_cb<<<512, 256>>>(ctx, out);
}